// round 5
// baseline (speedup 1.0000x reference)
#include <cuda_runtime.h>
#include <cuda_bf16.h>
#include <math.h>
#include <stdint.h>

// ---------------- problem constants ----------------
#define TOTN   131072      // B*N nodes
#define EMAX   1048576
#define FDIM   64
#define HSD    128
#define RSD    32
#define NPG    4096        // nodes per graph (temporal length)

// tcgen05 only legal in the arch-specific (sm_103a) compile pass
#if defined(__CUDA_ARCH_FEAT_SM103_ALL) || defined(__CUDA_ARCH_FEAT_SM100_ALL) || \
    (defined(__CUDA_ARCH_SPECIFIC__) && (__CUDA_ARCH_SPECIFIC__ >= 1000))
#define TC_OK 1
#else
#define TC_OK 0
#endif

// ---------------- device scratch (no cudaMalloc allowed) ----------------
__device__ int   g_is64;
__device__ float g_dinv [TOTN];
__device__ int   g_cnt  [TOTN];
__device__ int   g_rowp [TOTN + 1];
__device__ int   g_curs [TOTN];
__device__ int   g_adj  [EMAX];
__device__ float g_A1   [TOTN * FDIM];
__device__ float g_H1   [TOTN * HSD];
__device__ float g_H2raw[TOTN * RSD];
__device__ float g_H2   [TOTN * RSD];
__device__ float g_A3   [TOTN * RSD];
__device__ float g_H3   [TOTN * HSD];
__device__ float g_C1   [TOTN * HSD];
__device__ float g_C2   [TOTN * RSD];
__device__ float g_C3   [TOTN * HSD];

// ---------------- packed f32x2 (for fallback path) ----------------
typedef unsigned long long u64t;
__device__ __forceinline__ u64t pkf2(float lo, float hi) {
    u64t r; asm("mov.b64 %0, {%1, %2};" : "=l"(r) : "f"(lo), "f"(hi)); return r;
}
__device__ __forceinline__ u64t fmaf2(u64t a, u64t b, u64t c) {
    u64t d; asm("fma.rn.f32x2 %0, %1, %2, %3;" : "=l"(d) : "l"(a), "l"(b), "l"(c)); return d;
}
__device__ __forceinline__ float2 upkf2(u64t v) {
    float2 f; asm("mov.b64 {%0, %1}, %2;" : "=f"(f.x), "=f"(f.y) : "l"(v)); return f;
}

// ================= tcgen05 helpers (guarded) =================
__device__ __forceinline__ uint32_t smem_u32(const void* p) {
    uint32_t a;
    asm("{ .reg .u64 t; cvta.to.shared.u64 t, %1; cvt.u32.u64 %0, t; }" : "=r"(a) : "l"(p));
    return a;
}
#if TC_OK
__device__ __forceinline__ int elect1() {
    uint32_t p;
    asm volatile("{\n\t.reg .pred p;\n\telect.sync _|p, 0xFFFFFFFF;\n\tselp.b32 %0, 1, 0, p;\n\t}" : "=r"(p));
    return (int)p;
}
__device__ __forceinline__ void tc_alloc(uint32_t dst_smem, uint32_t ncols) {
    asm volatile("tcgen05.alloc.cta_group::1.sync.aligned.shared::cta.b32 [%0], %1;"
                 :: "r"(dst_smem), "r"(ncols) : "memory");
}
__device__ __forceinline__ void tc_dealloc(uint32_t tmem, uint32_t ncols) {
    asm volatile("tcgen05.dealloc.cta_group::1.sync.aligned.b32 %0, %1;" :: "r"(tmem), "r"(ncols));
}
__device__ __forceinline__ void tc_relinquish() {
    asm volatile("tcgen05.relinquish_alloc_permit.cta_group::1.sync.aligned;");
}
__device__ __forceinline__ void mbar_init(uint32_t mbar, uint32_t cnt) {
    asm volatile("mbarrier.init.shared.b64 [%0], %1;" :: "r"(mbar), "r"(cnt) : "memory");
}
__device__ __forceinline__ void mbar_inval(uint32_t mbar) {
    asm volatile("mbarrier.inval.shared.b64 [%0];" :: "r"(mbar) : "memory");
}
__device__ __forceinline__ void mbar_wait(uint32_t mbar, uint32_t parity) {
    asm volatile(
        "{\n\t.reg .pred P;\n\t"
        "W%=:\n\t"
        "mbarrier.try_wait.parity.acquire.cta.shared::cta.b64 P, [%0], %1;\n\t"
        "@!P bra W%=;\n\t}"
        :: "r"(mbar), "r"(parity) : "memory");
}
__device__ __forceinline__ void tc_commit(uint32_t mbar) {
    asm volatile("tcgen05.commit.cta_group::1.mbarrier::arrive::one.shared::cluster.b64 [%0];"
                 :: "r"(mbar) : "memory");
}
__device__ __forceinline__ void mma_f16_ss(uint32_t d_tmem, uint64_t a_desc, uint64_t b_desc,
                                           uint32_t idesc, int enable_d) {
    uint32_t z = 0;
    asm volatile(
        "{\n\t.reg .pred p;\n\t"
        "setp.ne.u32 p, %5, 0;\n\t"
        "tcgen05.mma.cta_group::1.kind::f16 [%0], %1, %2, %3, {%4, %4, %4, %4}, p;\n\t}"
        :: "r"(d_tmem), "l"(a_desc), "l"(b_desc), "r"(idesc), "r"(z), "r"((uint32_t)enable_d)
        : "memory");
}
__device__ __forceinline__ void tc_ld32(uint32_t* r, uint32_t tmem_addr) {
    asm volatile(
        "tcgen05.ld.sync.aligned.32x32b.x32.b32 "
        "{%0, %1, %2, %3, %4, %5, %6, %7, %8, %9, %10, %11, %12, %13, %14, %15, "
        " %16, %17, %18, %19, %20, %21, %22, %23, %24, %25, %26, %27, %28, %29, %30, %31}, [%32];"
        : "=r"(r[0]),  "=r"(r[1]),  "=r"(r[2]),  "=r"(r[3]),
          "=r"(r[4]),  "=r"(r[5]),  "=r"(r[6]),  "=r"(r[7]),
          "=r"(r[8]),  "=r"(r[9]),  "=r"(r[10]), "=r"(r[11]),
          "=r"(r[12]), "=r"(r[13]), "=r"(r[14]), "=r"(r[15]),
          "=r"(r[16]), "=r"(r[17]), "=r"(r[18]), "=r"(r[19]),
          "=r"(r[20]), "=r"(r[21]), "=r"(r[22]), "=r"(r[23]),
          "=r"(r[24]), "=r"(r[25]), "=r"(r[26]), "=r"(r[27]),
          "=r"(r[28]), "=r"(r[29]), "=r"(r[30]), "=r"(r[31])
        : "r"(tmem_addr));
}
__device__ __forceinline__ void tc_wait_ld() {
    asm volatile("tcgen05.wait::ld.sync.aligned;" ::: "memory");
}
__device__ __forceinline__ void tc_fence_after() {
    asm volatile("tcgen05.fence::after_thread_sync;" ::: "memory");
}
__device__ __forceinline__ void tc_fence_before() {
    asm volatile("tcgen05.fence::before_thread_sync;" ::: "memory");
}
#endif  // TC_OK

#define SWZ(o) ((o) ^ (((o) >> 3) & 0x70))
#define DESC_BASE ((2ull << 61) | (1ull << 46) | (64ull << 32) | (1ull << 16))

__device__ __forceinline__ uint32_t pack_bf(float a, float b) {
    __nv_bfloat162 t;
    t.x = __float2bfloat16(a);
    t.y = __float2bfloat16(b);
    return *reinterpret_cast<uint32_t*>(&t);
}

// =========== unified dense layer ===========
// OUT[r, n] = act( sum_{s<TAPS} sum_{c<CIN} X[r+s-1, c] * Wmat(n, c, s) + bias[n] )
// WCONV=1: W is [COUT][CIN][3]; WCONV=0: W is [CIN][COUT] (tap 0 only).
// TC path: bf16 hi/lo split SS MMA, fp32 TMEM accum. Fallback: SIMT FFMA2.
template <int CIN, int COUT, int TAPS, int KCH, int WCONV, int HASBIAS, int HASRELU>
__global__ void __launch_bounds__(128)
tc_layer(const float* __restrict__ X, const float* __restrict__ W,
         const float* __restrict__ bias, float* __restrict__ OUT) {
    extern __shared__ __align__(1024) char smem[];
    constexpr int KTOT = CIN * TAPS;
    constexpr int NCH  = KTOT / KCH;
    int tid = threadIdx.x;
    int row0 = blockIdx.x * 128;
    int gb = (row0 / NPG) * NPG;

#if TC_OK
    // -------------------- tensor-core path --------------------
    constexpr int KSTEPS = KCH / 16;
    constexpr uint32_t IDESC =
        (1u << 4) | (1u << 7) | (1u << 10) | ((uint32_t)(COUT / 8) << 17) | (8u << 24);
    constexpr int A_HI = 1024;
    constexpr int A_LO = A_HI + 128 * 128;
    constexpr int B_HI = A_LO + 128 * 128;
    constexpr int B_LO = B_HI + COUT * 128;

    uint32_t sbase = smem_u32(smem);
    int wid = tid >> 5;
    int lid = tid & 31;
    uint32_t mbar = sbase + 8;

    if (wid == 0) tc_alloc(sbase, 128);
    if (tid == 0) mbar_init(mbar, 1);
    __syncthreads();
    uint32_t tmem;
    asm volatile("ld.shared.b32 %0, [%1];" : "=r"(tmem) : "r"(sbase));

    const uint64_t dAhi = DESC_BASE | (((uint64_t)(sbase + A_HI) >> 4) & 0x3FFF);
    const uint64_t dAlo = DESC_BASE | (((uint64_t)(sbase + A_LO) >> 4) & 0x3FFF);
    const uint64_t dBhi = DESC_BASE | (((uint64_t)(sbase + B_HI) >> 4) & 0x3FFF);
    const uint64_t dBlo = DESC_BASE | (((uint64_t)(sbase + B_LO) >> 4) & 0x3FFF);

    for (int c = 0; c < NCH; c++) {
        const int s  = (c * KCH) / CIN;
        const int c0 = (c * KCH) % CIN;

        {   // stage A chunk (tap-shifted rows), bf16 hi/lo, SW128
            int r = tid;
            long src = (long)row0 + r + (TAPS == 3 ? (s - 1) : 0);
            bool valid = (src >= gb) && (src < (long)gb + NPG);
            const float* xp = X + src * CIN + c0;
            #pragma unroll
            for (int j = 0; j < KCH; j += 2) {
                float ax = 0.0f, ay = 0.0f;
                if (valid) { float2 v = *(const float2*)(xp + j); ax = v.x; ay = v.y; }
                __nv_bfloat16 hx = __float2bfloat16(ax);
                __nv_bfloat16 hy = __float2bfloat16(ay);
                float lx = ax - __bfloat162float(hx);
                float ly = ay - __bfloat162float(hy);
                __nv_bfloat162 hp; hp.x = hx; hp.y = hy;
                uint32_t off = SWZ((uint32_t)(r * 128 + j * 2));
                *(uint32_t*)(smem + A_HI + off) = *reinterpret_cast<uint32_t*>(&hp);
                *(uint32_t*)(smem + A_LO + off) = pack_bf(lx, ly);
            }
        }
        if (tid < COUT) {   // stage B chunk, bf16 hi/lo, SW128
            int n = tid;
            #pragma unroll
            for (int j = 0; j < KCH; j += 2) {
                float w0, w1;
                if (WCONV) {
                    w0 = W[((size_t)n * CIN + (c0 + j)) * 3 + s];
                    w1 = W[((size_t)n * CIN + (c0 + j + 1)) * 3 + s];
                } else {
                    w0 = W[(size_t)(c0 + j) * COUT + n];
                    w1 = W[(size_t)(c0 + j + 1) * COUT + n];
                }
                __nv_bfloat16 h0 = __float2bfloat16(w0);
                __nv_bfloat16 h1 = __float2bfloat16(w1);
                float l0 = w0 - __bfloat162float(h0);
                float l1 = w1 - __bfloat162float(h1);
                __nv_bfloat162 hp; hp.x = h0; hp.y = h1;
                uint32_t off = SWZ((uint32_t)(n * 128 + j * 2));
                *(uint32_t*)(smem + B_HI + off) = *reinterpret_cast<uint32_t*>(&hp);
                *(uint32_t*)(smem + B_LO + off) = pack_bf(l0, l1);
            }
        }
        __syncthreads();

        if (wid == 0) {
            if (elect1()) {
                #pragma unroll
                for (int ks = 0; ks < KSTEPS; ks++) {
                    uint64_t o = (uint64_t)(2 * ks);
                    int first = (c == 0 && ks == 0);
                    mma_f16_ss(tmem, dAhi + o, dBhi + o, IDESC, !first);
                    mma_f16_ss(tmem, dAhi + o, dBlo + o, IDESC, 1);
                    mma_f16_ss(tmem, dAlo + o, dBhi + o, IDESC, 1);
                }
                tc_commit(mbar);
            }
        }
        mbar_wait(mbar, (uint32_t)(c & 1));
        __syncthreads();
    }

    tc_fence_after();
    uint32_t dr[COUT];
    #pragma unroll
    for (int cb = 0; cb < COUT; cb += 32) tc_ld32(dr + cb, tmem + cb);
    tc_wait_ld();
    tc_fence_before();

    int row = row0 + wid * 32 + lid;
    float* op = OUT + (size_t)row * COUT;
    #pragma unroll
    for (int n = 0; n < COUT; n++) {
        float v = __uint_as_float(dr[n]);
        if (HASBIAS) v += bias[n];
        if (HASRELU) v = fmaxf(v, 0.0f);
        op[n] = v;
    }

    __syncthreads();
    if (tid == 0) mbar_inval(mbar);
    __syncthreads();
    if (wid == 0) {
        tc_relinquish();
        tc_dealloc(tmem, 128);
    }
#else
    // -------------------- SIMT FFMA2 fallback (correctness insurance) --------------------
    constexpr int TN_F   = (COUT >= 128) ? 16 : 8;
    constexpr int TCOLS  = COUT / TN_F;            // 8 or 4
    constexpr int TROWS  = 128 / TCOLS;            // 16 or 32
    constexpr int TM_F   = 128 / TROWS;            // 8 or 4
    constexpr int TN2    = TN_F / 2;
    float* As = (float*)(smem + 1024);             // [KCH][128]
    float* Bs = As + KCH * 128;                    // [KCH][COUT]
    int tx = tid % TCOLS, ty = tid / TCOLS;

    u64t acc[TM_F][TN2];
    #pragma unroll
    for (int i = 0; i < TM_F; i++)
        #pragma unroll
        for (int j = 0; j < TN2; j++) acc[i][j] = 0ull;

    for (int c = 0; c < NCH; c++) {
        const int s  = (c * KCH) / CIN;
        const int c0 = (c * KCH) % CIN;
        {
            int r = tid;
            long src = (long)row0 + r + (TAPS == 3 ? (s - 1) : 0);
            bool valid = (src >= gb) && (src < (long)gb + NPG);
            const float* xp = X + src * CIN + c0;
            #pragma unroll
            for (int j = 0; j < KCH; j++) As[j * 128 + r] = valid ? xp[j] : 0.0f;
        }
        for (int i = tid; i < KCH * COUT; i += 128) {
            int kk = i / COUT, n = i % COUT;
            Bs[kk * COUT + n] = WCONV ? W[((size_t)n * CIN + (c0 + kk)) * 3 + s]
                                      : W[(size_t)(c0 + kk) * COUT + n];
        }
        __syncthreads();
        #pragma unroll 4
        for (int kk = 0; kk < KCH; kk++) {
            u64t a2[TM_F];
            #pragma unroll
            for (int i = 0; i < TM_F; i++) {
                float a = As[kk * 128 + ty * TM_F + i];
                a2[i] = pkf2(a, a);
            }
            const u64t* bp = (const u64t*)&Bs[kk * COUT + tx * TN_F];
            u64t b2[TN2];
            #pragma unroll
            for (int j = 0; j < TN2; j++) b2[j] = bp[j];
            #pragma unroll
            for (int i = 0; i < TM_F; i++)
                #pragma unroll
                for (int j = 0; j < TN2; j++)
                    acc[i][j] = fmaf2(a2[i], b2[j], acc[i][j]);
        }
        __syncthreads();
    }
    #pragma unroll
    for (int i = 0; i < TM_F; i++) {
        size_t r = row0 + ty * TM_F + i;
        #pragma unroll
        for (int j = 0; j < TN2; j++) {
            int n = tx * TN_F + 2 * j;
            float2 v = upkf2(acc[i][j]);
            if (HASBIAS) { v.x += bias[n]; v.y += bias[n + 1]; }
            if (HASRELU) { v.x = fmaxf(v.x, 0.0f); v.y = fmaxf(v.y, 0.0f); }
            *(float2*)&OUT[r * COUT + n] = v;
        }
    }
#endif
}

// ---------------- edge dtype detection ----------------
__global__ void detect_kernel(const unsigned int* e) {
    if (blockIdx.x == 0 && threadIdx.x == 0) {
        int ok = 1;
        #pragma unroll 1
        for (int i = 0; i < 64; i++)
            if (e[2 * i + 1] != 0u) { ok = 0; break; }
        g_is64 = ok;
    }
}
__device__ __forceinline__ int edge_at(const void* e, int idx, int is64) {
    if (is64) return (int)((const long long*)e)[idx];
    return ((const int*)e)[idx];
}

// ---------------- CSR build ----------------
__global__ void zero_cnt_kernel(int* cnt, int n) {
    int i  = blockIdx.x * blockDim.x + threadIdx.x;
    int st = gridDim.x * blockDim.x;
    for (; i < n; i += st) cnt[i] = 0;
}
__global__ void count_kernel(const void* edges, int* cnt, int E) {
    int is64 = g_is64;
    int i  = blockIdx.x * blockDim.x + threadIdx.x;
    int st = gridDim.x * blockDim.x;
    for (; i < E; i += st) {
        int d = edge_at(edges, E + i, is64);
        atomicAdd(&cnt[d], 1);
    }
}
__global__ void dinv_kernel(const int* __restrict__ cnt, float* dinv, int n) {
    int i  = blockIdx.x * blockDim.x + threadIdx.x;
    int st = gridDim.x * blockDim.x;
    for (; i < n; i += st) dinv[i] = rsqrtf((float)cnt[i] + 1.0f);
}
__global__ void __launch_bounds__(1024)
scan_kernel(const int* __restrict__ cnt, int* row_ptr, int* cursor) {
    const int T = 1024;
    const int C = TOTN / T;
    int tid  = threadIdx.x;
    int base = tid * C;
    int s = 0;
    #pragma unroll 8
    for (int c = 0; c < C; c++) s += cnt[base + c];
    __shared__ int sh[T];
    sh[tid] = s;
    __syncthreads();
    for (int off = 1; off < T; off <<= 1) {
        int v = (tid >= off) ? sh[tid - off] : 0;
        __syncthreads();
        sh[tid] += v;
        __syncthreads();
    }
    int run = sh[tid] - s;
    #pragma unroll 8
    for (int c = 0; c < C; c++) {
        row_ptr[base + c] = run;
        cursor[base + c]  = run;
        run += cnt[base + c];
    }
    if (tid == T - 1) row_ptr[TOTN] = run;
}
__global__ void fill_kernel(const void* edges, int* cursor, int* adj, int E) {
    int is64 = g_is64;
    int i  = blockIdx.x * blockDim.x + threadIdx.x;
    int st = gridDim.x * blockDim.x;
    for (; i < E; i += st) {
        int s = edge_at(edges, i, is64);
        int d = edge_at(edges, E + i, is64);
        int pos = atomicAdd(&cursor[d], 1);
        adj[pos] = s;
    }
}

// ---------------- CSR gather + fused epilogue ----------------
template <int D, int BIASRELU>
__global__ void gather_kernel(const int* __restrict__ row_ptr, const int* __restrict__ adj,
                              const float* __restrict__ dinv, const float* __restrict__ X,
                              const float* __restrict__ bias, float* __restrict__ OUT, int n) {
    int lane = threadIdx.x & 31;
    int node = (blockIdx.x * blockDim.x + threadIdx.x) >> 5;
    if (node >= n) return;
    int beg = row_ptr[node];
    int end = row_ptr[node + 1];
    float di = dinv[node];
    float c  = di * di;
    if (D == 64) {
        float ax = 0.0f, ay = 0.0f;
        for (int j = beg; j < end; j++) {
            int s = adj[j];
            float ws = __ldg(&dinv[s]);
            float2 v = ((const float2*)(X + (size_t)s * 64))[lane];
            ax = fmaf(ws, v.x, ax);
            ay = fmaf(ws, v.y, ay);
        }
        float2 xv = ((const float2*)(X + (size_t)node * 64))[lane];
        float2 o;
        o.x = c * (ax + xv.x);
        o.y = c * (ay + xv.y);
        if (BIASRELU) {
            o.x = fmaxf(o.x + bias[2 * lane],     0.0f);
            o.y = fmaxf(o.y + bias[2 * lane + 1], 0.0f);
        }
        ((float2*)(OUT + (size_t)node * 64))[lane] = o;
    } else {
        float acc = 0.0f;
        for (int j = beg; j < end; j++) {
            int s = adj[j];
            float ws = __ldg(&dinv[s]);
            acc = fmaf(ws, X[(size_t)s * 32 + lane], acc);
        }
        float v = c * (acc + X[(size_t)node * 32 + lane]);
        if (BIASRELU) v = fmaxf(v + bias[lane], 0.0f);
        OUT[(size_t)node * 32 + lane] = v;
    }
}

// ---------------- 3 scalar heads ----------------
__global__ void heads_kernel(const float* __restrict__ X,
                             const float* __restrict__ Wpi, const float* __restrict__ bpi,
                             const float* __restrict__ Wn,  const float* __restrict__ bn,
                             const float* __restrict__ Wp,  const float* __restrict__ bp,
                             float* __restrict__ out, int M) {
    int lane = threadIdx.x & 31;
    int warp = (blockIdx.x * blockDim.x + threadIdx.x) >> 5;
    int nw   = (gridDim.x * blockDim.x) >> 5;
    float4 wa = ((const float4*)Wpi)[lane];
    float4 wb = ((const float4*)Wn)[lane];
    float4 wc = ((const float4*)Wp)[lane];
    for (int r = warp; r < M; r += nw) {
        float4 x = ((const float4*)(X + (size_t)r * 128))[lane];
        float s1 = x.x * wa.x + x.y * wa.y + x.z * wa.z + x.w * wa.w;
        float s2 = x.x * wb.x + x.y * wb.y + x.z * wb.z + x.w * wb.w;
        float s3 = x.x * wc.x + x.y * wc.y + x.z * wc.z + x.w * wc.w;
        #pragma unroll
        for (int o = 16; o > 0; o >>= 1) {
            s1 += __shfl_xor_sync(0xffffffffu, s1, o);
            s2 += __shfl_xor_sync(0xffffffffu, s2, o);
            s3 += __shfl_xor_sync(0xffffffffu, s3, o);
        }
        if (lane == 0) {
            float zpi = s1 + bpi[0];
            float zn  = s2 + bn[0];
            float zp  = s3 + bp[0];
            out[r]         = 1.0f / (1.0f + expf(-zpi));
            out[M + r]     = (zn > 0.0f) ? (zn + log1pf(expf(-zn))) : log1pf(expf(zn));
            out[2 * M + r] = 1.0f / (1.0f + expf(-zp));
        }
    }
}

// ---------------- launch ----------------
extern "C" void kernel_launch(void* const* d_in, const int* in_sizes, int n_in,
                              void* d_out, int out_size) {
    const float* x     = (const float*)d_in[0];
    const void*  edges = d_in[1];
    const float* W1  = (const float*)d_in[3];  const float* b1  = (const float*)d_in[4];
    const float* W2  = (const float*)d_in[5];  const float* b2  = (const float*)d_in[6];
    const float* W3  = (const float*)d_in[7];  const float* b3  = (const float*)d_in[8];
    const float* tW1 = (const float*)d_in[9];  const float* tb1 = (const float*)d_in[10];
    const float* tW2 = (const float*)d_in[11]; const float* tb2 = (const float*)d_in[12];
    const float* tW3 = (const float*)d_in[13]; const float* tb3 = (const float*)d_in[14];
    const float* Wpi = (const float*)d_in[15]; const float* bpi = (const float*)d_in[16];
    const float* Wn  = (const float*)d_in[17]; const float* bn  = (const float*)d_in[18];
    const float* Wp  = (const float*)d_in[19]; const float* bp  = (const float*)d_in[20];
    float* out = (float*)d_out;

    const int TOT = in_sizes[0] / FDIM;
    const int E   = in_sizes[1] / 2;

    float *dinv, *A1, *H1, *H2raw, *H2, *A3, *H3, *C1, *C2, *C3;
    int *cnt, *rowp, *curs, *adj;
    cudaGetSymbolAddress((void**)&dinv,  g_dinv);
    cudaGetSymbolAddress((void**)&cnt,   g_cnt);
    cudaGetSymbolAddress((void**)&rowp,  g_rowp);
    cudaGetSymbolAddress((void**)&curs,  g_curs);
    cudaGetSymbolAddress((void**)&adj,   g_adj);
    cudaGetSymbolAddress((void**)&A1,    g_A1);
    cudaGetSymbolAddress((void**)&H1,    g_H1);
    cudaGetSymbolAddress((void**)&H2raw, g_H2raw);
    cudaGetSymbolAddress((void**)&H2,    g_H2);
    cudaGetSymbolAddress((void**)&A3,    g_A3);
    cudaGetSymbolAddress((void**)&H3,    g_H3);
    cudaGetSymbolAddress((void**)&C1,    g_C1);
    cudaGetSymbolAddress((void**)&C2,    g_C2);
    cudaGetSymbolAddress((void**)&C3,    g_C3);

    const int gatherBlocks = (TOT * 32) / 256;
    const int tcGrid = TOT / 128;

    // dynamic smem (covers both tc and fallback layouts)
    const int SM128 = 1024 + 32768 + 2 * 128 * 128;   // 66560
    const int SM32  = 1024 + 32768 + 2 * 32 * 128;    // 41984

    cudaFuncSetAttribute(tc_layer<64, 128, 1, 64, 0, 1, 1>, cudaFuncAttributeMaxDynamicSharedMemorySize, SM128);
    cudaFuncSetAttribute(tc_layer<128, 32, 1, 64, 0, 0, 0>, cudaFuncAttributeMaxDynamicSharedMemorySize, SM32);
    cudaFuncSetAttribute(tc_layer<32, 128, 1, 32, 0, 1, 1>, cudaFuncAttributeMaxDynamicSharedMemorySize, SM128);
    cudaFuncSetAttribute(tc_layer<128, 128, 3, 64, 1, 1, 1>, cudaFuncAttributeMaxDynamicSharedMemorySize, SM128);
    cudaFuncSetAttribute(tc_layer<128, 32, 3, 64, 1, 1, 1>, cudaFuncAttributeMaxDynamicSharedMemorySize, SM32);
    cudaFuncSetAttribute(tc_layer<32, 128, 3, 32, 1, 1, 1>, cudaFuncAttributeMaxDynamicSharedMemorySize, SM128);

    detect_kernel<<<1, 32>>>((const unsigned int*)edges);

    // ---- CSR build ----
    zero_cnt_kernel<<<256, 256>>>(cnt, TOT);
    count_kernel<<<2048, 256>>>(edges, cnt, E);
    dinv_kernel<<<256, 256>>>(cnt, dinv, TOT);
    scan_kernel<<<1, 1024>>>(cnt, rowp, curs);
    fill_kernel<<<2048, 256>>>(edges, curs, adj, E);

    // ---- GCN layer 1: gather raw input, then GEMM ----
    gather_kernel<64, 0><<<gatherBlocks, 256>>>(rowp, adj, dinv, x, nullptr, A1, TOT);
    tc_layer<64, 128, 1, 64, 0, 1, 1><<<tcGrid, 128, SM128>>>(A1, W1, b1, H1);

    // ---- GCN layer 2 ----
    tc_layer<128, 32, 1, 64, 0, 0, 0><<<tcGrid, 128, SM32>>>(H1, W2, nullptr, H2raw);
    gather_kernel<32, 1><<<gatherBlocks, 256>>>(rowp, adj, dinv, H2raw, b2, H2, TOT);

    // ---- GCN layer 3 ----
    gather_kernel<32, 0><<<gatherBlocks, 256>>>(rowp, adj, dinv, H2, nullptr, A3, TOT);
    tc_layer<32, 128, 1, 32, 0, 1, 1><<<tcGrid, 128, SM128>>>(A3, W3, b3, H3);

    // ---- temporal conv stack (k=3, pad=1) ----
    tc_layer<128, 128, 3, 64, 1, 1, 1><<<tcGrid, 128, SM128>>>(H3, tW1, tb1, C1);
    tc_layer<128, 32, 3, 64, 1, 1, 1><<<tcGrid, 128, SM32>>>(C1, tW2, tb2, C2);
    tc_layer<32, 128, 3, 32, 1, 1, 1><<<tcGrid, 128, SM128>>>(C2, tW3, tb3, C3);

    // ---- heads ----
    heads_kernel<<<TOT / 8, 256>>>(C3, Wpi, bpi, Wn, bn, Wp, bp, out, TOT);
}

// round 6
// speedup vs baseline: 1.5857x; 1.5857x over previous
#include <cuda_runtime.h>
#include <cuda_bf16.h>
#include <math.h>
#include <stdint.h>

// ---------------- problem constants ----------------
#define TOTN   131072      // B*N nodes
#define EMAX   1048576
#define FDIM   64
#define HSD    128
#define RSD    32
#define NPG    4096        // nodes per graph (temporal length)

// ---------------- device scratch (no cudaMalloc allowed) ----------------
__device__ int   g_is64;
__device__ float g_dinv [TOTN];
__device__ int   g_cnt  [TOTN];
__device__ int   g_rowp [TOTN + 1];
__device__ int   g_curs [TOTN];
__device__ int   g_adj  [EMAX];
__device__ float g_A1   [TOTN * FDIM];
__device__ float g_H1   [TOTN * HSD];
__device__ float g_H2raw[TOTN * RSD];
__device__ float g_H2   [TOTN * RSD];
__device__ float g_A3   [TOTN * RSD];
__device__ float g_H3   [TOTN * HSD];
__device__ float g_C1   [TOTN * HSD];
__device__ float g_C2   [TOTN * RSD];
__device__ float g_C3   [TOTN * HSD];

__device__ __forceinline__ uint32_t pack_bf(float a, float b) {
    __nv_bfloat162 t;
    t.x = __float2bfloat16(a);
    t.y = __float2bfloat16(b);
    return *reinterpret_cast<uint32_t*>(&t);
}

// m16n8k16 row.col f32.bf16.bf16.f32 (portable PTX, sm_80+)
__device__ __forceinline__ void mma16816(float* d, uint32_t a0, uint32_t a1, uint32_t a2,
                                         uint32_t a3, uint32_t b0, uint32_t b1) {
    asm volatile(
        "mma.sync.aligned.m16n8k16.row.col.f32.bf16.bf16.f32 "
        "{%0,%1,%2,%3}, {%4,%5,%6,%7}, {%8,%9}, {%0,%1,%2,%3};"
        : "+f"(d[0]), "+f"(d[1]), "+f"(d[2]), "+f"(d[3])
        : "r"(a0), "r"(a1), "r"(a2), "r"(a3), "r"(b0), "r"(b1));
}

// =========== unified dense layer on tensor cores (mma.sync) ===========
// OUT[r, n] = act( sum_{s<TAPS} sum_{c<CIN} X[r+s-1, c] * Wmat(n, c, s) + bias[n] )
// WCONV=1: W is [COUT][CIN][3]; WCONV=0: W is [CIN][COUT] (tap 0 only).
// bf16 hi/lo split (3 MMA terms), fp32 register accumulation.
// CTA: 256 threads = 8 warps; warp w computes rows [w*16, w*16+16) x all COUT.
template <int CIN, int COUT, int TAPS, int KCH, int WCONV, int HASBIAS, int HASRELU>
__global__ void __launch_bounds__(256)
mma_layer(const float* __restrict__ X, const float* __restrict__ W,
          const float* __restrict__ bias, float* __restrict__ OUT) {
    constexpr int KTOT = CIN * TAPS;
    constexpr int NCH  = KTOT / KCH;
    constexpr int P    = KCH + 8;         // bf16 pitch (even -> 4B aligned u32 loads)
    constexpr int NT   = COUT / 8;        // n-tiles per warp

    extern __shared__ __align__(16) char smem[];
    __nv_bfloat16* Ah = (__nv_bfloat16*)smem;       // [128][P]
    __nv_bfloat16* Al = Ah + 128 * P;
    __nv_bfloat16* Bh = Al + 128 * P;               // [COUT][P]
    __nv_bfloat16* Bl = Bh + COUT * P;

    int tid  = threadIdx.x;
    int w    = tid >> 5;
    int lane = tid & 31;
    int gid  = lane >> 2;     // 0..7
    int qid  = lane & 3;      // 0..3
    int row0 = blockIdx.x * 128;
    int gb   = (row0 / NPG) * NPG;

    float d[NT][4];
    #pragma unroll
    for (int t = 0; t < NT; t++)
        #pragma unroll
        for (int i = 0; i < 4; i++) d[t][i] = 0.0f;

    for (int c = 0; c < NCH; c++) {
        const int s  = (c * KCH) / CIN;   // tap
        const int c0 = (c * KCH) % CIN;   // channel offset

        // ---- stage A chunk (tap-shifted rows), hi/lo bf16 ----
        for (int idx = tid; idx < 128 * (KCH / 2); idx += 256) {
            int r = idx / (KCH / 2);
            int j = (idx % (KCH / 2)) * 2;
            long src = (long)row0 + r + (TAPS == 3 ? (s - 1) : 0);
            float ax = 0.0f, ay = 0.0f;
            if (src >= gb && src < (long)gb + NPG) {
                float2 v = *(const float2*)(X + src * CIN + c0 + j);
                ax = v.x; ay = v.y;
            }
            __nv_bfloat16 hx = __float2bfloat16(ax);
            __nv_bfloat16 hy = __float2bfloat16(ay);
            float lx = ax - __bfloat162float(hx);
            float ly = ay - __bfloat162float(hy);
            __nv_bfloat162 hp; hp.x = hx; hp.y = hy;
            *(uint32_t*)&Ah[r * P + j] = *reinterpret_cast<uint32_t*>(&hp);
            *(uint32_t*)&Al[r * P + j] = pack_bf(lx, ly);
        }
        // ---- stage B chunk, hi/lo bf16 (B stored [n][k], k contiguous = col-major) ----
        for (int idx = tid; idx < COUT * (KCH / 2); idx += 256) {
            int n = idx / (KCH / 2);
            int j = (idx % (KCH / 2)) * 2;
            float w0, w1;
            if (WCONV) {
                w0 = W[((size_t)n * CIN + (c0 + j)) * 3 + s];
                w1 = W[((size_t)n * CIN + (c0 + j + 1)) * 3 + s];
            } else {
                w0 = W[(size_t)(c0 + j) * COUT + n];
                w1 = W[(size_t)(c0 + j + 1) * COUT + n];
            }
            __nv_bfloat16 h0 = __float2bfloat16(w0);
            __nv_bfloat16 h1 = __float2bfloat16(w1);
            float l0 = w0 - __bfloat162float(h0);
            float l1 = w1 - __bfloat162float(h1);
            __nv_bfloat162 hp; hp.x = h0; hp.y = h1;
            *(uint32_t*)&Bh[n * P + j] = *reinterpret_cast<uint32_t*>(&hp);
            *(uint32_t*)&Bl[n * P + j] = pack_bf(l0, l1);
        }
        __syncthreads();

        // ---- MMA over this K chunk ----
        #pragma unroll
        for (int ks = 0; ks < KCH / 16; ks++) {
            int ac = ks * 16 + qid * 2;
            int ar = w * 16 + gid;
            uint32_t ah0 = *(const uint32_t*)&Ah[ar * P + ac];
            uint32_t ah1 = *(const uint32_t*)&Ah[(ar + 8) * P + ac];
            uint32_t ah2 = *(const uint32_t*)&Ah[ar * P + ac + 8];
            uint32_t ah3 = *(const uint32_t*)&Ah[(ar + 8) * P + ac + 8];
            uint32_t al0 = *(const uint32_t*)&Al[ar * P + ac];
            uint32_t al1 = *(const uint32_t*)&Al[(ar + 8) * P + ac];
            uint32_t al2 = *(const uint32_t*)&Al[ar * P + ac + 8];
            uint32_t al3 = *(const uint32_t*)&Al[(ar + 8) * P + ac + 8];
            #pragma unroll
            for (int t = 0; t < NT; t++) {
                int n = t * 8 + gid;
                uint32_t bh0 = *(const uint32_t*)&Bh[n * P + ac];
                uint32_t bh1 = *(const uint32_t*)&Bh[n * P + ac + 8];
                uint32_t bl0 = *(const uint32_t*)&Bl[n * P + ac];
                uint32_t bl1 = *(const uint32_t*)&Bl[n * P + ac + 8];
                mma16816(d[t], ah0, ah1, ah2, ah3, bh0, bh1);
                mma16816(d[t], ah0, ah1, ah2, ah3, bl0, bl1);
                mma16816(d[t], al0, al1, al2, al3, bh0, bh1);
            }
        }
        __syncthreads();
    }

    // ---- epilogue: bias/relu, store fp32 ----
    int r0 = row0 + w * 16 + gid;
    #pragma unroll
    for (int t = 0; t < NT; t++) {
        int n = t * 8 + qid * 2;
        float2 v0 = make_float2(d[t][0], d[t][1]);
        float2 v1 = make_float2(d[t][2], d[t][3]);
        if (HASBIAS) {
            float bx = bias[n], by = bias[n + 1];
            v0.x += bx; v0.y += by;
            v1.x += bx; v1.y += by;
        }
        if (HASRELU) {
            v0.x = fmaxf(v0.x, 0.0f); v0.y = fmaxf(v0.y, 0.0f);
            v1.x = fmaxf(v1.x, 0.0f); v1.y = fmaxf(v1.y, 0.0f);
        }
        *(float2*)&OUT[(size_t)r0 * COUT + n]       = v0;
        *(float2*)&OUT[(size_t)(r0 + 8) * COUT + n] = v1;
    }
}

// ---------------- edge dtype detection ----------------
__global__ void detect_kernel(const unsigned int* e) {
    if (blockIdx.x == 0 && threadIdx.x == 0) {
        int ok = 1;
        #pragma unroll 1
        for (int i = 0; i < 64; i++)
            if (e[2 * i + 1] != 0u) { ok = 0; break; }
        g_is64 = ok;
    }
}
__device__ __forceinline__ int edge_at(const void* e, int idx, int is64) {
    if (is64) return (int)((const long long*)e)[idx];
    return ((const int*)e)[idx];
}

// ---------------- CSR build ----------------
__global__ void zero_cnt_kernel(int* cnt, int n) {
    int i  = blockIdx.x * blockDim.x + threadIdx.x;
    int st = gridDim.x * blockDim.x;
    for (; i < n; i += st) cnt[i] = 0;
}
__global__ void count_kernel(const void* edges, int* cnt, int E) {
    int is64 = g_is64;
    int i  = blockIdx.x * blockDim.x + threadIdx.x;
    int st = gridDim.x * blockDim.x;
    for (; i < E; i += st) {
        int d = edge_at(edges, E + i, is64);
        atomicAdd(&cnt[d], 1);
    }
}
__global__ void dinv_kernel(const int* __restrict__ cnt, float* dinv, int n) {
    int i  = blockIdx.x * blockDim.x + threadIdx.x;
    int st = gridDim.x * blockDim.x;
    for (; i < n; i += st) dinv[i] = rsqrtf((float)cnt[i] + 1.0f);
}
__global__ void __launch_bounds__(1024)
scan_kernel(const int* __restrict__ cnt, int* row_ptr, int* cursor) {
    const int T = 1024;
    const int C = TOTN / T;
    int tid  = threadIdx.x;
    int base = tid * C;
    int s = 0;
    #pragma unroll 8
    for (int c = 0; c < C; c++) s += cnt[base + c];
    __shared__ int sh[T];
    sh[tid] = s;
    __syncthreads();
    for (int off = 1; off < T; off <<= 1) {
        int v = (tid >= off) ? sh[tid - off] : 0;
        __syncthreads();
        sh[tid] += v;
        __syncthreads();
    }
    int run = sh[tid] - s;
    #pragma unroll 8
    for (int c = 0; c < C; c++) {
        row_ptr[base + c] = run;
        cursor[base + c]  = run;
        run += cnt[base + c];
    }
    if (tid == T - 1) row_ptr[TOTN] = run;
}
__global__ void fill_kernel(const void* edges, int* cursor, int* adj, int E) {
    int is64 = g_is64;
    int i  = blockIdx.x * blockDim.x + threadIdx.x;
    int st = gridDim.x * blockDim.x;
    for (; i < E; i += st) {
        int s = edge_at(edges, i, is64);
        int d = edge_at(edges, E + i, is64);
        int pos = atomicAdd(&cursor[d], 1);
        adj[pos] = s;
    }
}

// ---------------- CSR gather + fused epilogue ----------------
// OUT[d] = di^2 * ( sum_{s in N(d)} dinv[s]*X[s]  +  X[d] )   (+bias, relu)
template <int D, int BIASRELU>
__global__ void gather_kernel(const int* __restrict__ row_ptr, const int* __restrict__ adj,
                              const float* __restrict__ dinv, const float* __restrict__ X,
                              const float* __restrict__ bias, float* __restrict__ OUT, int n) {
    int lane = threadIdx.x & 31;
    int node = (blockIdx.x * blockDim.x + threadIdx.x) >> 5;
    if (node >= n) return;
    int beg = row_ptr[node];
    int end = row_ptr[node + 1];
    float di = dinv[node];
    float c  = di * di;
    if (D == 64) {
        float ax = 0.0f, ay = 0.0f;
        for (int j = beg; j < end; j++) {
            int s = adj[j];
            float ws = __ldg(&dinv[s]);
            float2 v = ((const float2*)(X + (size_t)s * 64))[lane];
            ax = fmaf(ws, v.x, ax);
            ay = fmaf(ws, v.y, ay);
        }
        float2 xv = ((const float2*)(X + (size_t)node * 64))[lane];
        float2 o;
        o.x = c * (ax + xv.x);
        o.y = c * (ay + xv.y);
        if (BIASRELU) {
            o.x = fmaxf(o.x + bias[2 * lane],     0.0f);
            o.y = fmaxf(o.y + bias[2 * lane + 1], 0.0f);
        }
        ((float2*)(OUT + (size_t)node * 64))[lane] = o;
    } else {
        float acc = 0.0f;
        for (int j = beg; j < end; j++) {
            int s = adj[j];
            float ws = __ldg(&dinv[s]);
            acc = fmaf(ws, X[(size_t)s * 32 + lane], acc);
        }
        float v = c * (acc + X[(size_t)node * 32 + lane]);
        if (BIASRELU) v = fmaxf(v + bias[lane], 0.0f);
        OUT[(size_t)node * 32 + lane] = v;
    }
}

// ---------------- 3 scalar heads ----------------
__global__ void heads_kernel(const float* __restrict__ X,
                             const float* __restrict__ Wpi, const float* __restrict__ bpi,
                             const float* __restrict__ Wn,  const float* __restrict__ bn,
                             const float* __restrict__ Wp,  const float* __restrict__ bp,
                             float* __restrict__ out, int M) {
    int lane = threadIdx.x & 31;
    int warp = (blockIdx.x * blockDim.x + threadIdx.x) >> 5;
    int nw   = (gridDim.x * blockDim.x) >> 5;
    float4 wa = ((const float4*)Wpi)[lane];
    float4 wb = ((const float4*)Wn)[lane];
    float4 wc = ((const float4*)Wp)[lane];
    for (int r = warp; r < M; r += nw) {
        float4 x = ((const float4*)(X + (size_t)r * 128))[lane];
        float s1 = x.x * wa.x + x.y * wa.y + x.z * wa.z + x.w * wa.w;
        float s2 = x.x * wb.x + x.y * wb.y + x.z * wb.z + x.w * wb.w;
        float s3 = x.x * wc.x + x.y * wc.y + x.z * wc.z + x.w * wc.w;
        #pragma unroll
        for (int o = 16; o > 0; o >>= 1) {
            s1 += __shfl_xor_sync(0xffffffffu, s1, o);
            s2 += __shfl_xor_sync(0xffffffffu, s2, o);
            s3 += __shfl_xor_sync(0xffffffffu, s3, o);
        }
        if (lane == 0) {
            float zpi = s1 + bpi[0];
            float zn  = s2 + bn[0];
            float zp  = s3 + bp[0];
            out[r]         = 1.0f / (1.0f + expf(-zpi));
            out[M + r]     = (zn > 0.0f) ? (zn + log1pf(expf(-zn))) : log1pf(expf(zn));
            out[2 * M + r] = 1.0f / (1.0f + expf(-zp));
        }
    }
}

// ---------------- launch ----------------
extern "C" void kernel_launch(void* const* d_in, const int* in_sizes, int n_in,
                              void* d_out, int out_size) {
    const float* x     = (const float*)d_in[0];
    const void*  edges = d_in[1];
    const float* W1  = (const float*)d_in[3];  const float* b1  = (const float*)d_in[4];
    const float* W2  = (const float*)d_in[5];  const float* b2  = (const float*)d_in[6];
    const float* W3  = (const float*)d_in[7];  const float* b3  = (const float*)d_in[8];
    const float* tW1 = (const float*)d_in[9];  const float* tb1 = (const float*)d_in[10];
    const float* tW2 = (const float*)d_in[11]; const float* tb2 = (const float*)d_in[12];
    const float* tW3 = (const float*)d_in[13]; const float* tb3 = (const float*)d_in[14];
    const float* Wpi = (const float*)d_in[15]; const float* bpi = (const float*)d_in[16];
    const float* Wn  = (const float*)d_in[17]; const float* bn  = (const float*)d_in[18];
    const float* Wp  = (const float*)d_in[19]; const float* bp  = (const float*)d_in[20];
    float* out = (float*)d_out;

    const int TOT = in_sizes[0] / FDIM;
    const int E   = in_sizes[1] / 2;

    float *dinv, *A1, *H1, *H2raw, *H2, *A3, *H3, *C1, *C2, *C3;
    int *cnt, *rowp, *curs, *adj;
    cudaGetSymbolAddress((void**)&dinv,  g_dinv);
    cudaGetSymbolAddress((void**)&cnt,   g_cnt);
    cudaGetSymbolAddress((void**)&rowp,  g_rowp);
    cudaGetSymbolAddress((void**)&curs,  g_curs);
    cudaGetSymbolAddress((void**)&adj,   g_adj);
    cudaGetSymbolAddress((void**)&A1,    g_A1);
    cudaGetSymbolAddress((void**)&H1,    g_H1);
    cudaGetSymbolAddress((void**)&H2raw, g_H2raw);
    cudaGetSymbolAddress((void**)&H2,    g_H2);
    cudaGetSymbolAddress((void**)&A3,    g_A3);
    cudaGetSymbolAddress((void**)&H3,    g_H3);
    cudaGetSymbolAddress((void**)&C1,    g_C1);
    cudaGetSymbolAddress((void**)&C2,    g_C2);
    cudaGetSymbolAddress((void**)&C3,    g_C3);

    const int gatherBlocks = (TOT * 32) / 256;
    const int grid = TOT / 128;

    // dynamic smem: (128 + COUT) * (KCH+8) * 2 bytes * 2 planes
    const int SM_K64_N128 = (128 + 128) * 72 * 2 * 2;  // 73728
    const int SM_K64_N32  = (128 + 32)  * 72 * 2 * 2;  // 46080
    const int SM_K32_N128 = (128 + 128) * 40 * 2 * 2;  // 40960

    cudaFuncSetAttribute(mma_layer<64, 128, 1, 64, 0, 1, 1>, cudaFuncAttributeMaxDynamicSharedMemorySize, SM_K64_N128);
    cudaFuncSetAttribute(mma_layer<128, 32, 1, 64, 0, 0, 0>, cudaFuncAttributeMaxDynamicSharedMemorySize, SM_K64_N32);
    cudaFuncSetAttribute(mma_layer<32, 128, 1, 32, 0, 1, 1>, cudaFuncAttributeMaxDynamicSharedMemorySize, SM_K32_N128);
    cudaFuncSetAttribute(mma_layer<128, 128, 3, 64, 1, 1, 1>, cudaFuncAttributeMaxDynamicSharedMemorySize, SM_K64_N128);
    cudaFuncSetAttribute(mma_layer<128, 32, 3, 64, 1, 1, 1>, cudaFuncAttributeMaxDynamicSharedMemorySize, SM_K64_N32);
    cudaFuncSetAttribute(mma_layer<32, 128, 3, 32, 1, 1, 1>, cudaFuncAttributeMaxDynamicSharedMemorySize, SM_K32_N128);

    detect_kernel<<<1, 32>>>((const unsigned int*)edges);

    // ---- CSR build ----
    zero_cnt_kernel<<<256, 256>>>(cnt, TOT);
    count_kernel<<<2048, 256>>>(edges, cnt, E);
    dinv_kernel<<<256, 256>>>(cnt, dinv, TOT);
    scan_kernel<<<1, 1024>>>(cnt, rowp, curs);
    fill_kernel<<<2048, 256>>>(edges, curs, adj, E);

    // ---- GCN layer 1: gather raw input, then tensor GEMM ----
    gather_kernel<64, 0><<<gatherBlocks, 256>>>(rowp, adj, dinv, x, nullptr, A1, TOT);
    mma_layer<64, 128, 1, 64, 0, 1, 1><<<grid, 256, SM_K64_N128>>>(A1, W1, b1, H1);

    // ---- GCN layer 2 ----
    mma_layer<128, 32, 1, 64, 0, 0, 0><<<grid, 256, SM_K64_N32>>>(H1, W2, nullptr, H2raw);
    gather_kernel<32, 1><<<gatherBlocks, 256>>>(rowp, adj, dinv, H2raw, b2, H2, TOT);

    // ---- GCN layer 3 ----
    gather_kernel<32, 0><<<gatherBlocks, 256>>>(rowp, adj, dinv, H2, nullptr, A3, TOT);
    mma_layer<32, 128, 1, 32, 0, 1, 1><<<grid, 256, SM_K32_N128>>>(A3, W3, b3, H3);

    // ---- temporal conv stack (k=3, pad=1) ----
    mma_layer<128, 128, 3, 64, 1, 1, 1><<<grid, 256, SM_K64_N128>>>(H3, tW1, tb1, C1);
    mma_layer<128, 32, 3, 64, 1, 1, 1><<<grid, 256, SM_K64_N32>>>(C1, tW2, tb2, C2);
    mma_layer<32, 128, 3, 32, 1, 1, 1><<<grid, 256, SM_K32_N128>>>(C2, tW3, tb3, C3);

    // ---- heads ----
    heads_kernel<<<TOT / 8, 256>>>(C3, Wpi, bpi, Wn, bn, Wp, bp, out, TOT);
}

// round 7
// speedup vs baseline: 1.8675x; 1.1777x over previous
#include <cuda_runtime.h>
#include <cuda_bf16.h>
#include <math.h>
#include <stdint.h>

// ---------------- problem constants ----------------
#define TOTN   131072      // B*N nodes
#define EMAX   1048576
#define FDIM   64
#define HSD    128
#define RSD    32
#define NPG    4096        // nodes per graph (temporal length)

typedef __nv_bfloat16 bf16;

// ---------------- device scratch (no cudaMalloc allowed) ----------------
__device__ int   g_is64;
__device__ float g_dinv [TOTN];
__device__ int   g_cnt  [TOTN];
__device__ int   g_rowp [TOTN + 1];
__device__ int   g_curs [TOTN];
__device__ int   g_adj  [EMAX];
// bf16 hi/lo planes for mma inputs
__device__ bf16  g_A1h[TOTN * FDIM], g_A1l[TOTN * FDIM];
__device__ bf16  g_H1h[TOTN * HSD],  g_H1l[TOTN * HSD];
__device__ bf16  g_A3h[TOTN * RSD],  g_A3l[TOTN * RSD];
__device__ bf16  g_H3h[TOTN * HSD],  g_H3l[TOTN * HSD];
__device__ bf16  g_C1h[TOTN * HSD],  g_C1l[TOTN * HSD];
__device__ bf16  g_C2h[TOTN * RSD],  g_C2l[TOTN * RSD];
// fp32 intermediates
__device__ float g_H2raw[TOTN * RSD];
__device__ float g_H2   [TOTN * RSD];
__device__ float g_C3   [TOTN * HSD];

__device__ __forceinline__ uint32_t pack_bf(float a, float b) {
    __nv_bfloat162 t;
    t.x = __float2bfloat16(a);
    t.y = __float2bfloat16(b);
    return *reinterpret_cast<uint32_t*>(&t);
}
__device__ __forceinline__ uint32_t smem_u32(const void* p) {
    uint32_t a;
    asm("{ .reg .u64 t; cvta.to.shared.u64 t, %1; cvt.u32.u64 %0, t; }" : "=r"(a) : "l"(p));
    return a;
}
// m16n8k16 row.col f32.bf16.bf16.f32 (portable PTX, sm_80+)
__device__ __forceinline__ void mma16816(float* d, uint32_t a0, uint32_t a1, uint32_t a2,
                                         uint32_t a3, uint32_t b0, uint32_t b1) {
    asm volatile(
        "mma.sync.aligned.m16n8k16.row.col.f32.bf16.bf16.f32 "
        "{%0,%1,%2,%3}, {%4,%5,%6,%7}, {%8,%9}, {%0,%1,%2,%3};"
        : "+f"(d[0]), "+f"(d[1]), "+f"(d[2]), "+f"(d[3])
        : "r"(a0), "r"(a1), "r"(a2), "r"(a3), "r"(b0), "r"(b1));
}
__device__ __forceinline__ void ldsm4(uint32_t& r0, uint32_t& r1, uint32_t& r2, uint32_t& r3,
                                      uint32_t addr) {
    asm volatile("ldmatrix.sync.aligned.m8n8.x4.shared.b16 {%0,%1,%2,%3}, [%4];"
                 : "=r"(r0), "=r"(r1), "=r"(r2), "=r"(r3) : "r"(addr));
}

// =========== unified dense layer on tensor cores ===========
// OUT[r, n] = act( sum_{s<TAPS} sum_{c<CIN} Xplanes[r+s-1, c] * Wmat(n, c, s) + bias[n] )
// Inputs are bf16 hi/lo planes. 3-term split MMA, fp32 reg accumulation.
// CTA: 256 thr = 8 warps, 128 rows; warp w -> rows [w*16, w*16+16).
template <int CIN, int COUT, int TAPS, int KCH, int WCONV, int HASBIAS, int HASRELU, int OUTPLANES>
__global__ void __launch_bounds__(256)
mma_layer(const bf16* __restrict__ XH, const bf16* __restrict__ XL,
          const float* __restrict__ W, const float* __restrict__ bias,
          float* __restrict__ OUT, bf16* __restrict__ OH, bf16* __restrict__ OL) {
    constexpr int NCHC  = CIN / KCH;          // channel chunks
    constexpr int P     = KCH + 8;            // bf16 pitch; %8==0 -> 16B-aligned rows
    constexpr int NT    = COUT / 8;           // n-octets per warp
    constexpr int HALO  = (TAPS == 3) ? 1 : 0;
    constexpr int RSTG  = 128 + 2 * HALO;

    extern __shared__ __align__(16) char smem[];
    bf16* Ah = (bf16*)smem;                 // [RSTG][P]
    bf16* Al = Ah + RSTG * P;
    bf16* Bh = Al + RSTG * P;               // [COUT][P]
    bf16* Bl = Bh + COUT * P;

    const uint32_t sb   = smem_u32(smem);
    const uint32_t sAh  = sb;
    const uint32_t sAl  = sAh + RSTG * P * 2;
    const uint32_t sBh  = sAl + RSTG * P * 2;
    const uint32_t sBl  = sBh + COUT * P * 2;

    int tid  = threadIdx.x;
    int w    = tid >> 5;
    int lane = tid & 31;
    int gid  = lane >> 2;
    int qid  = lane & 3;
    int seg  = lane >> 3;
    int rin  = lane & 7;
    int row0 = blockIdx.x * 128;
    int gb   = (row0 / NPG) * NPG;

    // ldmatrix per-lane address components
    int arow = w * 16 + rin + ((seg & 1) << 3);   // + s per tap
    int acol = (seg >> 1) << 3;                   // + kc
    int brow = rin + ((seg >> 1) << 3);           // + g*16
    int bcol = (seg & 1) << 3;                    // + kc

    float d[NT][4];
    #pragma unroll
    for (int t = 0; t < NT; t++)
        #pragma unroll
        for (int i = 0; i < 4; i++) d[t][i] = 0.0f;

    for (int c = 0; c < NCHC; c++) {
        const int c0 = c * KCH;
        // ---- stage A chunk (with halo), plain u32 plane copies ----
        for (int idx = tid; idx < RSTG * (KCH / 2); idx += 256) {
            int r = idx / (KCH / 2);
            int j = (idx % (KCH / 2)) * 2;
            long src = (long)row0 - HALO + r;
            uint32_t vh = 0, vl = 0;
            if (!HALO || (src >= gb && src < (long)gb + NPG)) {
                vh = *(const uint32_t*)&XH[src * CIN + c0 + j];
                vl = *(const uint32_t*)&XL[src * CIN + c0 + j];
            }
            *(uint32_t*)&Ah[r * P + j] = vh;
            *(uint32_t*)&Al[r * P + j] = vl;
        }

        #pragma unroll
        for (int s = 0; s < TAPS; s++) {
            // ---- stage B(tap s): fp32 -> hi/lo bf16 ----
            for (int idx = tid; idx < COUT * (KCH / 2); idx += 256) {
                int n = idx / (KCH / 2);
                int j = (idx % (KCH / 2)) * 2;
                float w0, w1;
                if (WCONV) {
                    w0 = W[((size_t)n * CIN + (c0 + j)) * 3 + s];
                    w1 = W[((size_t)n * CIN + (c0 + j + 1)) * 3 + s];
                } else {
                    w0 = W[(size_t)(c0 + j) * COUT + n];
                    w1 = W[(size_t)(c0 + j + 1) * COUT + n];
                }
                bf16 h0 = __float2bfloat16(w0);
                bf16 h1 = __float2bfloat16(w1);
                *(uint32_t*)&Bh[n * P + j] = pack_bf(w0, w1);  // hi = bf16(w)
                *(uint32_t*)&Bl[n * P + j] = pack_bf(w0 - __bfloat162float(h0),
                                                     w1 - __bfloat162float(h1));
            }
            __syncthreads();

            // ---- MMA over this K chunk, tap-shifted A rows ----
            #pragma unroll
            for (int ks = 0; ks < KCH / 16; ks++) {
                int kc = ks * 16;
                uint32_t aoff = (uint32_t)((arow + s) * P + kc + acol) * 2;
                uint32_t ah0, ah1, ah2, ah3, al0, al1, al2, al3;
                ldsm4(ah0, ah1, ah2, ah3, sAh + aoff);
                ldsm4(al0, al1, al2, al3, sAl + aoff);
                #pragma unroll
                for (int g = 0; g < NT / 2; g++) {
                    uint32_t boff = (uint32_t)((g * 16 + brow) * P + kc + bcol) * 2;
                    uint32_t bh0, bh1, bh2, bh3, bl0, bl1, bl2, bl3;
                    ldsm4(bh0, bh1, bh2, bh3, sBh + boff);
                    ldsm4(bl0, bl1, bl2, bl3, sBl + boff);
                    mma16816(d[2 * g],     ah0, ah1, ah2, ah3, bh0, bh1);
                    mma16816(d[2 * g],     ah0, ah1, ah2, ah3, bl0, bl1);
                    mma16816(d[2 * g],     al0, al1, al2, al3, bh0, bh1);
                    mma16816(d[2 * g + 1], ah0, ah1, ah2, ah3, bh2, bh3);
                    mma16816(d[2 * g + 1], ah0, ah1, ah2, ah3, bl2, bl3);
                    mma16816(d[2 * g + 1], al0, al1, al2, al3, bh2, bh3);
                }
            }
            __syncthreads();
        }
    }

    // ---- epilogue ----
    int r0 = row0 + w * 16 + gid;
    #pragma unroll
    for (int t = 0; t < NT; t++) {
        int n = t * 8 + qid * 2;
        float2 v0 = make_float2(d[t][0], d[t][1]);
        float2 v1 = make_float2(d[t][2], d[t][3]);
        if (HASBIAS) {
            float bx = bias[n], by = bias[n + 1];
            v0.x += bx; v0.y += by;
            v1.x += bx; v1.y += by;
        }
        if (HASRELU) {
            v0.x = fmaxf(v0.x, 0.0f); v0.y = fmaxf(v0.y, 0.0f);
            v1.x = fmaxf(v1.x, 0.0f); v1.y = fmaxf(v1.y, 0.0f);
        }
        if (OUTPLANES) {
            bf16 h0 = __float2bfloat16(v0.x), h1 = __float2bfloat16(v0.y);
            bf16 h2 = __float2bfloat16(v1.x), h3 = __float2bfloat16(v1.y);
            *(uint32_t*)&OH[(size_t)r0 * COUT + n]       = pack_bf(v0.x, v0.y);
            *(uint32_t*)&OL[(size_t)r0 * COUT + n]       = pack_bf(v0.x - __bfloat162float(h0),
                                                                   v0.y - __bfloat162float(h1));
            *(uint32_t*)&OH[(size_t)(r0 + 8) * COUT + n] = pack_bf(v1.x, v1.y);
            *(uint32_t*)&OL[(size_t)(r0 + 8) * COUT + n] = pack_bf(v1.x - __bfloat162float(h2),
                                                                   v1.y - __bfloat162float(h3));
        } else {
            *(float2*)&OUT[(size_t)r0 * COUT + n]       = v0;
            *(float2*)&OUT[(size_t)(r0 + 8) * COUT + n] = v1;
        }
    }
}

// ---------------- edge dtype detection ----------------
__global__ void detect_kernel(const unsigned int* e) {
    if (blockIdx.x == 0 && threadIdx.x == 0) {
        int ok = 1;
        #pragma unroll 1
        for (int i = 0; i < 64; i++)
            if (e[2 * i + 1] != 0u) { ok = 0; break; }
        g_is64 = ok;
    }
}
__device__ __forceinline__ int edge_at(const void* e, int idx, int is64) {
    if (is64) return (int)((const long long*)e)[idx];
    return ((const int*)e)[idx];
}

// ---------------- CSR build ----------------
__global__ void zero_cnt_kernel(int* cnt, int n) {
    int i  = blockIdx.x * blockDim.x + threadIdx.x;
    int st = gridDim.x * blockDim.x;
    for (; i < n; i += st) cnt[i] = 0;
}
__global__ void count_kernel(const void* edges, int* cnt, int E) {
    int is64 = g_is64;
    int i  = blockIdx.x * blockDim.x + threadIdx.x;
    int st = gridDim.x * blockDim.x;
    for (; i < E; i += st) {
        int d = edge_at(edges, E + i, is64);
        atomicAdd(&cnt[d], 1);
    }
}
__global__ void dinv_kernel(const int* __restrict__ cnt, float* dinv, int n) {
    int i  = blockIdx.x * blockDim.x + threadIdx.x;
    int st = gridDim.x * blockDim.x;
    for (; i < n; i += st) dinv[i] = rsqrtf((float)cnt[i] + 1.0f);
}
__global__ void __launch_bounds__(1024)
scan_kernel(const int* __restrict__ cnt, int* row_ptr, int* cursor) {
    const int T = 1024;
    const int C = TOTN / T;
    int tid  = threadIdx.x;
    int base = tid * C;
    int s = 0;
    #pragma unroll 8
    for (int c = 0; c < C; c++) s += cnt[base + c];
    __shared__ int sh[T];
    sh[tid] = s;
    __syncthreads();
    for (int off = 1; off < T; off <<= 1) {
        int v = (tid >= off) ? sh[tid - off] : 0;
        __syncthreads();
        sh[tid] += v;
        __syncthreads();
    }
    int run = sh[tid] - s;
    #pragma unroll 8
    for (int c = 0; c < C; c++) {
        row_ptr[base + c] = run;
        cursor[base + c]  = run;
        run += cnt[base + c];
    }
    if (tid == T - 1) row_ptr[TOTN] = run;
}
__global__ void fill_kernel(const void* edges, int* cursor, int* adj, int E) {
    int is64 = g_is64;
    int i  = blockIdx.x * blockDim.x + threadIdx.x;
    int st = gridDim.x * blockDim.x;
    for (; i < E; i += st) {
        int s = edge_at(edges, i, is64);
        int d = edge_at(edges, E + i, is64);
        int pos = atomicAdd(&cursor[d], 1);
        adj[pos] = s;
    }
}

// ---------------- CSR gather + fused epilogue ----------------
// OUT[d] = di^2 * ( sum_{s in N(d)} dinv[s]*X[s]  +  X[d] )   (+bias, relu)
// OUTPLANES: emit bf16 hi/lo planes instead of fp32.
template <int D, int BIASRELU, int OUTPLANES>
__global__ void gather_kernel(const int* __restrict__ row_ptr, const int* __restrict__ adj,
                              const float* __restrict__ dinv, const float* __restrict__ X,
                              const float* __restrict__ bias, float* __restrict__ OUT,
                              bf16* __restrict__ OH, bf16* __restrict__ OL, int n) {
    int lane = threadIdx.x & 31;
    int node = (blockIdx.x * blockDim.x + threadIdx.x) >> 5;
    if (node >= n) return;
    int beg = row_ptr[node];
    int end = row_ptr[node + 1];
    float di = dinv[node];
    float c  = di * di;
    if (D == 64) {
        float ax = 0.0f, ay = 0.0f;
        for (int j = beg; j < end; j++) {
            int s = adj[j];
            float ws = __ldg(&dinv[s]);
            float2 v = ((const float2*)(X + (size_t)s * 64))[lane];
            ax = fmaf(ws, v.x, ax);
            ay = fmaf(ws, v.y, ay);
        }
        float2 xv = ((const float2*)(X + (size_t)node * 64))[lane];
        float2 o;
        o.x = c * (ax + xv.x);
        o.y = c * (ay + xv.y);
        if (BIASRELU) {
            o.x = fmaxf(o.x + bias[2 * lane],     0.0f);
            o.y = fmaxf(o.y + bias[2 * lane + 1], 0.0f);
        }
        if (OUTPLANES) {
            bf16 hx = __float2bfloat16(o.x), hy = __float2bfloat16(o.y);
            *(uint32_t*)&OH[(size_t)node * 64 + 2 * lane] = pack_bf(o.x, o.y);
            *(uint32_t*)&OL[(size_t)node * 64 + 2 * lane] = pack_bf(o.x - __bfloat162float(hx),
                                                                    o.y - __bfloat162float(hy));
        } else {
            ((float2*)(OUT + (size_t)node * 64))[lane] = o;
        }
    } else {
        float acc = 0.0f;
        for (int j = beg; j < end; j++) {
            int s = adj[j];
            float ws = __ldg(&dinv[s]);
            acc = fmaf(ws, X[(size_t)s * 32 + lane], acc);
        }
        float v = c * (acc + X[(size_t)node * 32 + lane]);
        if (BIASRELU) v = fmaxf(v + bias[lane], 0.0f);
        if (OUTPLANES) {
            bf16 h = __float2bfloat16(v);
            OH[(size_t)node * 32 + lane] = h;
            OL[(size_t)node * 32 + lane] = __float2bfloat16(v - __bfloat162float(h));
        } else {
            OUT[(size_t)node * 32 + lane] = v;
        }
    }
}

// ---------------- 3 scalar heads ----------------
__global__ void heads_kernel(const float* __restrict__ X,
                             const float* __restrict__ Wpi, const float* __restrict__ bpi,
                             const float* __restrict__ Wn,  const float* __restrict__ bn,
                             const float* __restrict__ Wp,  const float* __restrict__ bp,
                             float* __restrict__ out, int M) {
    int lane = threadIdx.x & 31;
    int warp = (blockIdx.x * blockDim.x + threadIdx.x) >> 5;
    int nw   = (gridDim.x * blockDim.x) >> 5;
    float4 wa = ((const float4*)Wpi)[lane];
    float4 wb = ((const float4*)Wn)[lane];
    float4 wc = ((const float4*)Wp)[lane];
    for (int r = warp; r < M; r += nw) {
        float4 x = ((const float4*)(X + (size_t)r * 128))[lane];
        float s1 = x.x * wa.x + x.y * wa.y + x.z * wa.z + x.w * wa.w;
        float s2 = x.x * wb.x + x.y * wb.y + x.z * wb.z + x.w * wb.w;
        float s3 = x.x * wc.x + x.y * wc.y + x.z * wc.z + x.w * wc.w;
        #pragma unroll
        for (int o = 16; o > 0; o >>= 1) {
            s1 += __shfl_xor_sync(0xffffffffu, s1, o);
            s2 += __shfl_xor_sync(0xffffffffu, s2, o);
            s3 += __shfl_xor_sync(0xffffffffu, s3, o);
        }
        if (lane == 0) {
            float zpi = s1 + bpi[0];
            float zn  = s2 + bn[0];
            float zp  = s3 + bp[0];
            out[r]         = 1.0f / (1.0f + expf(-zpi));
            out[M + r]     = (zn > 0.0f) ? (zn + log1pf(expf(-zn))) : log1pf(expf(zn));
            out[2 * M + r] = 1.0f / (1.0f + expf(-zp));
        }
    }
}

// ---------------- launch ----------------
extern "C" void kernel_launch(void* const* d_in, const int* in_sizes, int n_in,
                              void* d_out, int out_size) {
    const float* x     = (const float*)d_in[0];
    const void*  edges = d_in[1];
    const float* W1  = (const float*)d_in[3];  const float* b1  = (const float*)d_in[4];
    const float* W2  = (const float*)d_in[5];  const float* b2  = (const float*)d_in[6];
    const float* W3  = (const float*)d_in[7];  const float* b3  = (const float*)d_in[8];
    const float* tW1 = (const float*)d_in[9];  const float* tb1 = (const float*)d_in[10];
    const float* tW2 = (const float*)d_in[11]; const float* tb2 = (const float*)d_in[12];
    const float* tW3 = (const float*)d_in[13]; const float* tb3 = (const float*)d_in[14];
    const float* Wpi = (const float*)d_in[15]; const float* bpi = (const float*)d_in[16];
    const float* Wn  = (const float*)d_in[17]; const float* bn  = (const float*)d_in[18];
    const float* Wp  = (const float*)d_in[19]; const float* bp  = (const float*)d_in[20];
    float* out = (float*)d_out;

    const int TOT = in_sizes[0] / FDIM;
    const int E   = in_sizes[1] / 2;

    float *dinv, *H2raw, *H2, *C3;
    int *cnt, *rowp, *curs, *adj;
    bf16 *A1h, *A1l, *H1h, *H1l, *A3h, *A3l, *H3h, *H3l, *C1h, *C1l, *C2h, *C2l;
    cudaGetSymbolAddress((void**)&dinv,  g_dinv);
    cudaGetSymbolAddress((void**)&cnt,   g_cnt);
    cudaGetSymbolAddress((void**)&rowp,  g_rowp);
    cudaGetSymbolAddress((void**)&curs,  g_curs);
    cudaGetSymbolAddress((void**)&adj,   g_adj);
    cudaGetSymbolAddress((void**)&A1h,   g_A1h);  cudaGetSymbolAddress((void**)&A1l, g_A1l);
    cudaGetSymbolAddress((void**)&H1h,   g_H1h);  cudaGetSymbolAddress((void**)&H1l, g_H1l);
    cudaGetSymbolAddress((void**)&A3h,   g_A3h);  cudaGetSymbolAddress((void**)&A3l, g_A3l);
    cudaGetSymbolAddress((void**)&H3h,   g_H3h);  cudaGetSymbolAddress((void**)&H3l, g_H3l);
    cudaGetSymbolAddress((void**)&C1h,   g_C1h);  cudaGetSymbolAddress((void**)&C1l, g_C1l);
    cudaGetSymbolAddress((void**)&C2h,   g_C2h);  cudaGetSymbolAddress((void**)&C2l, g_C2l);
    cudaGetSymbolAddress((void**)&H2raw, g_H2raw);
    cudaGetSymbolAddress((void**)&H2,    g_H2);
    cudaGetSymbolAddress((void**)&C3,    g_C3);

    const int gatherBlocks = (TOT * 32) / 256;
    const int grid = TOT / 128;

    // smem bytes = (2*RSTG*P + 2*COUT*P) * 2
    const int SM_G1  = (2 * 130 * 72 + 2 * 128 * 72) * 2;  // mma1  (K64,N128)   74304
    const int SM_G2  = (2 * 130 * 72 + 2 * 32  * 72) * 2;  // mma2  (K64,N32)    46656
    const int SM_G3  = (2 * 130 * 40 + 2 * 128 * 40) * 2;  // mma3  (K32,N128)   41280
    const int SM_C1  = SM_G1;                              // conv1 (K64,N128)
    const int SM_C2  = SM_G2;                              // conv2 (K64,N32)
    const int SM_C3  = SM_G3;                              // conv3 (K32,N128)

    cudaFuncSetAttribute(mma_layer<64, 128, 1, 64, 0, 1, 1, 1>, cudaFuncAttributeMaxDynamicSharedMemorySize, SM_G1);
    cudaFuncSetAttribute(mma_layer<128, 32, 1, 64, 0, 0, 0, 0>, cudaFuncAttributeMaxDynamicSharedMemorySize, SM_G2);
    cudaFuncSetAttribute(mma_layer<32, 128, 1, 32, 0, 1, 1, 1>, cudaFuncAttributeMaxDynamicSharedMemorySize, SM_G3);
    cudaFuncSetAttribute(mma_layer<128, 128, 3, 64, 1, 1, 1, 1>, cudaFuncAttributeMaxDynamicSharedMemorySize, SM_C1);
    cudaFuncSetAttribute(mma_layer<128, 32, 3, 64, 1, 1, 1, 1>, cudaFuncAttributeMaxDynamicSharedMemorySize, SM_C2);
    cudaFuncSetAttribute(mma_layer<32, 128, 3, 32, 1, 1, 1, 0>, cudaFuncAttributeMaxDynamicSharedMemorySize, SM_C3);

    detect_kernel<<<1, 32>>>((const unsigned int*)edges);

    // ---- CSR build ----
    zero_cnt_kernel<<<256, 256>>>(cnt, TOT);
    count_kernel<<<2048, 256>>>(edges, cnt, E);
    dinv_kernel<<<256, 256>>>(cnt, dinv, TOT);
    scan_kernel<<<1, 1024>>>(cnt, rowp, curs);
    fill_kernel<<<2048, 256>>>(edges, curs, adj, E);

    // ---- GCN layer 1: gather raw input (emit planes), then MMA ----
    gather_kernel<64, 0, 1><<<gatherBlocks, 256>>>(rowp, adj, dinv, x, nullptr, nullptr, A1h, A1l, TOT);
    mma_layer<64, 128, 1, 64, 0, 1, 1, 1><<<grid, 256, SM_G1>>>(A1h, A1l, W1, b1, nullptr, H1h, H1l);

    // ---- GCN layer 2 ----
    mma_layer<128, 32, 1, 64, 0, 0, 0, 0><<<grid, 256, SM_G2>>>(H1h, H1l, W2, nullptr, H2raw, nullptr, nullptr);
    gather_kernel<32, 1, 0><<<gatherBlocks, 256>>>(rowp, adj, dinv, H2raw, b2, H2, nullptr, nullptr, TOT);

    // ---- GCN layer 3 ----
    gather_kernel<32, 0, 1><<<gatherBlocks, 256>>>(rowp, adj, dinv, H2, nullptr, nullptr, A3h, A3l, TOT);
    mma_layer<32, 128, 1, 32, 0, 1, 1, 1><<<grid, 256, SM_G3>>>(A3h, A3l, W3, b3, nullptr, H3h, H3l);

    // ---- temporal conv stack (k=3, pad=1) ----
    mma_layer<128, 128, 3, 64, 1, 1, 1, 1><<<grid, 256, SM_C1>>>(H3h, H3l, tW1, tb1, nullptr, C1h, C1l);
    mma_layer<128, 32, 3, 64, 1, 1, 1, 1><<<grid, 256, SM_C2>>>(C1h, C1l, tW2, tb2, nullptr, C2h, C2l);
    mma_layer<32, 128, 3, 32, 1, 1, 1, 0><<<grid, 256, SM_C3>>>(C2h, C2l, tW3, tb3, C3, nullptr, nullptr);

    // ---- heads ----
    heads_kernel<<<TOT / 8, 256>>>(C3, Wpi, bpi, Wn, bn, Wp, bp, out, TOT);
}

// round 8
// speedup vs baseline: 2.0278x; 1.0858x over previous
#include <cuda_runtime.h>
#include <cuda_bf16.h>
#include <math.h>
#include <stdint.h>

// ---------------- problem constants ----------------
#define TOTN   131072      // B*N nodes
#define EMAX   1048576
#define FDIM   64
#define HSD    128
#define RSD    32
#define NPG    4096        // nodes per graph (temporal length)

typedef __nv_bfloat16 bf16;

// ---------------- device scratch (no cudaMalloc allowed) ----------------
__device__ int   g_is64;
__device__ float g_dinv [TOTN];
__device__ int   g_cnt  [TOTN];
__device__ int   g_rowp [TOTN + 1];
__device__ int   g_curs [TOTN];
__device__ int   g_adj  [EMAX];
// bf16 hi/lo planes for activations
__device__ __align__(16) bf16 g_A1h[TOTN * FDIM], g_A1l[TOTN * FDIM];
__device__ __align__(16) bf16 g_H1h[TOTN * HSD],  g_H1l[TOTN * HSD];
__device__ __align__(16) bf16 g_A3h[TOTN * RSD],  g_A3l[TOTN * RSD];
__device__ __align__(16) bf16 g_H3h[TOTN * HSD],  g_H3l[TOTN * HSD];
__device__ __align__(16) bf16 g_C1h[TOTN * HSD],  g_C1l[TOTN * HSD];
__device__ __align__(16) bf16 g_C2h[TOTN * RSD],  g_C2l[TOTN * RSD];
// fp32 intermediates
__device__ float g_H2raw[TOTN * RSD];
__device__ float g_H2   [TOTN * RSD];
// weight planes (k-major [tap][COUT][CIN])
__device__ __align__(16) bf16 g_W1h[128 * 64],      g_W1l[128 * 64];
__device__ __align__(16) bf16 g_W2h[32 * 128],      g_W2l[32 * 128];
__device__ __align__(16) bf16 g_W3h[128 * 32],      g_W3l[128 * 32];
__device__ __align__(16) bf16 g_T1h[3 * 128 * 128], g_T1l[3 * 128 * 128];
__device__ __align__(16) bf16 g_T2h[3 * 32 * 128],  g_T2l[3 * 32 * 128];
__device__ __align__(16) bf16 g_T3h[3 * 128 * 32],  g_T3l[3 * 128 * 32];

__device__ __forceinline__ uint32_t pack_bf(float a, float b) {
    __nv_bfloat162 t;
    t.x = __float2bfloat16(a);
    t.y = __float2bfloat16(b);
    return *reinterpret_cast<uint32_t*>(&t);
}
__device__ __forceinline__ uint32_t smem_u32(const void* p) {
    uint32_t a;
    asm("{ .reg .u64 t; cvta.to.shared.u64 t, %1; cvt.u32.u64 %0, t; }" : "=r"(a) : "l"(p));
    return a;
}
__device__ __forceinline__ void mma16816(float* d, uint32_t a0, uint32_t a1, uint32_t a2,
                                         uint32_t a3, uint32_t b0, uint32_t b1) {
    asm volatile(
        "mma.sync.aligned.m16n8k16.row.col.f32.bf16.bf16.f32 "
        "{%0,%1,%2,%3}, {%4,%5,%6,%7}, {%8,%9}, {%0,%1,%2,%3};"
        : "+f"(d[0]), "+f"(d[1]), "+f"(d[2]), "+f"(d[3])
        : "r"(a0), "r"(a1), "r"(a2), "r"(a3), "r"(b0), "r"(b1));
}
__device__ __forceinline__ void ldsm4(uint32_t& r0, uint32_t& r1, uint32_t& r2, uint32_t& r3,
                                      uint32_t addr) {
    asm volatile("ldmatrix.sync.aligned.m8n8.x4.shared.b16 {%0,%1,%2,%3}, [%4];"
                 : "=r"(r0), "=r"(r1), "=r"(r2), "=r"(r3) : "r"(addr));
}

// ---------------- weight plane precompute ----------------
__device__ void wlin(const float* W, bf16* WH, bf16* WL, int CIN, int COUT, int tid, int nt) {
    for (int i = tid; i < CIN * COUT; i += nt) {
        int n = i / CIN, k = i % CIN;
        float w = W[(size_t)k * COUT + n];
        bf16 h = __float2bfloat16(w);
        WH[i] = h;
        WL[i] = __float2bfloat16(w - __bfloat162float(h));
    }
}
__device__ void wconv(const float* W, bf16* WH, bf16* WL, int CIN, int COUT, int tid, int nt) {
    for (int i = tid; i < 3 * CIN * COUT; i += nt) {
        int s = i / (CIN * COUT);
        int n = (i / CIN) % COUT;
        int k = i % CIN;
        float w = W[((size_t)n * CIN + k) * 3 + s];
        bf16 h = __float2bfloat16(w);
        WH[i] = h;
        WL[i] = __float2bfloat16(w - __bfloat162float(h));
    }
}
__global__ void wplanes_kernel(const float* W1, const float* W2, const float* W3,
                               const float* T1, const float* T2, const float* T3) {
    int tid = blockIdx.x * blockDim.x + threadIdx.x;
    int nt  = gridDim.x * blockDim.x;
    wlin(W1, g_W1h, g_W1l, 64, 128, tid, nt);
    wlin(W2, g_W2h, g_W2l, 128, 32, tid, nt);
    wlin(W3, g_W3h, g_W3l, 32, 128, tid, nt);
    wconv(T1, g_T1h, g_T1l, 128, 128, tid, nt);
    wconv(T2, g_T2h, g_T2l, 128, 32, tid, nt);
    wconv(T3, g_T3h, g_T3l, 32, 128, tid, nt);
}

// =========== unified dense layer on tensor cores ===========
template <int CIN, int COUT, int TAPS, int KCH, int HASBIAS, int HASRELU, int OUTPLANES, int HEADS>
__global__ void __launch_bounds__(256, 2)
mma_layer(const bf16* __restrict__ XH, const bf16* __restrict__ XL,
          const bf16* __restrict__ WH, const bf16* __restrict__ WL,
          const float* __restrict__ bias,
          float* __restrict__ OUT, bf16* __restrict__ OH, bf16* __restrict__ OL,
          const float* __restrict__ HWpi, const float* __restrict__ HWn,
          const float* __restrict__ HWp, const float* __restrict__ Hbpi,
          const float* __restrict__ Hbn, const float* __restrict__ Hbp,
          float* __restrict__ hout) {
    constexpr int NCHC = CIN / KCH;
    constexpr int P    = KCH + 8;
    constexpr int HALO = (TAPS == 3) ? 1 : 0;
    constexpr int RSTG = 128 + 2 * HALO;
    constexpr bool BIG = (COUT == 128);
    constexpr bool ALLTAPS = (TAPS == 3) && (COUT == 32 || CIN == 32);
    constexpr int BTAPS = ALLTAPS ? 3 : 1;
    constexpr int U4   = KCH / 8;
    constexpr int FD   = BIG ? 2 : 1;
    constexpr int TD   = BIG ? 8 : 4;

    extern __shared__ __align__(16) char smem[];
    bf16* Ah = (bf16*)smem;
    bf16* Al = Ah + RSTG * P;
    bf16* Bh = Al + RSTG * P;
    bf16* Bl = Bh + BTAPS * COUT * P;
    float* hbuf = (float*)(Bl + BTAPS * COUT * P);   // [3][128] when HEADS

    const uint32_t sb  = smem_u32(smem);
    const uint32_t sAh = sb;
    const uint32_t sAl = sAh + RSTG * P * 2;
    const uint32_t sBh = sAl + RSTG * P * 2;
    const uint32_t sBl = sBh + BTAPS * COUT * P * 2;

    int tid  = threadIdx.x;
    int w    = tid >> 5;
    int lane = tid & 31;
    int gid  = lane >> 2;
    int qid  = lane & 3;
    int seg  = lane >> 3;
    int rin  = lane & 7;
    int row0 = blockIdx.x * 128;
    int gb   = (row0 / NPG) * NPG;
    int wm   = BIG ? (w & 3) : w;
    int wn   = BIG ? (w >> 2) : 0;

    float d[FD][TD][4];
    #pragma unroll
    for (int f = 0; f < FD; f++)
        #pragma unroll
        for (int t = 0; t < TD; t++)
            #pragma unroll
            for (int i = 0; i < 4; i++) d[f][t][i] = 0.0f;

    for (int c = 0; c < NCHC; c++) {
        const int c0 = c * KCH;
        // ---- stage A chunk (uint4 copies) ----
        for (int idx = tid; idx < RSTG * U4; idx += 256) {
            int r = idx / U4;
            int j = (idx % U4) * 8;
            long src = (long)row0 - HALO + r;
            uint4 vh = make_uint4(0, 0, 0, 0), vl = vh;
            if (!HALO || (src >= gb && src < (long)gb + NPG)) {
                vh = *(const uint4*)&XH[src * CIN + c0 + j];
                vl = *(const uint4*)&XL[src * CIN + c0 + j];
            }
            *(uint4*)&Ah[r * P + j] = vh;
            *(uint4*)&Al[r * P + j] = vl;
        }

        if (ALLTAPS) {
            // stage all taps' B once
            for (int idx = tid; idx < BTAPS * COUT * U4; idx += 256) {
                int n2 = idx / U4;
                int j  = (idx % U4) * 8;
                *(uint4*)&Bh[n2 * P + j] = *(const uint4*)&WH[(size_t)n2 * CIN + c0 + j];
                *(uint4*)&Bl[n2 * P + j] = *(const uint4*)&WL[(size_t)n2 * CIN + c0 + j];
            }
            __syncthreads();
        }

        #pragma unroll
        for (int s = 0; s < TAPS; s++) {
            if (!ALLTAPS) {
                for (int idx = tid; idx < COUT * U4; idx += 256) {
                    int n = idx / U4;
                    int j = (idx % U4) * 8;
                    *(uint4*)&Bh[n * P + j] = *(const uint4*)&WH[((size_t)s * COUT + n) * CIN + c0 + j];
                    *(uint4*)&Bl[n * P + j] = *(const uint4*)&WL[((size_t)s * COUT + n) * CIN + c0 + j];
                }
                __syncthreads();
            }
            const int bt = ALLTAPS ? s : 0;

            #pragma unroll
            for (int ks = 0; ks < KCH / 16; ks++) {
                int kc = ks * 16;
                if (BIG) {
                    uint32_t ah[FD][4], al[FD][4];
                    #pragma unroll
                    for (int f = 0; f < FD; f++) {
                        uint32_t aoff = (uint32_t)((wm * 32 + f * 16 + rin + ((seg & 1) << 3) + s) * P
                                                   + kc + ((seg >> 1) << 3)) * 2;
                        ldsm4(ah[f][0], ah[f][1], ah[f][2], ah[f][3], sAh + aoff);
                        ldsm4(al[f][0], al[f][1], al[f][2], al[f][3], sAl + aoff);
                    }
                    #pragma unroll
                    for (int g = 0; g < 4; g++) {
                        uint32_t boff = (uint32_t)(((bt * COUT) + wn * 64 + g * 16 + rin + ((seg >> 1) << 3)) * P
                                                   + kc + ((seg & 1) << 3)) * 2;
                        uint32_t bh0, bh1, bh2, bh3, bl0, bl1, bl2, bl3;
                        ldsm4(bh0, bh1, bh2, bh3, sBh + boff);
                        ldsm4(bl0, bl1, bl2, bl3, sBl + boff);
                        #pragma unroll
                        for (int f = 0; f < FD; f++) {
                            mma16816(d[f][2 * g],     ah[f][0], ah[f][1], ah[f][2], ah[f][3], bh0, bh1);
                            mma16816(d[f][2 * g],     ah[f][0], ah[f][1], ah[f][2], ah[f][3], bl0, bl1);
                            mma16816(d[f][2 * g],     al[f][0], al[f][1], al[f][2], al[f][3], bh0, bh1);
                            mma16816(d[f][2 * g + 1], ah[f][0], ah[f][1], ah[f][2], ah[f][3], bh2, bh3);
                            mma16816(d[f][2 * g + 1], ah[f][0], ah[f][1], ah[f][2], ah[f][3], bl2, bl3);
                            mma16816(d[f][2 * g + 1], al[f][0], al[f][1], al[f][2], al[f][3], bh2, bh3);
                        }
                    }
                } else {
                    uint32_t aoff = (uint32_t)((w * 16 + rin + ((seg & 1) << 3) + s) * P
                                               + kc + ((seg >> 1) << 3)) * 2;
                    uint32_t ah0, ah1, ah2, ah3, al0, al1, al2, al3;
                    ldsm4(ah0, ah1, ah2, ah3, sAh + aoff);
                    ldsm4(al0, al1, al2, al3, sAl + aoff);
                    #pragma unroll
                    for (int g = 0; g < 2; g++) {
                        uint32_t boff = (uint32_t)(((bt * COUT) + g * 16 + rin + ((seg >> 1) << 3)) * P
                                                   + kc + ((seg & 1) << 3)) * 2;
                        uint32_t bh0, bh1, bh2, bh3, bl0, bl1, bl2, bl3;
                        ldsm4(bh0, bh1, bh2, bh3, sBh + boff);
                        ldsm4(bl0, bl1, bl2, bl3, sBl + boff);
                        mma16816(d[0][2 * g],     ah0, ah1, ah2, ah3, bh0, bh1);
                        mma16816(d[0][2 * g],     ah0, ah1, ah2, ah3, bl0, bl1);
                        mma16816(d[0][2 * g],     al0, al1, al2, al3, bh0, bh1);
                        mma16816(d[0][2 * g + 1], ah0, ah1, ah2, ah3, bh2, bh3);
                        mma16816(d[0][2 * g + 1], ah0, ah1, ah2, ah3, bl2, bl3);
                        mma16816(d[0][2 * g + 1], al0, al1, al2, al3, bh2, bh3);
                    }
                }
            }
            if (!ALLTAPS) __syncthreads();
        }
        if (ALLTAPS) __syncthreads();
    }

    if (HEADS) {
        // fused heads: bias+relu then 3 dot products per row (fp32)
        float p1[2][2] = {}, p2[2][2] = {}, p3[2][2] = {};
        #pragma unroll
        for (int f = 0; f < FD; f++)
            #pragma unroll
            for (int t = 0; t < TD; t++) {
                int n = wn * 64 + t * 8 + qid * 2;
                float b0 = bias[n], b1 = bias[n + 1];
                float v00 = fmaxf(d[f][t][0] + b0, 0.0f);
                float v01 = fmaxf(d[f][t][1] + b1, 0.0f);
                float v10 = fmaxf(d[f][t][2] + b0, 0.0f);
                float v11 = fmaxf(d[f][t][3] + b1, 0.0f);
                float wa0 = HWpi[n], wa1 = HWpi[n + 1];
                float wb0 = HWn[n],  wb1 = HWn[n + 1];
                float wc0 = HWp[n],  wc1 = HWp[n + 1];
                p1[f][0] += v00 * wa0 + v01 * wa1;  p1[f][1] += v10 * wa0 + v11 * wa1;
                p2[f][0] += v00 * wb0 + v01 * wb1;  p2[f][1] += v10 * wb0 + v11 * wb1;
                p3[f][0] += v00 * wc0 + v01 * wc1;  p3[f][1] += v10 * wc0 + v11 * wc1;
            }
        #pragma unroll
        for (int f = 0; f < 2; f++)
            #pragma unroll
            for (int h = 0; h < 2; h++) {
                p1[f][h] += __shfl_xor_sync(0xffffffffu, p1[f][h], 1);
                p1[f][h] += __shfl_xor_sync(0xffffffffu, p1[f][h], 2);
                p2[f][h] += __shfl_xor_sync(0xffffffffu, p2[f][h], 1);
                p2[f][h] += __shfl_xor_sync(0xffffffffu, p2[f][h], 2);
                p3[f][h] += __shfl_xor_sync(0xffffffffu, p3[f][h], 1);
                p3[f][h] += __shfl_xor_sync(0xffffffffu, p3[f][h], 2);
            }
        if (wn == 0 && qid == 0) {
            #pragma unroll
            for (int f = 0; f < 2; f++) {
                int r = wm * 32 + f * 16 + gid;
                hbuf[r] = p1[f][0];        hbuf[r + 8] = p1[f][1];
                hbuf[128 + r] = p2[f][0];  hbuf[128 + r + 8] = p2[f][1];
                hbuf[256 + r] = p3[f][0];  hbuf[256 + r + 8] = p3[f][1];
            }
        }
        __syncthreads();
        if (wn == 1 && qid == 0) {
            #pragma unroll
            for (int f = 0; f < 2; f++)
                #pragma unroll
                for (int h = 0; h < 2; h++) {
                    int r = wm * 32 + f * 16 + gid + h * 8;
                    int rg = row0 + r;
                    float z1 = hbuf[r] + p1[f][h] + Hbpi[0];
                    float z2 = hbuf[128 + r] + p2[f][h] + Hbn[0];
                    float z3 = hbuf[256 + r] + p3[f][h] + Hbp[0];
                    hout[rg]            = 1.0f / (1.0f + expf(-z1));
                    hout[TOTN + rg]     = (z2 > 0.0f) ? (z2 + log1pf(expf(-z2))) : log1pf(expf(z2));
                    hout[2 * TOTN + rg] = 1.0f / (1.0f + expf(-z3));
                }
        }
    } else {
        // generic epilogue
        #pragma unroll
        for (int f = 0; f < FD; f++) {
            int r0 = row0 + (BIG ? (wm * 32 + f * 16) : (w * 16)) + gid;
            #pragma unroll
            for (int t = 0; t < TD; t++) {
                int n = (BIG ? wn * 64 : 0) + t * 8 + qid * 2;
                float2 v0 = make_float2(d[f][t][0], d[f][t][1]);
                float2 v1 = make_float2(d[f][t][2], d[f][t][3]);
                if (HASBIAS) {
                    float bx = bias[n], by = bias[n + 1];
                    v0.x += bx; v0.y += by;
                    v1.x += bx; v1.y += by;
                }
                if (HASRELU) {
                    v0.x = fmaxf(v0.x, 0.0f); v0.y = fmaxf(v0.y, 0.0f);
                    v1.x = fmaxf(v1.x, 0.0f); v1.y = fmaxf(v1.y, 0.0f);
                }
                if (OUTPLANES) {
                    bf16 h0 = __float2bfloat16(v0.x), h1 = __float2bfloat16(v0.y);
                    bf16 h2 = __float2bfloat16(v1.x), h3 = __float2bfloat16(v1.y);
                    *(uint32_t*)&OH[(size_t)r0 * COUT + n] = pack_bf(v0.x, v0.y);
                    *(uint32_t*)&OL[(size_t)r0 * COUT + n] = pack_bf(v0.x - __bfloat162float(h0),
                                                                     v0.y - __bfloat162float(h1));
                    *(uint32_t*)&OH[(size_t)(r0 + 8) * COUT + n] = pack_bf(v1.x, v1.y);
                    *(uint32_t*)&OL[(size_t)(r0 + 8) * COUT + n] = pack_bf(v1.x - __bfloat162float(h2),
                                                                           v1.y - __bfloat162float(h3));
                } else {
                    *(float2*)&OUT[(size_t)r0 * COUT + n]       = v0;
                    *(float2*)&OUT[(size_t)(r0 + 8) * COUT + n] = v1;
                }
            }
        }
    }
}

// ---------------- CSR build ----------------
__device__ __forceinline__ int edge_at(const void* e, int idx, int is64) {
    if (is64) return (int)((const long long*)e)[idx];
    return ((const int*)e)[idx];
}
// zero counts + detect edge dtype (block 0 thread 0)
__global__ void zero_detect_kernel(int* cnt, int n, const unsigned int* e) {
    int i  = blockIdx.x * blockDim.x + threadIdx.x;
    int st = gridDim.x * blockDim.x;
    for (; i < n; i += st) cnt[i] = 0;
    if (blockIdx.x == 0 && threadIdx.x == 0) {
        int ok = 1;
        #pragma unroll 1
        for (int k = 0; k < 64; k++)
            if (e[2 * k + 1] != 0u) { ok = 0; break; }
        g_is64 = ok;
    }
}
__global__ void count_kernel(const void* edges, int* cnt, int E) {
    int is64 = g_is64;
    int i  = blockIdx.x * blockDim.x + threadIdx.x;
    int st = gridDim.x * blockDim.x;
    for (; i < E; i += st) {
        int d = edge_at(edges, E + i, is64);
        atomicAdd(&cnt[d], 1);
    }
}
// scan + dinv fused
__global__ void __launch_bounds__(1024)
scan_kernel(const int* __restrict__ cnt, int* row_ptr, int* cursor, float* dinv) {
    const int T = 1024;
    const int C = TOTN / T;
    int tid  = threadIdx.x;
    int base = tid * C;
    int s = 0;
    #pragma unroll 8
    for (int c = 0; c < C; c++) s += cnt[base + c];
    __shared__ int sh[T];
    sh[tid] = s;
    __syncthreads();
    for (int off = 1; off < T; off <<= 1) {
        int v = (tid >= off) ? sh[tid - off] : 0;
        __syncthreads();
        sh[tid] += v;
        __syncthreads();
    }
    int run = sh[tid] - s;
    #pragma unroll 8
    for (int c = 0; c < C; c++) {
        int cc = cnt[base + c];
        row_ptr[base + c] = run;
        cursor[base + c]  = run;
        dinv[base + c]    = rsqrtf((float)cc + 1.0f);
        run += cc;
    }
    if (tid == T - 1) row_ptr[TOTN] = run;
}
__global__ void fill_kernel(const void* edges, int* cursor, int* adj, int E) {
    int is64 = g_is64;
    int i  = blockIdx.x * blockDim.x + threadIdx.x;
    int st = gridDim.x * blockDim.x;
    for (; i < E; i += st) {
        int s = edge_at(edges, i, is64);
        int d = edge_at(edges, E + i, is64);
        int pos = atomicAdd(&cursor[d], 1);
        adj[pos] = s;
    }
}

// ---------------- CSR gather + fused epilogue ----------------
template <int D, int BIASRELU, int OUTPLANES>
__global__ void gather_kernel(const int* __restrict__ row_ptr, const int* __restrict__ adj,
                              const float* __restrict__ dinv, const float* __restrict__ X,
                              const float* __restrict__ bias, float* __restrict__ OUT,
                              bf16* __restrict__ OH, bf16* __restrict__ OL, int n) {
    int lane = threadIdx.x & 31;
    int node = (blockIdx.x * blockDim.x + threadIdx.x) >> 5;
    if (node >= n) return;
    int beg = row_ptr[node];
    int end = row_ptr[node + 1];
    float di = dinv[node];
    float c  = di * di;
    if (D == 64) {
        float ax = 0.0f, ay = 0.0f;
        for (int j = beg; j < end; j++) {
            int s = adj[j];
            float ws = __ldg(&dinv[s]);
            float2 v = ((const float2*)(X + (size_t)s * 64))[lane];
            ax = fmaf(ws, v.x, ax);
            ay = fmaf(ws, v.y, ay);
        }
        float2 xv = ((const float2*)(X + (size_t)node * 64))[lane];
        float2 o;
        o.x = c * (ax + xv.x);
        o.y = c * (ay + xv.y);
        if (BIASRELU) {
            o.x = fmaxf(o.x + bias[2 * lane],     0.0f);
            o.y = fmaxf(o.y + bias[2 * lane + 1], 0.0f);
        }
        if (OUTPLANES) {
            bf16 hx = __float2bfloat16(o.x), hy = __float2bfloat16(o.y);
            *(uint32_t*)&OH[(size_t)node * 64 + 2 * lane] = pack_bf(o.x, o.y);
            *(uint32_t*)&OL[(size_t)node * 64 + 2 * lane] = pack_bf(o.x - __bfloat162float(hx),
                                                                    o.y - __bfloat162float(hy));
        } else {
            ((float2*)(OUT + (size_t)node * 64))[lane] = o;
        }
    } else {
        float acc = 0.0f;
        for (int j = beg; j < end; j++) {
            int s = adj[j];
            float ws = __ldg(&dinv[s]);
            acc = fmaf(ws, X[(size_t)s * 32 + lane], acc);
        }
        float v = c * (acc + X[(size_t)node * 32 + lane]);
        if (BIASRELU) v = fmaxf(v + bias[lane], 0.0f);
        if (OUTPLANES) {
            bf16 h = __float2bfloat16(v);
            OH[(size_t)node * 32 + lane] = h;
            OL[(size_t)node * 32 + lane] = __float2bfloat16(v - __bfloat162float(h));
        } else {
            OUT[(size_t)node * 32 + lane] = v;
        }
    }
}

// ---------------- launch ----------------
extern "C" void kernel_launch(void* const* d_in, const int* in_sizes, int n_in,
                              void* d_out, int out_size) {
    const float* x     = (const float*)d_in[0];
    const void*  edges = d_in[1];
    const float* W1  = (const float*)d_in[3];  const float* b1  = (const float*)d_in[4];
    const float* W2  = (const float*)d_in[5];  const float* b2  = (const float*)d_in[6];
    const float* W3  = (const float*)d_in[7];  const float* b3  = (const float*)d_in[8];
    const float* tW1 = (const float*)d_in[9];  const float* tb1 = (const float*)d_in[10];
    const float* tW2 = (const float*)d_in[11]; const float* tb2 = (const float*)d_in[12];
    const float* tW3 = (const float*)d_in[13]; const float* tb3 = (const float*)d_in[14];
    const float* Wpi = (const float*)d_in[15]; const float* bpi = (const float*)d_in[16];
    const float* Wn  = (const float*)d_in[17]; const float* bn  = (const float*)d_in[18];
    const float* Wp  = (const float*)d_in[19]; const float* bp  = (const float*)d_in[20];
    float* out = (float*)d_out;

    const int TOT = in_sizes[0] / FDIM;
    const int E   = in_sizes[1] / 2;

    float *dinv, *H2raw, *H2;
    int *cnt, *rowp, *curs, *adj;
    bf16 *A1h, *A1l, *H1h, *H1l, *A3h, *A3l, *H3h, *H3l, *C1h, *C1l, *C2h, *C2l;
    bf16 *W1h, *W1l, *W2h, *W2l, *W3h, *W3l, *T1h, *T1l, *T2h, *T2l, *T3h, *T3l;
    cudaGetSymbolAddress((void**)&dinv,  g_dinv);
    cudaGetSymbolAddress((void**)&cnt,   g_cnt);
    cudaGetSymbolAddress((void**)&rowp,  g_rowp);
    cudaGetSymbolAddress((void**)&curs,  g_curs);
    cudaGetSymbolAddress((void**)&adj,   g_adj);
    cudaGetSymbolAddress((void**)&A1h,   g_A1h);  cudaGetSymbolAddress((void**)&A1l, g_A1l);
    cudaGetSymbolAddress((void**)&H1h,   g_H1h);  cudaGetSymbolAddress((void**)&H1l, g_H1l);
    cudaGetSymbolAddress((void**)&A3h,   g_A3h);  cudaGetSymbolAddress((void**)&A3l, g_A3l);
    cudaGetSymbolAddress((void**)&H3h,   g_H3h);  cudaGetSymbolAddress((void**)&H3l, g_H3l);
    cudaGetSymbolAddress((void**)&C1h,   g_C1h);  cudaGetSymbolAddress((void**)&C1l, g_C1l);
    cudaGetSymbolAddress((void**)&C2h,   g_C2h);  cudaGetSymbolAddress((void**)&C2l, g_C2l);
    cudaGetSymbolAddress((void**)&H2raw, g_H2raw);
    cudaGetSymbolAddress((void**)&H2,    g_H2);
    cudaGetSymbolAddress((void**)&W1h, g_W1h); cudaGetSymbolAddress((void**)&W1l, g_W1l);
    cudaGetSymbolAddress((void**)&W2h, g_W2h); cudaGetSymbolAddress((void**)&W2l, g_W2l);
    cudaGetSymbolAddress((void**)&W3h, g_W3h); cudaGetSymbolAddress((void**)&W3l, g_W3l);
    cudaGetSymbolAddress((void**)&T1h, g_T1h); cudaGetSymbolAddress((void**)&T1l, g_T1l);
    cudaGetSymbolAddress((void**)&T2h, g_T2h); cudaGetSymbolAddress((void**)&T2l, g_T2l);
    cudaGetSymbolAddress((void**)&T3h, g_T3h); cudaGetSymbolAddress((void**)&T3l, g_T3l);

    const int gatherBlocks = (TOT * 32) / 256;
    const int grid = TOT / 128;

    // smem sizes (bytes)
    const int SM_G1 = (2 * 128 * 72  + 2 * 128 * 72) * 2;              // 73728
    const int SM_G2 = (2 * 128 * 136 + 2 * 32 * 136) * 2;              // 87040
    const int SM_G3 = (2 * 128 * 40  + 2 * 128 * 40) * 2;              // 40960
    const int SM_C1 = (2 * 130 * 72  + 2 * 128 * 72) * 2;              // 74304
    const int SM_C2 = (2 * 130 * 72  + 2 * 3 * 32 * 72) * 2;           // 65088
    const int SM_C3 = (2 * 130 * 40  + 2 * 3 * 128 * 40) * 2 + 1536;   // 83776

    cudaFuncSetAttribute(mma_layer<64, 128, 1, 64, 1, 1, 1, 0>,  cudaFuncAttributeMaxDynamicSharedMemorySize, SM_G1);
    cudaFuncSetAttribute(mma_layer<128, 32, 1, 128, 0, 0, 0, 0>, cudaFuncAttributeMaxDynamicSharedMemorySize, SM_G2);
    cudaFuncSetAttribute(mma_layer<32, 128, 1, 32, 1, 1, 1, 0>,  cudaFuncAttributeMaxDynamicSharedMemorySize, SM_G3);
    cudaFuncSetAttribute(mma_layer<128, 128, 3, 64, 1, 1, 1, 0>, cudaFuncAttributeMaxDynamicSharedMemorySize, SM_C1);
    cudaFuncSetAttribute(mma_layer<128, 32, 3, 64, 1, 1, 1, 0>,  cudaFuncAttributeMaxDynamicSharedMemorySize, SM_C2);
    cudaFuncSetAttribute(mma_layer<32, 128, 3, 32, 1, 1, 0, 1>,  cudaFuncAttributeMaxDynamicSharedMemorySize, SM_C3);

    // ---- weight planes + CSR build ----
    wplanes_kernel<<<128, 256>>>(W1, W2, W3, tW1, tW2, tW3);
    zero_detect_kernel<<<256, 256>>>(cnt, TOT, (const unsigned int*)edges);
    count_kernel<<<2048, 256>>>(edges, cnt, E);
    scan_kernel<<<1, 1024>>>(cnt, rowp, curs, dinv);
    fill_kernel<<<2048, 256>>>(edges, curs, adj, E);

    // ---- GCN stack ----
    gather_kernel<64, 0, 1><<<gatherBlocks, 256>>>(rowp, adj, dinv, x, nullptr, nullptr, A1h, A1l, TOT);
    mma_layer<64, 128, 1, 64, 1, 1, 1, 0><<<grid, 256, SM_G1>>>(
        A1h, A1l, W1h, W1l, b1, nullptr, H1h, H1l,
        nullptr, nullptr, nullptr, nullptr, nullptr, nullptr, nullptr);
    mma_layer<128, 32, 1, 128, 0, 0, 0, 0><<<grid, 256, SM_G2>>>(
        H1h, H1l, W2h, W2l, nullptr, H2raw, nullptr, nullptr,
        nullptr, nullptr, nullptr, nullptr, nullptr, nullptr, nullptr);
    gather_kernel<32, 1, 0><<<gatherBlocks, 256>>>(rowp, adj, dinv, H2raw, b2, H2, nullptr, nullptr, TOT);
    gather_kernel<32, 0, 1><<<gatherBlocks, 256>>>(rowp, adj, dinv, H2, nullptr, nullptr, A3h, A3l, TOT);
    mma_layer<32, 128, 1, 32, 1, 1, 1, 0><<<grid, 256, SM_G3>>>(
        A3h, A3l, W3h, W3l, b3, nullptr, H3h, H3l,
        nullptr, nullptr, nullptr, nullptr, nullptr, nullptr, nullptr);

    // ---- temporal conv stack (k=3, pad=1); conv3 fuses the 3 heads ----
    mma_layer<128, 128, 3, 64, 1, 1, 1, 0><<<grid, 256, SM_C1>>>(
        H3h, H3l, T1h, T1l, tb1, nullptr, C1h, C1l,
        nullptr, nullptr, nullptr, nullptr, nullptr, nullptr, nullptr);
    mma_layer<128, 32, 3, 64, 1, 1, 1, 0><<<grid, 256, SM_C2>>>(
        C1h, C1l, T2h, T2l, tb2, nullptr, C2h, C2l,
        nullptr, nullptr, nullptr, nullptr, nullptr, nullptr, nullptr);
    mma_layer<32, 128, 3, 32, 1, 1, 0, 1><<<grid, 256, SM_C3>>>(
        C2h, C2l, T3h, T3l, tb3, nullptr, nullptr, nullptr,
        Wpi, Wn, Wp, bpi, bn, bp, out);
}

// round 9
// speedup vs baseline: 3.7310x; 1.8400x over previous
#include <cuda_runtime.h>
#include <cuda_bf16.h>
#include <math.h>
#include <stdint.h>

// ---------------- problem constants ----------------
#define TOTN   131072      // B*N nodes
#define EMAX   1048576
#define FDIM   64
#define HSD    128
#define RSD    32
#define NPG    4096        // nodes per graph (temporal length)
#define SCB    512         // scan blocks
#define SCCH   (TOTN / SCB)   // 256 elems per scan block

typedef __nv_bfloat16 bf16;

// ---------------- device scratch (no cudaMalloc allowed) ----------------
__device__ int   g_is64;
__device__ float g_dinv [TOTN];
__device__ int   g_cnt  [TOTN];
__device__ int   g_rowp [TOTN + 1];
__device__ int   g_curs [TOTN];
__device__ int   g_adj  [EMAX];
__device__ int   g_part [SCB];
// bf16 hi/lo planes for activations
__device__ __align__(16) bf16 g_A1h[TOTN * FDIM], g_A1l[TOTN * FDIM];
__device__ __align__(16) bf16 g_H1h[TOTN * HSD],  g_H1l[TOTN * HSD];
__device__ __align__(16) bf16 g_A3h[TOTN * RSD],  g_A3l[TOTN * RSD];
__device__ __align__(16) bf16 g_H3h[TOTN * HSD],  g_H3l[TOTN * HSD];
__device__ __align__(16) bf16 g_C1h[TOTN * HSD],  g_C1l[TOTN * HSD];
__device__ __align__(16) bf16 g_C2h[TOTN * RSD],  g_C2l[TOTN * RSD];
// fp32 intermediates
__device__ float g_H2raw[TOTN * RSD];
__device__ float g_H2   [TOTN * RSD];
// weight planes (k-major [tap][COUT][CIN])
__device__ __align__(16) bf16 g_W1h[128 * 64],      g_W1l[128 * 64];
__device__ __align__(16) bf16 g_W2h[32 * 128],      g_W2l[32 * 128];
__device__ __align__(16) bf16 g_W3h[128 * 32],      g_W3l[128 * 32];
__device__ __align__(16) bf16 g_T1h[3 * 128 * 128], g_T1l[3 * 128 * 128];
__device__ __align__(16) bf16 g_T2h[3 * 32 * 128],  g_T2l[3 * 32 * 128];
__device__ __align__(16) bf16 g_T3h[3 * 128 * 32],  g_T3l[3 * 128 * 32];

__device__ __forceinline__ uint32_t pack_bf(float a, float b) {
    __nv_bfloat162 t;
    t.x = __float2bfloat16(a);
    t.y = __float2bfloat16(b);
    return *reinterpret_cast<uint32_t*>(&t);
}
__device__ __forceinline__ uint32_t smem_u32(const void* p) {
    uint32_t a;
    asm("{ .reg .u64 t; cvta.to.shared.u64 t, %1; cvt.u32.u64 %0, t; }" : "=r"(a) : "l"(p));
    return a;
}
__device__ __forceinline__ void mma16816(float* d, uint32_t a0, uint32_t a1, uint32_t a2,
                                         uint32_t a3, uint32_t b0, uint32_t b1) {
    asm volatile(
        "mma.sync.aligned.m16n8k16.row.col.f32.bf16.bf16.f32 "
        "{%0,%1,%2,%3}, {%4,%5,%6,%7}, {%8,%9}, {%0,%1,%2,%3};"
        : "+f"(d[0]), "+f"(d[1]), "+f"(d[2]), "+f"(d[3])
        : "r"(a0), "r"(a1), "r"(a2), "r"(a3), "r"(b0), "r"(b1));
}
__device__ __forceinline__ void ldsm4(uint32_t& r0, uint32_t& r1, uint32_t& r2, uint32_t& r3,
                                      uint32_t addr) {
    asm volatile("ldmatrix.sync.aligned.m8n8.x4.shared.b16 {%0,%1,%2,%3}, [%4];"
                 : "=r"(r0), "=r"(r1), "=r"(r2), "=r"(r3) : "r"(addr));
}

// ---------------- weight plane precompute ----------------
__device__ void wlin(const float* W, bf16* WH, bf16* WL, int CIN, int COUT, int tid, int nt) {
    for (int i = tid; i < CIN * COUT; i += nt) {
        int n = i / CIN, k = i % CIN;
        float w = W[(size_t)k * COUT + n];
        bf16 h = __float2bfloat16(w);
        WH[i] = h;
        WL[i] = __float2bfloat16(w - __bfloat162float(h));
    }
}
__device__ void wconv(const float* W, bf16* WH, bf16* WL, int CIN, int COUT, int tid, int nt) {
    for (int i = tid; i < 3 * CIN * COUT; i += nt) {
        int s = i / (CIN * COUT);
        int n = (i / CIN) % COUT;
        int k = i % CIN;
        float w = W[((size_t)n * CIN + k) * 3 + s];
        bf16 h = __float2bfloat16(w);
        WH[i] = h;
        WL[i] = __float2bfloat16(w - __bfloat162float(h));
    }
}
__global__ void wplanes_kernel(const float* W1, const float* W2, const float* W3,
                               const float* T1, const float* T2, const float* T3) {
    int tid = blockIdx.x * blockDim.x + threadIdx.x;
    int nt  = gridDim.x * blockDim.x;
    wlin(W1, g_W1h, g_W1l, 64, 128, tid, nt);
    wlin(W2, g_W2h, g_W2l, 128, 32, tid, nt);
    wlin(W3, g_W3h, g_W3l, 32, 128, tid, nt);
    wconv(T1, g_T1h, g_T1l, 128, 128, tid, nt);
    wconv(T2, g_T2h, g_T2l, 128, 32, tid, nt);
    wconv(T3, g_T3h, g_T3l, 32, 128, tid, nt);
}

// =========== unified dense layer on tensor cores ===========
template <int CIN, int COUT, int TAPS, int KCH, int HASBIAS, int HASRELU, int OUTPLANES, int HEADS>
__global__ void __launch_bounds__(256, 2)
mma_layer(const bf16* __restrict__ XH, const bf16* __restrict__ XL,
          const bf16* __restrict__ WH, const bf16* __restrict__ WL,
          const float* __restrict__ bias,
          float* __restrict__ OUT, bf16* __restrict__ OH, bf16* __restrict__ OL,
          const float* __restrict__ HWpi, const float* __restrict__ HWn,
          const float* __restrict__ HWp, const float* __restrict__ Hbpi,
          const float* __restrict__ Hbn, const float* __restrict__ Hbp,
          float* __restrict__ hout) {
    constexpr int NCHC = CIN / KCH;
    constexpr int P    = KCH + 8;
    constexpr int HALO = (TAPS == 3) ? 1 : 0;
    constexpr int RSTG = 128 + 2 * HALO;
    constexpr bool BIG = (COUT == 128);
    constexpr bool ALLTAPS = (TAPS == 3) && (COUT == 32 || CIN == 32);
    constexpr int BTAPS = ALLTAPS ? 3 : 1;
    constexpr int U4   = KCH / 8;
    constexpr int FD   = BIG ? 2 : 1;
    constexpr int TD   = BIG ? 8 : 4;

    extern __shared__ __align__(16) char smem[];
    bf16* Ah = (bf16*)smem;
    bf16* Al = Ah + RSTG * P;
    bf16* Bh = Al + RSTG * P;
    bf16* Bl = Bh + BTAPS * COUT * P;
    float* hbuf = (float*)(Bl + BTAPS * COUT * P);

    const uint32_t sb  = smem_u32(smem);
    const uint32_t sAh = sb;
    const uint32_t sAl = sAh + RSTG * P * 2;
    const uint32_t sBh = sAl + RSTG * P * 2;
    const uint32_t sBl = sBh + BTAPS * COUT * P * 2;

    int tid  = threadIdx.x;
    int w    = tid >> 5;
    int lane = tid & 31;
    int gid  = lane >> 2;
    int qid  = lane & 3;
    int seg  = lane >> 3;
    int rin  = lane & 7;
    int row0 = blockIdx.x * 128;
    int gb   = (row0 / NPG) * NPG;
    int wm   = BIG ? (w & 3) : w;
    int wn   = BIG ? (w >> 2) : 0;

    float d[FD][TD][4];
    #pragma unroll
    for (int f = 0; f < FD; f++)
        #pragma unroll
        for (int t = 0; t < TD; t++)
            #pragma unroll
            for (int i = 0; i < 4; i++) d[f][t][i] = 0.0f;

    for (int c = 0; c < NCHC; c++) {
        const int c0 = c * KCH;
        for (int idx = tid; idx < RSTG * U4; idx += 256) {
            int r = idx / U4;
            int j = (idx % U4) * 8;
            long src = (long)row0 - HALO + r;
            uint4 vh = make_uint4(0, 0, 0, 0), vl = vh;
            if (!HALO || (src >= gb && src < (long)gb + NPG)) {
                vh = *(const uint4*)&XH[src * CIN + c0 + j];
                vl = *(const uint4*)&XL[src * CIN + c0 + j];
            }
            *(uint4*)&Ah[r * P + j] = vh;
            *(uint4*)&Al[r * P + j] = vl;
        }

        if (ALLTAPS) {
            for (int idx = tid; idx < BTAPS * COUT * U4; idx += 256) {
                int n2 = idx / U4;
                int j  = (idx % U4) * 8;
                *(uint4*)&Bh[n2 * P + j] = *(const uint4*)&WH[(size_t)n2 * CIN + c0 + j];
                *(uint4*)&Bl[n2 * P + j] = *(const uint4*)&WL[(size_t)n2 * CIN + c0 + j];
            }
            __syncthreads();
        }

        #pragma unroll
        for (int s = 0; s < TAPS; s++) {
            if (!ALLTAPS) {
                for (int idx = tid; idx < COUT * U4; idx += 256) {
                    int n = idx / U4;
                    int j = (idx % U4) * 8;
                    *(uint4*)&Bh[n * P + j] = *(const uint4*)&WH[((size_t)s * COUT + n) * CIN + c0 + j];
                    *(uint4*)&Bl[n * P + j] = *(const uint4*)&WL[((size_t)s * COUT + n) * CIN + c0 + j];
                }
                __syncthreads();
            }
            const int bt = ALLTAPS ? s : 0;

            #pragma unroll
            for (int ks = 0; ks < KCH / 16; ks++) {
                int kc = ks * 16;
                if (BIG) {
                    uint32_t ah[FD][4], al[FD][4];
                    #pragma unroll
                    for (int f = 0; f < FD; f++) {
                        uint32_t aoff = (uint32_t)((wm * 32 + f * 16 + rin + ((seg & 1) << 3) + s) * P
                                                   + kc + ((seg >> 1) << 3)) * 2;
                        ldsm4(ah[f][0], ah[f][1], ah[f][2], ah[f][3], sAh + aoff);
                        ldsm4(al[f][0], al[f][1], al[f][2], al[f][3], sAl + aoff);
                    }
                    #pragma unroll
                    for (int g = 0; g < 4; g++) {
                        uint32_t boff = (uint32_t)(((bt * COUT) + wn * 64 + g * 16 + rin + ((seg >> 1) << 3)) * P
                                                   + kc + ((seg & 1) << 3)) * 2;
                        uint32_t bh0, bh1, bh2, bh3, bl0, bl1, bl2, bl3;
                        ldsm4(bh0, bh1, bh2, bh3, sBh + boff);
                        ldsm4(bl0, bl1, bl2, bl3, sBl + boff);
                        #pragma unroll
                        for (int f = 0; f < FD; f++) {
                            mma16816(d[f][2 * g],     ah[f][0], ah[f][1], ah[f][2], ah[f][3], bh0, bh1);
                            mma16816(d[f][2 * g],     ah[f][0], ah[f][1], ah[f][2], ah[f][3], bl0, bl1);
                            mma16816(d[f][2 * g],     al[f][0], al[f][1], al[f][2], al[f][3], bh0, bh1);
                            mma16816(d[f][2 * g + 1], ah[f][0], ah[f][1], ah[f][2], ah[f][3], bh2, bh3);
                            mma16816(d[f][2 * g + 1], ah[f][0], ah[f][1], ah[f][2], ah[f][3], bl2, bl3);
                            mma16816(d[f][2 * g + 1], al[f][0], al[f][1], al[f][2], al[f][3], bh2, bh3);
                        }
                    }
                } else {
                    uint32_t aoff = (uint32_t)((w * 16 + rin + ((seg & 1) << 3) + s) * P
                                               + kc + ((seg >> 1) << 3)) * 2;
                    uint32_t ah0, ah1, ah2, ah3, al0, al1, al2, al3;
                    ldsm4(ah0, ah1, ah2, ah3, sAh + aoff);
                    ldsm4(al0, al1, al2, al3, sAl + aoff);
                    #pragma unroll
                    for (int g = 0; g < 2; g++) {
                        uint32_t boff = (uint32_t)(((bt * COUT) + g * 16 + rin + ((seg >> 1) << 3)) * P
                                                   + kc + ((seg & 1) << 3)) * 2;
                        uint32_t bh0, bh1, bh2, bh3, bl0, bl1, bl2, bl3;
                        ldsm4(bh0, bh1, bh2, bh3, sBh + boff);
                        ldsm4(bl0, bl1, bl2, bl3, sBl + boff);
                        mma16816(d[0][2 * g],     ah0, ah1, ah2, ah3, bh0, bh1);
                        mma16816(d[0][2 * g],     ah0, ah1, ah2, ah3, bl0, bl1);
                        mma16816(d[0][2 * g],     al0, al1, al2, al3, bh0, bh1);
                        mma16816(d[0][2 * g + 1], ah0, ah1, ah2, ah3, bh2, bh3);
                        mma16816(d[0][2 * g + 1], ah0, ah1, ah2, ah3, bl2, bl3);
                        mma16816(d[0][2 * g + 1], al0, al1, al2, al3, bh2, bh3);
                    }
                }
            }
            if (!ALLTAPS) __syncthreads();
        }
        if (ALLTAPS) __syncthreads();
    }

    if (HEADS) {
        float p1[2][2] = {}, p2[2][2] = {}, p3[2][2] = {};
        #pragma unroll
        for (int f = 0; f < FD; f++)
            #pragma unroll
            for (int t = 0; t < TD; t++) {
                int n = wn * 64 + t * 8 + qid * 2;
                float b0 = bias[n], b1 = bias[n + 1];
                float v00 = fmaxf(d[f][t][0] + b0, 0.0f);
                float v01 = fmaxf(d[f][t][1] + b1, 0.0f);
                float v10 = fmaxf(d[f][t][2] + b0, 0.0f);
                float v11 = fmaxf(d[f][t][3] + b1, 0.0f);
                float wa0 = HWpi[n], wa1 = HWpi[n + 1];
                float wb0 = HWn[n],  wb1 = HWn[n + 1];
                float wc0 = HWp[n],  wc1 = HWp[n + 1];
                p1[f][0] += v00 * wa0 + v01 * wa1;  p1[f][1] += v10 * wa0 + v11 * wa1;
                p2[f][0] += v00 * wb0 + v01 * wb1;  p2[f][1] += v10 * wb0 + v11 * wb1;
                p3[f][0] += v00 * wc0 + v01 * wc1;  p3[f][1] += v10 * wc0 + v11 * wc1;
            }
        #pragma unroll
        for (int f = 0; f < 2; f++)
            #pragma unroll
            for (int h = 0; h < 2; h++) {
                p1[f][h] += __shfl_xor_sync(0xffffffffu, p1[f][h], 1);
                p1[f][h] += __shfl_xor_sync(0xffffffffu, p1[f][h], 2);
                p2[f][h] += __shfl_xor_sync(0xffffffffu, p2[f][h], 1);
                p2[f][h] += __shfl_xor_sync(0xffffffffu, p2[f][h], 2);
                p3[f][h] += __shfl_xor_sync(0xffffffffu, p3[f][h], 1);
                p3[f][h] += __shfl_xor_sync(0xffffffffu, p3[f][h], 2);
            }
        if (wn == 0 && qid == 0) {
            #pragma unroll
            for (int f = 0; f < 2; f++) {
                int r = wm * 32 + f * 16 + gid;
                hbuf[r] = p1[f][0];        hbuf[r + 8] = p1[f][1];
                hbuf[128 + r] = p2[f][0];  hbuf[128 + r + 8] = p2[f][1];
                hbuf[256 + r] = p3[f][0];  hbuf[256 + r + 8] = p3[f][1];
            }
        }
        __syncthreads();
        if (wn == 1 && qid == 0) {
            #pragma unroll
            for (int f = 0; f < 2; f++)
                #pragma unroll
                for (int h = 0; h < 2; h++) {
                    int r = wm * 32 + f * 16 + gid + h * 8;
                    int rg = row0 + r;
                    float z1 = hbuf[r] + p1[f][h] + Hbpi[0];
                    float z2 = hbuf[128 + r] + p2[f][h] + Hbn[0];
                    float z3 = hbuf[256 + r] + p3[f][h] + Hbp[0];
                    hout[rg]            = 1.0f / (1.0f + expf(-z1));
                    hout[TOTN + rg]     = (z2 > 0.0f) ? (z2 + log1pf(expf(-z2))) : log1pf(expf(z2));
                    hout[2 * TOTN + rg] = 1.0f / (1.0f + expf(-z3));
                }
        }
    } else {
        #pragma unroll
        for (int f = 0; f < FD; f++) {
            int r0 = row0 + (BIG ? (wm * 32 + f * 16) : (w * 16)) + gid;
            #pragma unroll
            for (int t = 0; t < TD; t++) {
                int n = (BIG ? wn * 64 : 0) + t * 8 + qid * 2;
                float2 v0 = make_float2(d[f][t][0], d[f][t][1]);
                float2 v1 = make_float2(d[f][t][2], d[f][t][3]);
                if (HASBIAS) {
                    float bx = bias[n], by = bias[n + 1];
                    v0.x += bx; v0.y += by;
                    v1.x += bx; v1.y += by;
                }
                if (HASRELU) {
                    v0.x = fmaxf(v0.x, 0.0f); v0.y = fmaxf(v0.y, 0.0f);
                    v1.x = fmaxf(v1.x, 0.0f); v1.y = fmaxf(v1.y, 0.0f);
                }
                if (OUTPLANES) {
                    bf16 h0 = __float2bfloat16(v0.x), h1 = __float2bfloat16(v0.y);
                    bf16 h2 = __float2bfloat16(v1.x), h3 = __float2bfloat16(v1.y);
                    *(uint32_t*)&OH[(size_t)r0 * COUT + n] = pack_bf(v0.x, v0.y);
                    *(uint32_t*)&OL[(size_t)r0 * COUT + n] = pack_bf(v0.x - __bfloat162float(h0),
                                                                     v0.y - __bfloat162float(h1));
                    *(uint32_t*)&OH[(size_t)(r0 + 8) * COUT + n] = pack_bf(v1.x, v1.y);
                    *(uint32_t*)&OL[(size_t)(r0 + 8) * COUT + n] = pack_bf(v1.x - __bfloat162float(h2),
                                                                           v1.y - __bfloat162float(h3));
                } else {
                    *(float2*)&OUT[(size_t)r0 * COUT + n]       = v0;
                    *(float2*)&OUT[(size_t)(r0 + 8) * COUT + n] = v1;
                }
            }
        }
    }
}

// ---------------- CSR build ----------------
__device__ __forceinline__ int edge_at(const void* e, int idx, int is64) {
    if (is64) return (int)((const long long*)e)[idx];
    return ((const int*)e)[idx];
}
__global__ void zero_detect_kernel(int* cnt, int n, const unsigned int* e) {
    int i  = blockIdx.x * blockDim.x + threadIdx.x;
    int st = gridDim.x * blockDim.x;
    for (; i < n; i += st) cnt[i] = 0;
    if (blockIdx.x == 0 && threadIdx.x == 0) {
        int ok = 1;
        #pragma unroll 1
        for (int k = 0; k < 64; k++)
            if (e[2 * k + 1] != 0u) { ok = 0; break; }
        g_is64 = ok;
    }
}
__global__ void count_kernel(const void* edges, int* cnt, int E) {
    int is64 = g_is64;
    int i  = blockIdx.x * blockDim.x + threadIdx.x;
    int st = gridDim.x * blockDim.x;
    for (; i < E; i += st) {
        int d = edge_at(edges, E + i, is64);
        atomicAdd(&cnt[d], 1);
    }
}
// --- phase 1: per-chunk sums ---
__global__ void __launch_bounds__(256)
scan_partial_kernel(const int* __restrict__ cnt, int* part) {
    __shared__ int sh[8];
    int tid = threadIdx.x;
    int v = cnt[blockIdx.x * SCCH + tid];
    #pragma unroll
    for (int o = 16; o > 0; o >>= 1) v += __shfl_xor_sync(0xffffffffu, v, o);
    if ((tid & 31) == 0) sh[tid >> 5] = v;
    __syncthreads();
    if (tid < 8) {
        int s = sh[tid];
        #pragma unroll
        for (int o = 4; o > 0; o >>= 1) s += __shfl_xor_sync(0xffu, s, o, 8);
        if (tid == 0) part[blockIdx.x] = s;
    }
}
// --- phase 2: exclusive scan of 512 partials (1 block) ---
__global__ void __launch_bounds__(SCB)
scan_top_kernel(int* part) {
    __shared__ int sh[SCB];
    int tid = threadIdx.x;
    int v = part[tid];
    sh[tid] = v;
    __syncthreads();
    for (int off = 1; off < SCB; off <<= 1) {
        int u = (tid >= off) ? sh[tid - off] : 0;
        __syncthreads();
        sh[tid] += u;
        __syncthreads();
    }
    part[tid] = sh[tid] - v;   // exclusive
}
// --- phase 3: block-local scan + emit rowp/curs/dinv ---
__global__ void __launch_bounds__(256)
scan_emit_kernel(const int* __restrict__ cnt, const int* __restrict__ part,
                 int* row_ptr, int* cursor, float* dinv) {
    __shared__ int wsum[8];
    int tid  = threadIdx.x;
    int lane = tid & 31;
    int wid  = tid >> 5;
    int i = blockIdx.x * SCCH + tid;
    int c = cnt[i];
    int v = c;
    #pragma unroll
    for (int o = 1; o < 32; o <<= 1) {
        int u = __shfl_up_sync(0xffffffffu, v, o);
        if (lane >= o) v += u;
    }
    if (lane == 31) wsum[wid] = v;
    __syncthreads();
    if (wid == 0 && lane < 8) {
        int s = wsum[lane];
        #pragma unroll
        for (int o = 1; o < 8; o <<= 1) {
            int u = __shfl_up_sync(0xffu, s, o, 8);
            if (lane >= o) s += u;
        }
        wsum[lane] = s;
    }
    __syncthreads();
    int excl = v - c + (wid > 0 ? wsum[wid - 1] : 0);
    int run = part[blockIdx.x] + excl;
    row_ptr[i] = run;
    cursor[i]  = run;
    dinv[i]    = rsqrtf((float)c + 1.0f);
    if (i == TOTN - 1) row_ptr[TOTN] = run + c;
}
__global__ void fill_kernel(const void* edges, int* cursor, int* adj, int E) {
    int is64 = g_is64;
    int i  = blockIdx.x * blockDim.x + threadIdx.x;
    int st = gridDim.x * blockDim.x;
    for (; i < E; i += st) {
        int s = edge_at(edges, i, is64);
        int d = edge_at(edges, E + i, is64);
        int pos = atomicAdd(&cursor[d], 1);
        adj[pos] = s;
    }
}

// ---------------- CSR gather + fused epilogue ----------------
template <int D, int BIASRELU, int OUTPLANES>
__global__ void gather_kernel(const int* __restrict__ row_ptr, const int* __restrict__ adj,
                              const float* __restrict__ dinv, const float* __restrict__ X,
                              const float* __restrict__ bias, float* __restrict__ OUT,
                              bf16* __restrict__ OH, bf16* __restrict__ OL, int n) {
    int lane = threadIdx.x & 31;
    int node = (blockIdx.x * blockDim.x + threadIdx.x) >> 5;
    if (node >= n) return;
    int beg = row_ptr[node];
    int end = row_ptr[node + 1];
    float di = dinv[node];
    float c  = di * di;
    if (D == 64) {
        float ax = 0.0f, ay = 0.0f;
        for (int j = beg; j < end; j++) {
            int s = adj[j];
            float ws = __ldg(&dinv[s]);
            float2 v = ((const float2*)(X + (size_t)s * 64))[lane];
            ax = fmaf(ws, v.x, ax);
            ay = fmaf(ws, v.y, ay);
        }
        float2 xv = ((const float2*)(X + (size_t)node * 64))[lane];
        float2 o;
        o.x = c * (ax + xv.x);
        o.y = c * (ay + xv.y);
        if (BIASRELU) {
            o.x = fmaxf(o.x + bias[2 * lane],     0.0f);
            o.y = fmaxf(o.y + bias[2 * lane + 1], 0.0f);
        }
        if (OUTPLANES) {
            bf16 hx = __float2bfloat16(o.x), hy = __float2bfloat16(o.y);
            *(uint32_t*)&OH[(size_t)node * 64 + 2 * lane] = pack_bf(o.x, o.y);
            *(uint32_t*)&OL[(size_t)node * 64 + 2 * lane] = pack_bf(o.x - __bfloat162float(hx),
                                                                    o.y - __bfloat162float(hy));
        } else {
            ((float2*)(OUT + (size_t)node * 64))[lane] = o;
        }
    } else {
        float acc = 0.0f;
        for (int j = beg; j < end; j++) {
            int s = adj[j];
            float ws = __ldg(&dinv[s]);
            acc = fmaf(ws, X[(size_t)s * 32 + lane], acc);
        }
        float v = c * (acc + X[(size_t)node * 32 + lane]);
        if (BIASRELU) v = fmaxf(v + bias[lane], 0.0f);
        if (OUTPLANES) {
            bf16 h = __float2bfloat16(v);
            OH[(size_t)node * 32 + lane] = h;
            OL[(size_t)node * 32 + lane] = __float2bfloat16(v - __bfloat162float(h));
        } else {
            OUT[(size_t)node * 32 + lane] = v;
        }
    }
}

// ---------------- launch ----------------
extern "C" void kernel_launch(void* const* d_in, const int* in_sizes, int n_in,
                              void* d_out, int out_size) {
    const float* x     = (const float*)d_in[0];
    const void*  edges = d_in[1];
    const float* W1  = (const float*)d_in[3];  const float* b1  = (const float*)d_in[4];
    const float* W2  = (const float*)d_in[5];  const float* b2  = (const float*)d_in[6];
    const float* W3  = (const float*)d_in[7];  const float* b3  = (const float*)d_in[8];
    const float* tW1 = (const float*)d_in[9];  const float* tb1 = (const float*)d_in[10];
    const float* tW2 = (const float*)d_in[11]; const float* tb2 = (const float*)d_in[12];
    const float* tW3 = (const float*)d_in[13]; const float* tb3 = (const float*)d_in[14];
    const float* Wpi = (const float*)d_in[15]; const float* bpi = (const float*)d_in[16];
    const float* Wn  = (const float*)d_in[17]; const float* bn  = (const float*)d_in[18];
    const float* Wp  = (const float*)d_in[19]; const float* bp  = (const float*)d_in[20];
    float* out = (float*)d_out;

    const int TOT = in_sizes[0] / FDIM;
    const int E   = in_sizes[1] / 2;

    float *dinv, *H2raw, *H2;
    int *cnt, *rowp, *curs, *adj, *part;
    bf16 *A1h, *A1l, *H1h, *H1l, *A3h, *A3l, *H3h, *H3l, *C1h, *C1l, *C2h, *C2l;
    bf16 *W1h, *W1l, *W2h, *W2l, *W3h, *W3l, *T1h, *T1l, *T2h, *T2l, *T3h, *T3l;
    cudaGetSymbolAddress((void**)&dinv,  g_dinv);
    cudaGetSymbolAddress((void**)&cnt,   g_cnt);
    cudaGetSymbolAddress((void**)&rowp,  g_rowp);
    cudaGetSymbolAddress((void**)&curs,  g_curs);
    cudaGetSymbolAddress((void**)&adj,   g_adj);
    cudaGetSymbolAddress((void**)&part,  g_part);
    cudaGetSymbolAddress((void**)&A1h,   g_A1h);  cudaGetSymbolAddress((void**)&A1l, g_A1l);
    cudaGetSymbolAddress((void**)&H1h,   g_H1h);  cudaGetSymbolAddress((void**)&H1l, g_H1l);
    cudaGetSymbolAddress((void**)&A3h,   g_A3h);  cudaGetSymbolAddress((void**)&A3l, g_A3l);
    cudaGetSymbolAddress((void**)&H3h,   g_H3h);  cudaGetSymbolAddress((void**)&H3l, g_H3l);
    cudaGetSymbolAddress((void**)&C1h,   g_C1h);  cudaGetSymbolAddress((void**)&C1l, g_C1l);
    cudaGetSymbolAddress((void**)&C2h,   g_C2h);  cudaGetSymbolAddress((void**)&C2l, g_C2l);
    cudaGetSymbolAddress((void**)&H2raw, g_H2raw);
    cudaGetSymbolAddress((void**)&H2,    g_H2);
    cudaGetSymbolAddress((void**)&W1h, g_W1h); cudaGetSymbolAddress((void**)&W1l, g_W1l);
    cudaGetSymbolAddress((void**)&W2h, g_W2h); cudaGetSymbolAddress((void**)&W2l, g_W2l);
    cudaGetSymbolAddress((void**)&W3h, g_W3h); cudaGetSymbolAddress((void**)&W3l, g_W3l);
    cudaGetSymbolAddress((void**)&T1h, g_T1h); cudaGetSymbolAddress((void**)&T1l, g_T1l);
    cudaGetSymbolAddress((void**)&T2h, g_T2h); cudaGetSymbolAddress((void**)&T2l, g_T2l);
    cudaGetSymbolAddress((void**)&T3h, g_T3h); cudaGetSymbolAddress((void**)&T3l, g_T3l);

    const int gatherBlocks = (TOT * 32) / 256;
    const int grid = TOT / 128;

    const int SM_G1 = (2 * 128 * 72  + 2 * 128 * 72) * 2;
    const int SM_G2 = (2 * 128 * 136 + 2 * 32 * 136) * 2;
    const int SM_G3 = (2 * 128 * 40  + 2 * 128 * 40) * 2;
    const int SM_C1 = (2 * 130 * 72  + 2 * 128 * 72) * 2;
    const int SM_C2 = (2 * 130 * 72  + 2 * 3 * 32 * 72) * 2;
    const int SM_C3 = (2 * 130 * 40  + 2 * 3 * 128 * 40) * 2 + 1536;

    cudaFuncSetAttribute(mma_layer<64, 128, 1, 64, 1, 1, 1, 0>,  cudaFuncAttributeMaxDynamicSharedMemorySize, SM_G1);
    cudaFuncSetAttribute(mma_layer<128, 32, 1, 128, 0, 0, 0, 0>, cudaFuncAttributeMaxDynamicSharedMemorySize, SM_G2);
    cudaFuncSetAttribute(mma_layer<32, 128, 1, 32, 1, 1, 1, 0>,  cudaFuncAttributeMaxDynamicSharedMemorySize, SM_G3);
    cudaFuncSetAttribute(mma_layer<128, 128, 3, 64, 1, 1, 1, 0>, cudaFuncAttributeMaxDynamicSharedMemorySize, SM_C1);
    cudaFuncSetAttribute(mma_layer<128, 32, 3, 64, 1, 1, 1, 0>,  cudaFuncAttributeMaxDynamicSharedMemorySize, SM_C2);
    cudaFuncSetAttribute(mma_layer<32, 128, 3, 32, 1, 1, 0, 1>,  cudaFuncAttributeMaxDynamicSharedMemorySize, SM_C3);

    // ---- weight planes + CSR build ----
    wplanes_kernel<<<128, 256>>>(W1, W2, W3, tW1, tW2, tW3);
    zero_detect_kernel<<<256, 256>>>(cnt, TOT, (const unsigned int*)edges);
    count_kernel<<<2048, 256>>>(edges, cnt, E);
    scan_partial_kernel<<<SCB, 256>>>(cnt, part);
    scan_top_kernel<<<1, SCB>>>(part);
    scan_emit_kernel<<<SCB, 256>>>(cnt, part, rowp, curs, dinv);
    fill_kernel<<<2048, 256>>>(edges, curs, adj, E);

    // ---- GCN stack ----
    gather_kernel<64, 0, 1><<<gatherBlocks, 256>>>(rowp, adj, dinv, x, nullptr, nullptr, A1h, A1l, TOT);
    mma_layer<64, 128, 1, 64, 1, 1, 1, 0><<<grid, 256, SM_G1>>>(
        A1h, A1l, W1h, W1l, b1, nullptr, H1h, H1l,
        nullptr, nullptr, nullptr, nullptr, nullptr, nullptr, nullptr);
    mma_layer<128, 32, 1, 128, 0, 0, 0, 0><<<grid, 256, SM_G2>>>(
        H1h, H1l, W2h, W2l, nullptr, H2raw, nullptr, nullptr,
        nullptr, nullptr, nullptr, nullptr, nullptr, nullptr, nullptr);
    gather_kernel<32, 1, 0><<<gatherBlocks, 256>>>(rowp, adj, dinv, H2raw, b2, H2, nullptr, nullptr, TOT);
    gather_kernel<32, 0, 1><<<gatherBlocks, 256>>>(rowp, adj, dinv, H2, nullptr, nullptr, A3h, A3l, TOT);
    mma_layer<32, 128, 1, 32, 1, 1, 1, 0><<<grid, 256, SM_G3>>>(
        A3h, A3l, W3h, W3l, b3, nullptr, H3h, H3l,
        nullptr, nullptr, nullptr, nullptr, nullptr, nullptr, nullptr);

    // ---- temporal conv stack (k=3, pad=1); conv3 fuses the 3 heads ----
    mma_layer<128, 128, 3, 64, 1, 1, 1, 0><<<grid, 256, SM_C1>>>(
        H3h, H3l, T1h, T1l, tb1, nullptr, C1h, C1l,
        nullptr, nullptr, nullptr, nullptr, nullptr, nullptr, nullptr);
    mma_layer<128, 32, 3, 64, 1, 1, 1, 0><<<grid, 256, SM_C2>>>(
        C1h, C1l, T2h, T2l, tb2, nullptr, C2h, C2l,
        nullptr, nullptr, nullptr, nullptr, nullptr, nullptr, nullptr);
    mma_layer<32, 128, 3, 32, 1, 1, 0, 1><<<grid, 256, SM_C3>>>(
        C2h, C2l, T3h, T3l, tb3, nullptr, nullptr, nullptr,
        Wpi, Wn, Wp, bpi, bn, bp, out);
}

// round 10
// speedup vs baseline: 4.1020x; 1.0994x over previous
#include <cuda_runtime.h>
#include <cuda_bf16.h>
#include <math.h>
#include <stdint.h>

// ---------------- problem constants ----------------
#define TOTN   131072      // B*N nodes
#define EMAX   1048576
#define FDIM   64
#define HSD    128
#define RSD    32
#define NPG    4096        // nodes per graph (temporal length)
#define SCB    512         // scan blocks
#define SCCH   (TOTN / SCB)

typedef __nv_bfloat16 bf16;

// ---------------- device scratch (no cudaMalloc allowed) ----------------
__device__ int   g_is64;
__device__ float g_dinv [TOTN];
__device__ int   g_cnt  [TOTN];
__device__ int   g_rowp [TOTN + 1];
__device__ int   g_curs [TOTN];
__device__ int   g_adj  [EMAX];
__device__ int   g_part [SCB];
// bf16 hi/lo planes for activations
__device__ __align__(16) bf16 g_A1h[TOTN * FDIM], g_A1l[TOTN * FDIM];
__device__ __align__(16) bf16 g_H1h[TOTN * HSD],  g_H1l[TOTN * HSD];
__device__ __align__(16) bf16 g_A3h[TOTN * RSD],  g_A3l[TOTN * RSD];
__device__ __align__(16) bf16 g_H3h[TOTN * HSD],  g_H3l[TOTN * HSD];
__device__ __align__(16) bf16 g_C1h[TOTN * HSD],  g_C1l[TOTN * HSD];
__device__ __align__(16) bf16 g_C2h[TOTN * RSD],  g_C2l[TOTN * RSD];
// fp32 intermediates
__device__ float g_H2raw[TOTN * RSD];
__device__ float g_H2   [TOTN * RSD];
// weight planes (k-major [tap][COUT][CIN])
__device__ __align__(16) bf16 g_W1h[128 * 64],      g_W1l[128 * 64];
__device__ __align__(16) bf16 g_W2h[32 * 128],      g_W2l[32 * 128];
__device__ __align__(16) bf16 g_W3h[128 * 32],      g_W3l[128 * 32];
__device__ __align__(16) bf16 g_T1h[3 * 128 * 128], g_T1l[3 * 128 * 128];
__device__ __align__(16) bf16 g_T2h[3 * 32 * 128],  g_T2l[3 * 32 * 128];
__device__ __align__(16) bf16 g_T3h[3 * 128 * 32],  g_T3l[3 * 128 * 32];

__device__ __forceinline__ uint32_t pack_bf(float a, float b) {
    __nv_bfloat162 t;
    t.x = __float2bfloat16(a);
    t.y = __float2bfloat16(b);
    return *reinterpret_cast<uint32_t*>(&t);
}
__device__ __forceinline__ uint32_t smem_u32(const void* p) {
    uint32_t a;
    asm("{ .reg .u64 t; cvta.to.shared.u64 t, %1; cvt.u32.u64 %0, t; }" : "=r"(a) : "l"(p));
    return a;
}
__device__ __forceinline__ void mma16816(float* d, uint32_t a0, uint32_t a1, uint32_t a2,
                                         uint32_t a3, uint32_t b0, uint32_t b1) {
    asm volatile(
        "mma.sync.aligned.m16n8k16.row.col.f32.bf16.bf16.f32 "
        "{%0,%1,%2,%3}, {%4,%5,%6,%7}, {%8,%9}, {%0,%1,%2,%3};"
        : "+f"(d[0]), "+f"(d[1]), "+f"(d[2]), "+f"(d[3])
        : "r"(a0), "r"(a1), "r"(a2), "r"(a3), "r"(b0), "r"(b1));
}
__device__ __forceinline__ void ldsm4(uint32_t& r0, uint32_t& r1, uint32_t& r2, uint32_t& r3,
                                      uint32_t addr) {
    asm volatile("ldmatrix.sync.aligned.m8n8.x4.shared.b16 {%0,%1,%2,%3}, [%4];"
                 : "=r"(r0), "=r"(r1), "=r"(r2), "=r"(r3) : "r"(addr));
}
__device__ __forceinline__ void cp16(uint32_t s, const void* g, bool p) {
    asm volatile("cp.async.cg.shared.global [%0], [%1], 16, %2;"
                 :: "r"(s), "l"(g), "r"(p ? 16 : 0));
}
#define CP_COMMIT() asm volatile("cp.async.commit_group;" ::: "memory")
#define CP_WAIT0()  asm volatile("cp.async.wait_group 0;" ::: "memory")

// ---------------- weight plane precompute ----------------
__device__ void wlin(const float* W, bf16* WH, bf16* WL, int CIN, int COUT, int tid, int nt) {
    for (int i = tid; i < CIN * COUT; i += nt) {
        int n = i / CIN, k = i % CIN;
        float w = W[(size_t)k * COUT + n];
        bf16 h = __float2bfloat16(w);
        WH[i] = h;
        WL[i] = __float2bfloat16(w - __bfloat162float(h));
    }
}
__device__ void wconv(const float* W, bf16* WH, bf16* WL, int CIN, int COUT, int tid, int nt) {
    for (int i = tid; i < 3 * CIN * COUT; i += nt) {
        int s = i / (CIN * COUT);
        int n = (i / CIN) % COUT;
        int k = i % CIN;
        float w = W[((size_t)n * CIN + k) * 3 + s];
        bf16 h = __float2bfloat16(w);
        WH[i] = h;
        WL[i] = __float2bfloat16(w - __bfloat162float(h));
    }
}
__global__ void wplanes_kernel(const float* W1, const float* W2, const float* W3,
                               const float* T1, const float* T2, const float* T3) {
    int tid = blockIdx.x * blockDim.x + threadIdx.x;
    int nt  = gridDim.x * blockDim.x;
    wlin(W1, g_W1h, g_W1l, 64, 128, tid, nt);
    wlin(W2, g_W2h, g_W2l, 128, 32, tid, nt);
    wlin(W3, g_W3h, g_W3l, 32, 128, tid, nt);
    wconv(T1, g_T1h, g_T1l, 128, 128, tid, nt);
    wconv(T2, g_T2h, g_T2l, 128, 32, tid, nt);
    wconv(T3, g_T3h, g_T3l, 32, 128, tid, nt);
}

// =========== unified dense layer on tensor cores ===========
// PIPE=1 (requires single K chunk, B static): double-buffered A via cp.async,
// B staged once per CTA, TILES row-tiles per CTA.
template <int CIN, int COUT, int TAPS, int KCH, int HASBIAS, int HASRELU,
          int OUTPLANES, int HEADS, int TILES, int PIPE>
__global__ void __launch_bounds__(256, 2)
mma_layer(const bf16* __restrict__ XH, const bf16* __restrict__ XL,
          const bf16* __restrict__ WH, const bf16* __restrict__ WL,
          const float* __restrict__ bias,
          float* __restrict__ OUT, bf16* __restrict__ OH, bf16* __restrict__ OL,
          const float* __restrict__ HWpi, const float* __restrict__ HWn,
          const float* __restrict__ HWp, const float* __restrict__ Hbpi,
          const float* __restrict__ Hbn, const float* __restrict__ Hbp,
          float* __restrict__ hout) {
    constexpr int NCHC = CIN / KCH;
    constexpr int P    = KCH + 8;
    constexpr int HALO = (TAPS == 3) ? 1 : 0;
    constexpr int RSTG = 128 + 2 * HALO;
    constexpr bool BIG = (COUT == 128);
    constexpr bool ALLTAPS = (TAPS == 3) && (COUT == 32 || CIN == 32);
    constexpr int BTAPS = ALLTAPS ? 3 : 1;
    constexpr int U4   = KCH / 8;
    constexpr int FD   = BIG ? 2 : 1;
    constexpr int TD   = BIG ? 8 : 4;
    constexpr int NBUF = PIPE ? 2 : 1;
    constexpr int ABUFB  = RSTG * P * 2;           // bytes per A plane
    constexpr int OFF_B  = NBUF * 2 * ABUFB;
    constexpr int BPL    = BTAPS * COUT * P * 2;   // bytes per B plane
    constexpr int OFF_BL = OFF_B + BPL;
    constexpr int OFF_HB = OFF_BL + BPL;

    extern __shared__ __align__(16) char smem[];
    const uint32_t sb = smem_u32(smem);
    float* hbuf = (float*)(smem + OFF_HB);

    int tid  = threadIdx.x;
    int w    = tid >> 5;
    int lane = tid & 31;
    int gid  = lane >> 2;
    int qid  = lane & 3;
    int seg  = lane >> 3;
    int rin  = lane & 7;
    int wm   = BIG ? (w & 3) : w;
    int wn   = BIG ? (w >> 2) : 0;

    float d[FD][TD][4];

    auto reset_acc = [&]() {
        #pragma unroll
        for (int f = 0; f < FD; f++)
            #pragma unroll
            for (int t = 0; t < TD; t++)
                #pragma unroll
                for (int i = 0; i < 4; i++) d[f][t][i] = 0.0f;
    };

    auto stage_A = [&](int trow0, int c0, int b) {
        int gbl = (trow0 / NPG) * NPG;
        uint32_t dh = sb + (uint32_t)(b * 2) * ABUFB;
        uint32_t dl = dh + ABUFB;
        for (int idx = tid; idx < RSTG * U4; idx += 256) {
            int r = idx / U4, j = (idx % U4) * 8;
            long src = (long)trow0 - HALO + r;
            bool ok = (!HALO) || (src >= gbl && src < (long)gbl + NPG);
            long sc = ok ? src : (long)trow0;
            cp16(dh + (uint32_t)(r * P + j) * 2, XH + sc * CIN + c0 + j, ok);
            cp16(dl + (uint32_t)(r * P + j) * 2, XL + sc * CIN + c0 + j, ok);
        }
    };
    auto stage_B_all = [&](int c0) {   // BTAPS*COUT rows (tap-major weight layout)
        for (int idx = tid; idx < BTAPS * COUT * U4; idx += 256) {
            int n2 = idx / U4, j = (idx % U4) * 8;
            cp16(sb + OFF_B  + (uint32_t)(n2 * P + j) * 2, WH + (size_t)n2 * CIN + c0 + j, true);
            cp16(sb + OFF_BL + (uint32_t)(n2 * P + j) * 2, WL + (size_t)n2 * CIN + c0 + j, true);
        }
    };
    auto stage_B_tap = [&](int s, int c0) {
        for (int idx = tid; idx < COUT * U4; idx += 256) {
            int n = idx / U4, j = (idx % U4) * 8;
            cp16(sb + OFF_B  + (uint32_t)(n * P + j) * 2,
                 WH + ((size_t)s * COUT + n) * CIN + c0 + j, true);
            cp16(sb + OFF_BL + (uint32_t)(n * P + j) * 2,
                 WL + ((size_t)s * COUT + n) * CIN + c0 + j, true);
        }
    };

    auto mma_chunk = [&](uint32_t aH, uint32_t aL, int s, int bt) {
        #pragma unroll
        for (int ks = 0; ks < KCH / 16; ks++) {
            int kc = ks * 16;
            if (BIG) {
                uint32_t ah[FD][4], al[FD][4];
                #pragma unroll
                for (int f = 0; f < FD; f++) {
                    uint32_t aoff = (uint32_t)((wm * 32 + f * 16 + rin + ((seg & 1) << 3) + s) * P
                                               + kc + ((seg >> 1) << 3)) * 2;
                    ldsm4(ah[f][0], ah[f][1], ah[f][2], ah[f][3], aH + aoff);
                    ldsm4(al[f][0], al[f][1], al[f][2], al[f][3], aL + aoff);
                }
                #pragma unroll
                for (int g = 0; g < 4; g++) {
                    uint32_t boff = (uint32_t)(((bt * COUT) + wn * 64 + g * 16 + rin + ((seg >> 1) << 3)) * P
                                               + kc + ((seg & 1) << 3)) * 2;
                    uint32_t bh0, bh1, bh2, bh3, bl0, bl1, bl2, bl3;
                    ldsm4(bh0, bh1, bh2, bh3, sb + OFF_B + boff);
                    ldsm4(bl0, bl1, bl2, bl3, sb + OFF_BL + boff);
                    #pragma unroll
                    for (int f = 0; f < FD; f++) {
                        mma16816(d[f][2 * g],     ah[f][0], ah[f][1], ah[f][2], ah[f][3], bh0, bh1);
                        mma16816(d[f][2 * g],     ah[f][0], ah[f][1], ah[f][2], ah[f][3], bl0, bl1);
                        mma16816(d[f][2 * g],     al[f][0], al[f][1], al[f][2], al[f][3], bh0, bh1);
                        mma16816(d[f][2 * g + 1], ah[f][0], ah[f][1], ah[f][2], ah[f][3], bh2, bh3);
                        mma16816(d[f][2 * g + 1], ah[f][0], ah[f][1], ah[f][2], ah[f][3], bl2, bl3);
                        mma16816(d[f][2 * g + 1], al[f][0], al[f][1], al[f][2], al[f][3], bh2, bh3);
                    }
                }
            } else {
                uint32_t aoff = (uint32_t)((w * 16 + rin + ((seg & 1) << 3) + s) * P
                                           + kc + ((seg >> 1) << 3)) * 2;
                uint32_t ah0, ah1, ah2, ah3, al0, al1, al2, al3;
                ldsm4(ah0, ah1, ah2, ah3, aH + aoff);
                ldsm4(al0, al1, al2, al3, aL + aoff);
                #pragma unroll
                for (int g = 0; g < 2; g++) {
                    uint32_t boff = (uint32_t)(((bt * COUT) + g * 16 + rin + ((seg >> 1) << 3)) * P
                                               + kc + ((seg & 1) << 3)) * 2;
                    uint32_t bh0, bh1, bh2, bh3, bl0, bl1, bl2, bl3;
                    ldsm4(bh0, bh1, bh2, bh3, sb + OFF_B + boff);
                    ldsm4(bl0, bl1, bl2, bl3, sb + OFF_BL + boff);
                    mma16816(d[0][2 * g],     ah0, ah1, ah2, ah3, bh0, bh1);
                    mma16816(d[0][2 * g],     ah0, ah1, ah2, ah3, bl0, bl1);
                    mma16816(d[0][2 * g],     al0, al1, al2, al3, bh0, bh1);
                    mma16816(d[0][2 * g + 1], ah0, ah1, ah2, ah3, bh2, bh3);
                    mma16816(d[0][2 * g + 1], ah0, ah1, ah2, ah3, bl2, bl3);
                    mma16816(d[0][2 * g + 1], al0, al1, al2, al3, bh2, bh3);
                }
            }
        }
    };

    auto epilogue = [&](int row0t) {
        if (HEADS) {
            float p1[2][2] = {}, p2[2][2] = {}, p3[2][2] = {};
            #pragma unroll
            for (int f = 0; f < FD; f++)
                #pragma unroll
                for (int t = 0; t < TD; t++) {
                    int n = wn * 64 + t * 8 + qid * 2;
                    float b0 = bias[n], b1 = bias[n + 1];
                    float v00 = fmaxf(d[f][t][0] + b0, 0.0f);
                    float v01 = fmaxf(d[f][t][1] + b1, 0.0f);
                    float v10 = fmaxf(d[f][t][2] + b0, 0.0f);
                    float v11 = fmaxf(d[f][t][3] + b1, 0.0f);
                    float wa0 = HWpi[n], wa1 = HWpi[n + 1];
                    float wb0 = HWn[n],  wb1 = HWn[n + 1];
                    float wc0 = HWp[n],  wc1 = HWp[n + 1];
                    p1[f][0] += v00 * wa0 + v01 * wa1;  p1[f][1] += v10 * wa0 + v11 * wa1;
                    p2[f][0] += v00 * wb0 + v01 * wb1;  p2[f][1] += v10 * wb0 + v11 * wb1;
                    p3[f][0] += v00 * wc0 + v01 * wc1;  p3[f][1] += v10 * wc0 + v11 * wc1;
                }
            #pragma unroll
            for (int f = 0; f < 2; f++)
                #pragma unroll
                for (int h = 0; h < 2; h++) {
                    p1[f][h] += __shfl_xor_sync(0xffffffffu, p1[f][h], 1);
                    p1[f][h] += __shfl_xor_sync(0xffffffffu, p1[f][h], 2);
                    p2[f][h] += __shfl_xor_sync(0xffffffffu, p2[f][h], 1);
                    p2[f][h] += __shfl_xor_sync(0xffffffffu, p2[f][h], 2);
                    p3[f][h] += __shfl_xor_sync(0xffffffffu, p3[f][h], 1);
                    p3[f][h] += __shfl_xor_sync(0xffffffffu, p3[f][h], 2);
                }
            if (wn == 0 && qid == 0) {
                #pragma unroll
                for (int f = 0; f < 2; f++) {
                    int r = wm * 32 + f * 16 + gid;
                    hbuf[r] = p1[f][0];        hbuf[r + 8] = p1[f][1];
                    hbuf[128 + r] = p2[f][0];  hbuf[128 + r + 8] = p2[f][1];
                    hbuf[256 + r] = p3[f][0];  hbuf[256 + r + 8] = p3[f][1];
                }
            }
            __syncthreads();
            if (wn == 1 && qid == 0) {
                #pragma unroll
                for (int f = 0; f < 2; f++)
                    #pragma unroll
                    for (int h = 0; h < 2; h++) {
                        int r = wm * 32 + f * 16 + gid + h * 8;
                        int rg = row0t + r;
                        float z1 = hbuf[r] + p1[f][h] + Hbpi[0];
                        float z2 = hbuf[128 + r] + p2[f][h] + Hbn[0];
                        float z3 = hbuf[256 + r] + p3[f][h] + Hbp[0];
                        hout[rg]            = 1.0f / (1.0f + expf(-z1));
                        hout[TOTN + rg]     = (z2 > 0.0f) ? (z2 + log1pf(expf(-z2))) : log1pf(expf(z2));
                        hout[2 * TOTN + rg] = 1.0f / (1.0f + expf(-z3));
                    }
            }
            __syncthreads();
        } else {
            #pragma unroll
            for (int f = 0; f < FD; f++) {
                int r0 = row0t + (BIG ? (wm * 32 + f * 16) : (w * 16)) + gid;
                #pragma unroll
                for (int t = 0; t < TD; t++) {
                    int n = (BIG ? wn * 64 : 0) + t * 8 + qid * 2;
                    float2 v0 = make_float2(d[f][t][0], d[f][t][1]);
                    float2 v1 = make_float2(d[f][t][2], d[f][t][3]);
                    if (HASBIAS) {
                        float bx = bias[n], by = bias[n + 1];
                        v0.x += bx; v0.y += by;
                        v1.x += bx; v1.y += by;
                    }
                    if (HASRELU) {
                        v0.x = fmaxf(v0.x, 0.0f); v0.y = fmaxf(v0.y, 0.0f);
                        v1.x = fmaxf(v1.x, 0.0f); v1.y = fmaxf(v1.y, 0.0f);
                    }
                    if (OUTPLANES) {
                        bf16 h0 = __float2bfloat16(v0.x), h1 = __float2bfloat16(v0.y);
                        bf16 h2 = __float2bfloat16(v1.x), h3 = __float2bfloat16(v1.y);
                        *(uint32_t*)&OH[(size_t)r0 * COUT + n] = pack_bf(v0.x, v0.y);
                        *(uint32_t*)&OL[(size_t)r0 * COUT + n] = pack_bf(v0.x - __bfloat162float(h0),
                                                                         v0.y - __bfloat162float(h1));
                        *(uint32_t*)&OH[(size_t)(r0 + 8) * COUT + n] = pack_bf(v1.x, v1.y);
                        *(uint32_t*)&OL[(size_t)(r0 + 8) * COUT + n] = pack_bf(v1.x - __bfloat162float(h2),
                                                                               v1.y - __bfloat162float(h3));
                    } else {
                        *(float2*)&OUT[(size_t)r0 * COUT + n]       = v0;
                        *(float2*)&OUT[(size_t)(r0 + 8) * COUT + n] = v1;
                    }
                }
            }
        }
    };

    if (PIPE) {
        // single K chunk, static B; double-buffered A prefetch across row tiles
        stage_A(blockIdx.x * TILES * 128, 0, 0);
        stage_B_all(0);
        CP_COMMIT();
        for (int t = 0; t < TILES; t++) {
            int row0t = (blockIdx.x * TILES + t) * 128;
            CP_WAIT0();
            __syncthreads();
            if (t + 1 < TILES) {
                stage_A(row0t + 128, 0, (t + 1) & 1);
                CP_COMMIT();
            }
            reset_acc();
            uint32_t aH = sb + (uint32_t)((t & 1) * 2) * ABUFB;
            uint32_t aL = aH + ABUFB;
            #pragma unroll
            for (int s = 0; s < TAPS; s++) mma_chunk(aH, aL, s, ALLTAPS ? s : 0);
            epilogue(row0t);
            __syncthreads();
        }
    } else {
        for (int t = 0; t < TILES; t++) {
            int row0t = (blockIdx.x * TILES + t) * 128;
            reset_acc();
            for (int c = 0; c < NCHC; c++) {
                int c0 = c * KCH;
                __syncthreads();
                stage_A(row0t, c0, 0);
                if (ALLTAPS) stage_B_all(c0);
                else if (TAPS == 1) { if (t == 0) stage_B_all(c0); }
                else stage_B_tap(0, c0);
                CP_COMMIT(); CP_WAIT0();
                __syncthreads();
                #pragma unroll
                for (int s = 0; s < TAPS; s++) {
                    mma_chunk(sb, sb + ABUFB, s, ALLTAPS ? s : 0);
                    if (TAPS == 3 && !ALLTAPS && s + 1 < TAPS) {
                        __syncthreads();
                        stage_B_tap(s + 1, c0);
                        CP_COMMIT(); CP_WAIT0();
                        __syncthreads();
                    }
                }
            }
            __syncthreads();
            epilogue(row0t);
        }
    }
}

// ---------------- CSR build ----------------
__device__ __forceinline__ int edge_at(const void* e, int idx, int is64) {
    if (is64) return (int)((const long long*)e)[idx];
    return ((const int*)e)[idx];
}
__global__ void zero_detect_kernel(int* cnt, int n, const unsigned int* e) {
    int i  = blockIdx.x * blockDim.x + threadIdx.x;
    int st = gridDim.x * blockDim.x;
    for (; i < n; i += st) cnt[i] = 0;
    if (blockIdx.x == 0 && threadIdx.x == 0) {
        int ok = 1;
        #pragma unroll 1
        for (int k = 0; k < 64; k++)
            if (e[2 * k + 1] != 0u) { ok = 0; break; }
        g_is64 = ok;
    }
}
__global__ void count_kernel(const void* edges, int* cnt, int E) {
    int is64 = g_is64;
    int i  = blockIdx.x * blockDim.x + threadIdx.x;
    int st = gridDim.x * blockDim.x;
    for (; i < E; i += st) {
        int d = edge_at(edges, E + i, is64);
        atomicAdd(&cnt[d], 1);
    }
}
__global__ void __launch_bounds__(256)
scan_partial_kernel(const int* __restrict__ cnt, int* part) {
    __shared__ int sh[8];
    int tid = threadIdx.x;
    int v = cnt[blockIdx.x * SCCH + tid];
    #pragma unroll
    for (int o = 16; o > 0; o >>= 1) v += __shfl_xor_sync(0xffffffffu, v, o);
    if ((tid & 31) == 0) sh[tid >> 5] = v;
    __syncthreads();
    if (tid < 8) {
        int s = sh[tid];
        #pragma unroll
        for (int o = 4; o > 0; o >>= 1) s += __shfl_xor_sync(0xffu, s, o, 8);
        if (tid == 0) part[blockIdx.x] = s;
    }
}
__global__ void __launch_bounds__(SCB)
scan_top_kernel(int* part) {
    __shared__ int sh[SCB];
    int tid = threadIdx.x;
    int v = part[tid];
    sh[tid] = v;
    __syncthreads();
    for (int off = 1; off < SCB; off <<= 1) {
        int u = (tid >= off) ? sh[tid - off] : 0;
        __syncthreads();
        sh[tid] += u;
        __syncthreads();
    }
    part[tid] = sh[tid] - v;
}
__global__ void __launch_bounds__(256)
scan_emit_kernel(const int* __restrict__ cnt, const int* __restrict__ part,
                 int* row_ptr, int* cursor, float* dinv) {
    __shared__ int wsum[8];
    int tid  = threadIdx.x;
    int lane = tid & 31;
    int wid  = tid >> 5;
    int i = blockIdx.x * SCCH + tid;
    int c = cnt[i];
    int v = c;
    #pragma unroll
    for (int o = 1; o < 32; o <<= 1) {
        int u = __shfl_up_sync(0xffffffffu, v, o);
        if (lane >= o) v += u;
    }
    if (lane == 31) wsum[wid] = v;
    __syncthreads();
    if (wid == 0 && lane < 8) {
        int s = wsum[lane];
        #pragma unroll
        for (int o = 1; o < 8; o <<= 1) {
            int u = __shfl_up_sync(0xffu, s, o, 8);
            if (lane >= o) s += u;
        }
        wsum[lane] = s;
    }
    __syncthreads();
    int excl = v - c + (wid > 0 ? wsum[wid - 1] : 0);
    int run = part[blockIdx.x] + excl;
    row_ptr[i] = run;
    cursor[i]  = run;
    dinv[i]    = rsqrtf((float)c + 1.0f);
    if (i == TOTN - 1) row_ptr[TOTN] = run + c;
}
__global__ void fill_kernel(const void* edges, int* cursor, int* adj, int E) {
    int is64 = g_is64;
    int i  = blockIdx.x * blockDim.x + threadIdx.x;
    int st = gridDim.x * blockDim.x;
    for (; i < E; i += st) {
        int s = edge_at(edges, i, is64);
        int d = edge_at(edges, E + i, is64);
        int pos = atomicAdd(&cursor[d], 1);
        adj[pos] = s;
    }
}

// ---------------- CSR gather + fused epilogue ----------------
template <int D, int BIASRELU, int OUTPLANES>
__global__ void gather_kernel(const int* __restrict__ row_ptr, const int* __restrict__ adj,
                              const float* __restrict__ dinv, const float* __restrict__ X,
                              const float* __restrict__ bias, float* __restrict__ OUT,
                              bf16* __restrict__ OH, bf16* __restrict__ OL, int n) {
    int lane = threadIdx.x & 31;
    int node = (blockIdx.x * blockDim.x + threadIdx.x) >> 5;
    if (node >= n) return;
    int beg = row_ptr[node];
    int end = row_ptr[node + 1];
    float di = dinv[node];
    float c  = di * di;
    if (D == 64) {
        float ax = 0.0f, ay = 0.0f;
        for (int j = beg; j < end; j++) {
            int s = adj[j];
            float ws = __ldg(&dinv[s]);
            float2 v = ((const float2*)(X + (size_t)s * 64))[lane];
            ax = fmaf(ws, v.x, ax);
            ay = fmaf(ws, v.y, ay);
        }
        float2 xv = ((const float2*)(X + (size_t)node * 64))[lane];
        float2 o;
        o.x = c * (ax + xv.x);
        o.y = c * (ay + xv.y);
        if (BIASRELU) {
            o.x = fmaxf(o.x + bias[2 * lane],     0.0f);
            o.y = fmaxf(o.y + bias[2 * lane + 1], 0.0f);
        }
        if (OUTPLANES) {
            bf16 hx = __float2bfloat16(o.x), hy = __float2bfloat16(o.y);
            *(uint32_t*)&OH[(size_t)node * 64 + 2 * lane] = pack_bf(o.x, o.y);
            *(uint32_t*)&OL[(size_t)node * 64 + 2 * lane] = pack_bf(o.x - __bfloat162float(hx),
                                                                    o.y - __bfloat162float(hy));
        } else {
            ((float2*)(OUT + (size_t)node * 64))[lane] = o;
        }
    } else {
        float acc = 0.0f;
        for (int j = beg; j < end; j++) {
            int s = adj[j];
            float ws = __ldg(&dinv[s]);
            acc = fmaf(ws, X[(size_t)s * 32 + lane], acc);
        }
        float v = c * (acc + X[(size_t)node * 32 + lane]);
        if (BIASRELU) v = fmaxf(v + bias[lane], 0.0f);
        if (OUTPLANES) {
            bf16 h = __float2bfloat16(v);
            OH[(size_t)node * 32 + lane] = h;
            OL[(size_t)node * 32 + lane] = __float2bfloat16(v - __bfloat162float(h));
        } else {
            OUT[(size_t)node * 32 + lane] = v;
        }
    }
}

// ---------------- launch ----------------
extern "C" void kernel_launch(void* const* d_in, const int* in_sizes, int n_in,
                              void* d_out, int out_size) {
    const float* x     = (const float*)d_in[0];
    const void*  edges = d_in[1];
    const float* W1  = (const float*)d_in[3];  const float* b1  = (const float*)d_in[4];
    const float* W2  = (const float*)d_in[5];  const float* b2  = (const float*)d_in[6];
    const float* W3  = (const float*)d_in[7];  const float* b3  = (const float*)d_in[8];
    const float* tW1 = (const float*)d_in[9];  const float* tb1 = (const float*)d_in[10];
    const float* tW2 = (const float*)d_in[11]; const float* tb2 = (const float*)d_in[12];
    const float* tW3 = (const float*)d_in[13]; const float* tb3 = (const float*)d_in[14];
    const float* Wpi = (const float*)d_in[15]; const float* bpi = (const float*)d_in[16];
    const float* Wn  = (const float*)d_in[17]; const float* bn  = (const float*)d_in[18];
    const float* Wp  = (const float*)d_in[19]; const float* bp  = (const float*)d_in[20];
    float* out = (float*)d_out;

    const int TOT = in_sizes[0] / FDIM;
    const int E   = in_sizes[1] / 2;

    float *dinv, *H2raw, *H2;
    int *cnt, *rowp, *curs, *adj, *part;
    bf16 *A1h, *A1l, *H1h, *H1l, *A3h, *A3l, *H3h, *H3l, *C1h, *C1l, *C2h, *C2l;
    bf16 *W1h, *W1l, *W2h, *W2l, *W3h, *W3l, *T1h, *T1l, *T2h, *T2l, *T3h, *T3l;
    cudaGetSymbolAddress((void**)&dinv,  g_dinv);
    cudaGetSymbolAddress((void**)&cnt,   g_cnt);
    cudaGetSymbolAddress((void**)&rowp,  g_rowp);
    cudaGetSymbolAddress((void**)&curs,  g_curs);
    cudaGetSymbolAddress((void**)&adj,   g_adj);
    cudaGetSymbolAddress((void**)&part,  g_part);
    cudaGetSymbolAddress((void**)&A1h,   g_A1h);  cudaGetSymbolAddress((void**)&A1l, g_A1l);
    cudaGetSymbolAddress((void**)&H1h,   g_H1h);  cudaGetSymbolAddress((void**)&H1l, g_H1l);
    cudaGetSymbolAddress((void**)&A3h,   g_A3h);  cudaGetSymbolAddress((void**)&A3l, g_A3l);
    cudaGetSymbolAddress((void**)&H3h,   g_H3h);  cudaGetSymbolAddress((void**)&H3l, g_H3l);
    cudaGetSymbolAddress((void**)&C1h,   g_C1h);  cudaGetSymbolAddress((void**)&C1l, g_C1l);
    cudaGetSymbolAddress((void**)&C2h,   g_C2h);  cudaGetSymbolAddress((void**)&C2l, g_C2l);
    cudaGetSymbolAddress((void**)&H2raw, g_H2raw);
    cudaGetSymbolAddress((void**)&H2,    g_H2);
    cudaGetSymbolAddress((void**)&W1h, g_W1h); cudaGetSymbolAddress((void**)&W1l, g_W1l);
    cudaGetSymbolAddress((void**)&W2h, g_W2h); cudaGetSymbolAddress((void**)&W2l, g_W2l);
    cudaGetSymbolAddress((void**)&W3h, g_W3h); cudaGetSymbolAddress((void**)&W3l, g_W3l);
    cudaGetSymbolAddress((void**)&T1h, g_T1h); cudaGetSymbolAddress((void**)&T1l, g_T1l);
    cudaGetSymbolAddress((void**)&T2h, g_T2h); cudaGetSymbolAddress((void**)&T2l, g_T2l);
    cudaGetSymbolAddress((void**)&T3h, g_T3h); cudaGetSymbolAddress((void**)&T3l, g_T3l);

    const int gatherBlocks = (TOT * 32) / 256;
    const int grid1 = TOT / 128;   // TILES=1
    const int grid2 = TOT / 256;   // TILES=2

    // smem sizes (bytes): NBUF*2*ABUFB + 2*BPL (+hbuf)
    const int SM_G1 = 4 * (128 * 72 * 2)  + 2 * (128 * 72 * 2);              // 110592
    const int SM_G2 = 2 * (128 * 136 * 2) + 2 * (32 * 136 * 2);              // 87040
    const int SM_G3 = 4 * (128 * 40 * 2)  + 2 * (128 * 40 * 2);              // 61440
    const int SM_C1 = 2 * (130 * 72 * 2)  + 2 * (128 * 72 * 2);              // 74304
    const int SM_C2 = 2 * (130 * 72 * 2)  + 2 * (3 * 32 * 72 * 2);           // 65088
    const int SM_C3 = 4 * (130 * 40 * 2)  + 2 * (3 * 128 * 40 * 2) + 1536;   // 104576

    cudaFuncSetAttribute(mma_layer<64, 128, 1, 64, 1, 1, 1, 0, 2, 1>,  cudaFuncAttributeMaxDynamicSharedMemorySize, SM_G1);
    cudaFuncSetAttribute(mma_layer<128, 32, 1, 128, 0, 0, 0, 0, 2, 0>, cudaFuncAttributeMaxDynamicSharedMemorySize, SM_G2);
    cudaFuncSetAttribute(mma_layer<32, 128, 1, 32, 1, 1, 1, 0, 2, 1>,  cudaFuncAttributeMaxDynamicSharedMemorySize, SM_G3);
    cudaFuncSetAttribute(mma_layer<128, 128, 3, 64, 1, 1, 1, 0, 1, 0>, cudaFuncAttributeMaxDynamicSharedMemorySize, SM_C1);
    cudaFuncSetAttribute(mma_layer<128, 32, 3, 64, 1, 1, 1, 0, 1, 0>,  cudaFuncAttributeMaxDynamicSharedMemorySize, SM_C2);
    cudaFuncSetAttribute(mma_layer<32, 128, 3, 32, 1, 1, 0, 1, 2, 1>,  cudaFuncAttributeMaxDynamicSharedMemorySize, SM_C3);

    // ---- weight planes + CSR build ----
    wplanes_kernel<<<128, 256>>>(W1, W2, W3, tW1, tW2, tW3);
    zero_detect_kernel<<<256, 256>>>(cnt, TOT, (const unsigned int*)edges);
    count_kernel<<<2048, 256>>>(edges, cnt, E);
    scan_partial_kernel<<<SCB, 256>>>(cnt, part);
    scan_top_kernel<<<1, SCB>>>(part);
    scan_emit_kernel<<<SCB, 256>>>(cnt, part, rowp, curs, dinv);
    fill_kernel<<<2048, 256>>>(edges, curs, adj, E);

    // ---- GCN stack ----
    gather_kernel<64, 0, 1><<<gatherBlocks, 256>>>(rowp, adj, dinv, x, nullptr, nullptr, A1h, A1l, TOT);
    mma_layer<64, 128, 1, 64, 1, 1, 1, 0, 2, 1><<<grid2, 256, SM_G1>>>(
        A1h, A1l, W1h, W1l, b1, nullptr, H1h, H1l,
        nullptr, nullptr, nullptr, nullptr, nullptr, nullptr, nullptr);
    mma_layer<128, 32, 1, 128, 0, 0, 0, 0, 2, 0><<<grid2, 256, SM_G2>>>(
        H1h, H1l, W2h, W2l, nullptr, H2raw, nullptr, nullptr,
        nullptr, nullptr, nullptr, nullptr, nullptr, nullptr, nullptr);
    gather_kernel<32, 1, 0><<<gatherBlocks, 256>>>(rowp, adj, dinv, H2raw, b2, H2, nullptr, nullptr, TOT);
    gather_kernel<32, 0, 1><<<gatherBlocks, 256>>>(rowp, adj, dinv, H2, nullptr, nullptr, A3h, A3l, TOT);
    mma_layer<32, 128, 1, 32, 1, 1, 1, 0, 2, 1><<<grid2, 256, SM_G3>>>(
        A3h, A3l, W3h, W3l, b3, nullptr, H3h, H3l,
        nullptr, nullptr, nullptr, nullptr, nullptr, nullptr, nullptr);

    // ---- temporal conv stack (k=3, pad=1); conv3 fuses the 3 heads ----
    mma_layer<128, 128, 3, 64, 1, 1, 1, 0, 1, 0><<<grid1, 256, SM_C1>>>(
        H3h, H3l, T1h, T1l, tb1, nullptr, C1h, C1l,
        nullptr, nullptr, nullptr, nullptr, nullptr, nullptr, nullptr);
    mma_layer<128, 32, 3, 64, 1, 1, 1, 0, 1, 0><<<grid1, 256, SM_C2>>>(
        C1h, C1l, T2h, T2l, tb2, nullptr, C2h, C2l,
        nullptr, nullptr, nullptr, nullptr, nullptr, nullptr, nullptr);
    mma_layer<32, 128, 3, 32, 1, 1, 0, 1, 2, 1><<<grid2, 256, SM_C3>>>(
        C2h, C2l, T3h, T3l, tb3, nullptr, nullptr, nullptr,
        Wpi, Wn, Wp, bpi, bn, bp, out);
}

// round 11
// speedup vs baseline: 4.2392x; 1.0335x over previous
#include <cuda_runtime.h>
#include <cuda_bf16.h>
#include <math.h>
#include <stdint.h>

// ---------------- problem constants ----------------
#define TOTN   131072      // B*N nodes
#define EMAX   1048576
#define FDIM   64
#define HSD    128
#define RSD    32
#define NPG    4096        // nodes per graph (temporal length)
#define SCB    512         // scan blocks
#define SCCH   (TOTN / SCB)

typedef __nv_bfloat16 bf16;

// ---------------- device scratch (no cudaMalloc allowed) ----------------
__device__ int   g_is64;
__device__ float g_dinv [TOTN];
__device__ int   g_cnt  [TOTN];
__device__ int   g_rowp [TOTN + 1];
__device__ int   g_curs [TOTN];
__device__ int   g_adj  [EMAX];
__device__ int   g_part [SCB];
// bf16 hi/lo planes for activations
__device__ __align__(16) bf16 g_A1h[TOTN * FDIM], g_A1l[TOTN * FDIM];
__device__ __align__(16) bf16 g_H1h[TOTN * HSD],  g_H1l[TOTN * HSD];
__device__ __align__(16) bf16 g_A3h[TOTN * RSD],  g_A3l[TOTN * RSD];
__device__ __align__(16) bf16 g_H3h[TOTN * HSD],  g_H3l[TOTN * HSD];
__device__ __align__(16) bf16 g_C1h[TOTN * HSD],  g_C1l[TOTN * HSD];
__device__ __align__(16) bf16 g_C2h[TOTN * RSD],  g_C2l[TOTN * RSD];
// fp32 intermediates
__device__ float g_H2raw[TOTN * RSD];
__device__ float g_H2   [TOTN * RSD];
// weight planes (k-major [tap][COUT][CIN])
__device__ __align__(16) bf16 g_W1h[128 * 64],      g_W1l[128 * 64];
__device__ __align__(16) bf16 g_W2h[32 * 128],      g_W2l[32 * 128];
__device__ __align__(16) bf16 g_W3h[128 * 32],      g_W3l[128 * 32];
__device__ __align__(16) bf16 g_T1h[3 * 128 * 128], g_T1l[3 * 128 * 128];
__device__ __align__(16) bf16 g_T2h[3 * 32 * 128],  g_T2l[3 * 32 * 128];
__device__ __align__(16) bf16 g_T3h[3 * 128 * 32],  g_T3l[3 * 128 * 32];

__device__ __forceinline__ uint32_t pack_bf(float a, float b) {
    __nv_bfloat162 t;
    t.x = __float2bfloat16(a);
    t.y = __float2bfloat16(b);
    return *reinterpret_cast<uint32_t*>(&t);
}
__device__ __forceinline__ uint32_t smem_u32(const void* p) {
    uint32_t a;
    asm("{ .reg .u64 t; cvta.to.shared.u64 t, %1; cvt.u32.u64 %0, t; }" : "=r"(a) : "l"(p));
    return a;
}
__device__ __forceinline__ void mma16816(float* d, uint32_t a0, uint32_t a1, uint32_t a2,
                                         uint32_t a3, uint32_t b0, uint32_t b1) {
    asm volatile(
        "mma.sync.aligned.m16n8k16.row.col.f32.bf16.bf16.f32 "
        "{%0,%1,%2,%3}, {%4,%5,%6,%7}, {%8,%9}, {%0,%1,%2,%3};"
        : "+f"(d[0]), "+f"(d[1]), "+f"(d[2]), "+f"(d[3])
        : "r"(a0), "r"(a1), "r"(a2), "r"(a3), "r"(b0), "r"(b1));
}
__device__ __forceinline__ void ldsm4(uint32_t& r0, uint32_t& r1, uint32_t& r2, uint32_t& r3,
                                      uint32_t addr) {
    asm volatile("ldmatrix.sync.aligned.m8n8.x4.shared.b16 {%0,%1,%2,%3}, [%4];"
                 : "=r"(r0), "=r"(r1), "=r"(r2), "=r"(r3) : "r"(addr));
}
__device__ __forceinline__ void cp16(uint32_t s, const void* g, bool p) {
    asm volatile("cp.async.cg.shared.global [%0], [%1], 16, %2;"
                 :: "r"(s), "l"(g), "r"(p ? 16 : 0));
}
#define CP_COMMIT() asm volatile("cp.async.commit_group;" ::: "memory")
#define CP_WAIT0()  asm volatile("cp.async.wait_group 0;" ::: "memory")

// ---------------- weight plane precompute (device helpers) ----------------
__device__ void wlin(const float* W, bf16* WH, bf16* WL, int CIN, int COUT, int tid, int nt) {
    for (int i = tid; i < CIN * COUT; i += nt) {
        int n = i / CIN, k = i % CIN;
        float w = W[(size_t)k * COUT + n];
        bf16 h = __float2bfloat16(w);
        WH[i] = h;
        WL[i] = __float2bfloat16(w - __bfloat162float(h));
    }
}
__device__ void wconv(const float* W, bf16* WH, bf16* WL, int CIN, int COUT, int tid, int nt) {
    for (int i = tid; i < 3 * CIN * COUT; i += nt) {
        int s = i / (CIN * COUT);
        int n = (i / CIN) % COUT;
        int k = i % CIN;
        float w = W[((size_t)n * CIN + k) * 3 + s];
        bf16 h = __float2bfloat16(w);
        WH[i] = h;
        WL[i] = __float2bfloat16(w - __bfloat162float(h));
    }
}

// prep: zero counts + detect edge dtype + build all weight planes (one launch)
__global__ void prep_kernel(int* cnt, int n, const unsigned int* e,
                            const float* W1, const float* W2, const float* W3,
                            const float* T1, const float* T2, const float* T3) {
    int tid = blockIdx.x * blockDim.x + threadIdx.x;
    int nt  = gridDim.x * blockDim.x;
    for (int i = tid; i < n; i += nt) cnt[i] = 0;
    if (tid == 0) {
        int ok = 1;
        #pragma unroll 1
        for (int k = 0; k < 64; k++)
            if (e[2 * k + 1] != 0u) { ok = 0; break; }
        g_is64 = ok;
    }
    wlin(W1, g_W1h, g_W1l, 64, 128, tid, nt);
    wlin(W2, g_W2h, g_W2l, 128, 32, tid, nt);
    wlin(W3, g_W3h, g_W3l, 32, 128, tid, nt);
    wconv(T1, g_T1h, g_T1l, 128, 128, tid, nt);
    wconv(T2, g_T2h, g_T2l, 128, 32, tid, nt);
    wconv(T3, g_T3h, g_T3l, 32, 128, tid, nt);
}

// =========== unified dense layer on tensor cores ===========
template <int CIN, int COUT, int TAPS, int KCH, int HASBIAS, int HASRELU,
          int OUTPLANES, int HEADS, int TILES, int PIPE>
__global__ void __launch_bounds__(256, 2)
mma_layer(const bf16* __restrict__ XH, const bf16* __restrict__ XL,
          const bf16* __restrict__ WH, const bf16* __restrict__ WL,
          const float* __restrict__ bias,
          float* __restrict__ OUT, bf16* __restrict__ OH, bf16* __restrict__ OL,
          const float* __restrict__ HWpi, const float* __restrict__ HWn,
          const float* __restrict__ HWp, const float* __restrict__ Hbpi,
          const float* __restrict__ Hbn, const float* __restrict__ Hbp,
          float* __restrict__ hout) {
    constexpr int NCHC = CIN / KCH;
    constexpr int P    = KCH + 8;
    constexpr int HALO = (TAPS == 3) ? 1 : 0;
    constexpr int RSTG = 128 + 2 * HALO;
    constexpr bool BIG = (COUT == 128);
    constexpr bool ALLTAPS = (TAPS == 3) && (COUT == 32 || CIN == 32);
    constexpr bool BDB = (TAPS == 3) && !ALLTAPS && !PIPE;   // B double-buffer (conv1)
    constexpr int BTAPS = ALLTAPS ? 3 : 1;
    constexpr int U4   = KCH / 8;
    constexpr int FD   = BIG ? 2 : 1;
    constexpr int TD   = BIG ? 8 : 4;
    constexpr int NBUF = PIPE ? 2 : 1;
    constexpr int ABUFB  = RSTG * P * 2;           // bytes per A plane
    constexpr int OFF_B  = NBUF * 2 * ABUFB;
    constexpr int BPL    = BTAPS * COUT * P * 2;   // bytes per B plane
    constexpr int NBB    = BDB ? 2 : 1;
    constexpr int OFF_HB = OFF_B + NBB * 2 * BPL;

    extern __shared__ __align__(16) char smem[];
    const uint32_t sb = smem_u32(smem);
    float* hbuf = (float*)(smem + OFF_HB);

    int tid  = threadIdx.x;
    int w    = tid >> 5;
    int lane = tid & 31;
    int gid  = lane >> 2;
    int qid  = lane & 3;
    int seg  = lane >> 3;
    int rin  = lane & 7;
    int wm   = BIG ? (w & 3) : w;
    int wn   = BIG ? (w >> 2) : 0;

    float d[FD][TD][4];

    auto reset_acc = [&]() {
        #pragma unroll
        for (int f = 0; f < FD; f++)
            #pragma unroll
            for (int t = 0; t < TD; t++)
                #pragma unroll
                for (int i = 0; i < 4; i++) d[f][t][i] = 0.0f;
    };

    auto stage_A = [&](int trow0, int c0, int b) {
        int gbl = (trow0 / NPG) * NPG;
        uint32_t dh = sb + (uint32_t)(b * 2) * ABUFB;
        uint32_t dl = dh + ABUFB;
        for (int idx = tid; idx < RSTG * U4; idx += 256) {
            int r = idx / U4, j = (idx % U4) * 8;
            long src = (long)trow0 - HALO + r;
            bool ok = (!HALO) || (src >= gbl && src < (long)gbl + NPG);
            long sc = ok ? src : (long)trow0;
            cp16(dh + (uint32_t)(r * P + j) * 2, XH + sc * CIN + c0 + j, ok);
            cp16(dl + (uint32_t)(r * P + j) * 2, XL + sc * CIN + c0 + j, ok);
        }
    };
    auto stage_B_all = [&](int c0) {
        for (int idx = tid; idx < BTAPS * COUT * U4; idx += 256) {
            int n2 = idx / U4, j = (idx % U4) * 8;
            cp16(sb + OFF_B        + (uint32_t)(n2 * P + j) * 2, WH + (size_t)n2 * CIN + c0 + j, true);
            cp16(sb + OFF_B + BPL  + (uint32_t)(n2 * P + j) * 2, WL + (size_t)n2 * CIN + c0 + j, true);
        }
    };
    auto stage_B_tap = [&](int s, int c0, int bb) {
        uint32_t bh = sb + OFF_B + (uint32_t)bb * 2 * BPL;
        for (int idx = tid; idx < COUT * U4; idx += 256) {
            int n = idx / U4, j = (idx % U4) * 8;
            cp16(bh       + (uint32_t)(n * P + j) * 2, WH + ((size_t)s * COUT + n) * CIN + c0 + j, true);
            cp16(bh + BPL + (uint32_t)(n * P + j) * 2, WL + ((size_t)s * COUT + n) * CIN + c0 + j, true);
        }
    };

    auto mma_chunk = [&](uint32_t aH, uint32_t aL, int s, int bt, int bb) {
        uint32_t bH = sb + OFF_B + (uint32_t)bb * 2 * BPL;
        uint32_t bL = bH + BPL;
        #pragma unroll
        for (int ks = 0; ks < KCH / 16; ks++) {
            int kc = ks * 16;
            if (BIG) {
                uint32_t ah[FD][4], al[FD][4];
                #pragma unroll
                for (int f = 0; f < FD; f++) {
                    uint32_t aoff = (uint32_t)((wm * 32 + f * 16 + rin + ((seg & 1) << 3) + s) * P
                                               + kc + ((seg >> 1) << 3)) * 2;
                    ldsm4(ah[f][0], ah[f][1], ah[f][2], ah[f][3], aH + aoff);
                    ldsm4(al[f][0], al[f][1], al[f][2], al[f][3], aL + aoff);
                }
                #pragma unroll
                for (int g = 0; g < 4; g++) {
                    uint32_t boff = (uint32_t)(((bt * COUT) + wn * 64 + g * 16 + rin + ((seg >> 1) << 3)) * P
                                               + kc + ((seg & 1) << 3)) * 2;
                    uint32_t bh0, bh1, bh2, bh3, bl0, bl1, bl2, bl3;
                    ldsm4(bh0, bh1, bh2, bh3, bH + boff);
                    ldsm4(bl0, bl1, bl2, bl3, bL + boff);
                    #pragma unroll
                    for (int f = 0; f < FD; f++) {
                        mma16816(d[f][2 * g],     ah[f][0], ah[f][1], ah[f][2], ah[f][3], bh0, bh1);
                        mma16816(d[f][2 * g],     ah[f][0], ah[f][1], ah[f][2], ah[f][3], bl0, bl1);
                        mma16816(d[f][2 * g],     al[f][0], al[f][1], al[f][2], al[f][3], bh0, bh1);
                        mma16816(d[f][2 * g + 1], ah[f][0], ah[f][1], ah[f][2], ah[f][3], bh2, bh3);
                        mma16816(d[f][2 * g + 1], ah[f][0], ah[f][1], ah[f][2], ah[f][3], bl2, bl3);
                        mma16816(d[f][2 * g + 1], al[f][0], al[f][1], al[f][2], al[f][3], bh2, bh3);
                    }
                }
            } else {
                uint32_t aoff = (uint32_t)((w * 16 + rin + ((seg & 1) << 3) + s) * P
                                           + kc + ((seg >> 1) << 3)) * 2;
                uint32_t ah0, ah1, ah2, ah3, al0, al1, al2, al3;
                ldsm4(ah0, ah1, ah2, ah3, aH + aoff);
                ldsm4(al0, al1, al2, al3, aL + aoff);
                #pragma unroll
                for (int g = 0; g < 2; g++) {
                    uint32_t boff = (uint32_t)(((bt * COUT) + g * 16 + rin + ((seg >> 1) << 3)) * P
                                               + kc + ((seg & 1) << 3)) * 2;
                    uint32_t bh0, bh1, bh2, bh3, bl0, bl1, bl2, bl3;
                    ldsm4(bh0, bh1, bh2, bh3, bH + boff);
                    ldsm4(bl0, bl1, bl2, bl3, bL + boff);
                    mma16816(d[0][2 * g],     ah0, ah1, ah2, ah3, bh0, bh1);
                    mma16816(d[0][2 * g],     ah0, ah1, ah2, ah3, bl0, bl1);
                    mma16816(d[0][2 * g],     al0, al1, al2, al3, bh0, bh1);
                    mma16816(d[0][2 * g + 1], ah0, ah1, ah2, ah3, bh2, bh3);
                    mma16816(d[0][2 * g + 1], ah0, ah1, ah2, ah3, bl2, bl3);
                    mma16816(d[0][2 * g + 1], al0, al1, al2, al3, bh2, bh3);
                }
            }
        }
    };

    auto epilogue = [&](int row0t) {
        if (HEADS) {
            float p1[2][2] = {}, p2[2][2] = {}, p3[2][2] = {};
            #pragma unroll
            for (int f = 0; f < FD; f++)
                #pragma unroll
                for (int t = 0; t < TD; t++) {
                    int n = wn * 64 + t * 8 + qid * 2;
                    float b0 = bias[n], b1 = bias[n + 1];
                    float v00 = fmaxf(d[f][t][0] + b0, 0.0f);
                    float v01 = fmaxf(d[f][t][1] + b1, 0.0f);
                    float v10 = fmaxf(d[f][t][2] + b0, 0.0f);
                    float v11 = fmaxf(d[f][t][3] + b1, 0.0f);
                    float wa0 = HWpi[n], wa1 = HWpi[n + 1];
                    float wb0 = HWn[n],  wb1 = HWn[n + 1];
                    float wc0 = HWp[n],  wc1 = HWp[n + 1];
                    p1[f][0] += v00 * wa0 + v01 * wa1;  p1[f][1] += v10 * wa0 + v11 * wa1;
                    p2[f][0] += v00 * wb0 + v01 * wb1;  p2[f][1] += v10 * wb0 + v11 * wb1;
                    p3[f][0] += v00 * wc0 + v01 * wc1;  p3[f][1] += v10 * wc0 + v11 * wc1;
                }
            #pragma unroll
            for (int f = 0; f < 2; f++)
                #pragma unroll
                for (int h = 0; h < 2; h++) {
                    p1[f][h] += __shfl_xor_sync(0xffffffffu, p1[f][h], 1);
                    p1[f][h] += __shfl_xor_sync(0xffffffffu, p1[f][h], 2);
                    p2[f][h] += __shfl_xor_sync(0xffffffffu, p2[f][h], 1);
                    p2[f][h] += __shfl_xor_sync(0xffffffffu, p2[f][h], 2);
                    p3[f][h] += __shfl_xor_sync(0xffffffffu, p3[f][h], 1);
                    p3[f][h] += __shfl_xor_sync(0xffffffffu, p3[f][h], 2);
                }
            if (wn == 0 && qid == 0) {
                #pragma unroll
                for (int f = 0; f < 2; f++) {
                    int r = wm * 32 + f * 16 + gid;
                    hbuf[r] = p1[f][0];        hbuf[r + 8] = p1[f][1];
                    hbuf[128 + r] = p2[f][0];  hbuf[128 + r + 8] = p2[f][1];
                    hbuf[256 + r] = p3[f][0];  hbuf[256 + r + 8] = p3[f][1];
                }
            }
            __syncthreads();
            if (wn == 1 && qid == 0) {
                #pragma unroll
                for (int f = 0; f < 2; f++)
                    #pragma unroll
                    for (int h = 0; h < 2; h++) {
                        int r = wm * 32 + f * 16 + gid + h * 8;
                        int rg = row0t + r;
                        float z1 = hbuf[r] + p1[f][h] + Hbpi[0];
                        float z2 = hbuf[128 + r] + p2[f][h] + Hbn[0];
                        float z3 = hbuf[256 + r] + p3[f][h] + Hbp[0];
                        hout[rg]            = 1.0f / (1.0f + expf(-z1));
                        hout[TOTN + rg]     = (z2 > 0.0f) ? (z2 + log1pf(expf(-z2))) : log1pf(expf(z2));
                        hout[2 * TOTN + rg] = 1.0f / (1.0f + expf(-z3));
                    }
            }
            __syncthreads();
        } else {
            #pragma unroll
            for (int f = 0; f < FD; f++) {
                int r0 = row0t + (BIG ? (wm * 32 + f * 16) : (w * 16)) + gid;
                #pragma unroll
                for (int t = 0; t < TD; t++) {
                    int n = (BIG ? wn * 64 : 0) + t * 8 + qid * 2;
                    float2 v0 = make_float2(d[f][t][0], d[f][t][1]);
                    float2 v1 = make_float2(d[f][t][2], d[f][t][3]);
                    if (HASBIAS) {
                        float bx = bias[n], by = bias[n + 1];
                        v0.x += bx; v0.y += by;
                        v1.x += bx; v1.y += by;
                    }
                    if (HASRELU) {
                        v0.x = fmaxf(v0.x, 0.0f); v0.y = fmaxf(v0.y, 0.0f);
                        v1.x = fmaxf(v1.x, 0.0f); v1.y = fmaxf(v1.y, 0.0f);
                    }
                    if (OUTPLANES) {
                        bf16 h0 = __float2bfloat16(v0.x), h1 = __float2bfloat16(v0.y);
                        bf16 h2 = __float2bfloat16(v1.x), h3 = __float2bfloat16(v1.y);
                        *(uint32_t*)&OH[(size_t)r0 * COUT + n] = pack_bf(v0.x, v0.y);
                        *(uint32_t*)&OL[(size_t)r0 * COUT + n] = pack_bf(v0.x - __bfloat162float(h0),
                                                                         v0.y - __bfloat162float(h1));
                        *(uint32_t*)&OH[(size_t)(r0 + 8) * COUT + n] = pack_bf(v1.x, v1.y);
                        *(uint32_t*)&OL[(size_t)(r0 + 8) * COUT + n] = pack_bf(v1.x - __bfloat162float(h2),
                                                                               v1.y - __bfloat162float(h3));
                    } else {
                        *(float2*)&OUT[(size_t)r0 * COUT + n]       = v0;
                        *(float2*)&OUT[(size_t)(r0 + 8) * COUT + n] = v1;
                    }
                }
            }
        }
    };

    if (PIPE) {
        stage_A(blockIdx.x * TILES * 128, 0, 0);
        stage_B_all(0);
        CP_COMMIT();
        for (int t = 0; t < TILES; t++) {
            int row0t = (blockIdx.x * TILES + t) * 128;
            CP_WAIT0();
            __syncthreads();
            if (t + 1 < TILES) {
                stage_A(row0t + 128, 0, (t + 1) & 1);
                CP_COMMIT();
            }
            reset_acc();
            uint32_t aH = sb + (uint32_t)((t & 1) * 2) * ABUFB;
            uint32_t aL = aH + ABUFB;
            #pragma unroll
            for (int s = 0; s < TAPS; s++) mma_chunk(aH, aL, s, ALLTAPS ? s : 0, 0);
            epilogue(row0t);
            __syncthreads();
        }
    } else {
        for (int t = 0; t < TILES; t++) {
            int row0t = (blockIdx.x * TILES + t) * 128;
            reset_acc();
            for (int c = 0; c < NCHC; c++) {
                int c0 = c * KCH;
                __syncthreads();
                stage_A(row0t, c0, 0);
                if (ALLTAPS) stage_B_all(c0);
                else if (TAPS == 1) { if (t == 0) stage_B_all(c0); }
                else stage_B_tap(0, c0, 0);
                CP_COMMIT(); CP_WAIT0();
                __syncthreads();
                #pragma unroll
                for (int s = 0; s < TAPS; s++) {
                    if (BDB && s + 1 < TAPS) {
                        stage_B_tap(s + 1, c0, (s + 1) & 1);   // overlap with mma(s)
                        CP_COMMIT();
                    }
                    mma_chunk(sb, sb + ABUFB, s, ALLTAPS ? s : 0, BDB ? (s & 1) : 0);
                    if (BDB && s + 1 < TAPS) {
                        CP_WAIT0();
                        __syncthreads();
                    }
                }
            }
            __syncthreads();
            epilogue(row0t);
        }
    }
}

// ---------------- CSR build ----------------
__device__ __forceinline__ int edge_at(const void* e, int idx, int is64) {
    if (is64) return (int)((const long long*)e)[idx];
    return ((const int*)e)[idx];
}
__global__ void count_kernel(const void* edges, int* cnt, int E) {
    int is64 = g_is64;
    int i  = blockIdx.x * blockDim.x + threadIdx.x;
    int st = gridDim.x * blockDim.x;
    for (; i < E; i += st) {
        int d = edge_at(edges, E + i, is64);
        atomicAdd(&cnt[d], 1);
    }
}
__global__ void __launch_bounds__(256)
scan_partial_kernel(const int* __restrict__ cnt, int* part) {
    __shared__ int sh[8];
    int tid = threadIdx.x;
    int v = cnt[blockIdx.x * SCCH + tid];
    #pragma unroll
    for (int o = 16; o > 0; o >>= 1) v += __shfl_xor_sync(0xffffffffu, v, o);
    if ((tid & 31) == 0) sh[tid >> 5] = v;
    __syncthreads();
    if (tid < 8) {
        int s = sh[tid];
        #pragma unroll
        for (int o = 4; o > 0; o >>= 1) s += __shfl_xor_sync(0xffu, s, o, 8);
        if (tid == 0) part[blockIdx.x] = s;
    }
}
// block-local scan + per-block base reduce (scan_top folded in) + emit
__global__ void __launch_bounds__(256)
scan_emit_kernel(const int* __restrict__ cnt, const int* __restrict__ part,
                 int* row_ptr, int* cursor, float* dinv) {
    __shared__ int wsum[8];
    __shared__ int bsum[8];
    int tid  = threadIdx.x;
    int lane = tid & 31;
    int wid  = tid >> 5;

    // base = sum(part[0..blockIdx.x))
    int bs = 0;
    for (int i = tid; i < blockIdx.x; i += 256) bs += part[i];
    #pragma unroll
    for (int o = 16; o > 0; o >>= 1) bs += __shfl_xor_sync(0xffffffffu, bs, o);
    if (lane == 0) bsum[wid] = bs;
    __syncthreads();
    if (tid == 0) {
        int b = 0;
        #pragma unroll
        for (int k = 0; k < 8; k++) b += bsum[k];
        bsum[0] = b;
    }
    __syncthreads();
    int base = bsum[0];

    int i = blockIdx.x * SCCH + tid;
    int c = cnt[i];
    int v = c;
    #pragma unroll
    for (int o = 1; o < 32; o <<= 1) {
        int u = __shfl_up_sync(0xffffffffu, v, o);
        if (lane >= o) v += u;
    }
    if (lane == 31) wsum[wid] = v;
    __syncthreads();
    if (wid == 0 && lane < 8) {
        int s = wsum[lane];
        #pragma unroll
        for (int o = 1; o < 8; o <<= 1) {
            int u = __shfl_up_sync(0xffu, s, o, 8);
            if (lane >= o) s += u;
        }
        wsum[lane] = s;
    }
    __syncthreads();
    int excl = v - c + (wid > 0 ? wsum[wid - 1] : 0);
    int run = base + excl;
    row_ptr[i] = run;
    cursor[i]  = run;
    dinv[i]    = rsqrtf((float)c + 1.0f);
    if (i == TOTN - 1) row_ptr[TOTN] = run + c;
}
__global__ void fill_kernel(const void* edges, int* cursor, int* adj, int E) {
    int is64 = g_is64;
    int i  = blockIdx.x * blockDim.x + threadIdx.x;
    int st = gridDim.x * blockDim.x;
    for (; i < E; i += st) {
        int s = edge_at(edges, i, is64);
        int d = edge_at(edges, E + i, is64);
        int pos = atomicAdd(&cursor[d], 1);
        adj[pos] = s;
    }
}

// ---------------- CSR gather + fused epilogue ----------------
template <int D, int BIASRELU, int OUTPLANES>
__global__ void gather_kernel(const int* __restrict__ row_ptr, const int* __restrict__ adj,
                              const float* __restrict__ dinv, const float* __restrict__ X,
                              const float* __restrict__ bias, float* __restrict__ OUT,
                              bf16* __restrict__ OH, bf16* __restrict__ OL, int n) {
    int lane = threadIdx.x & 31;
    int node = (blockIdx.x * blockDim.x + threadIdx.x) >> 5;
    if (node >= n) return;
    int beg = row_ptr[node];
    int end = row_ptr[node + 1];
    float di = dinv[node];
    float c  = di * di;
    if (D == 64) {
        float ax = 0.0f, ay = 0.0f;
        #pragma unroll 4
        for (int j = beg; j < end; j++) {
            int s = adj[j];
            float ws = __ldg(&dinv[s]);
            float2 v = ((const float2*)(X + (size_t)s * 64))[lane];
            ax = fmaf(ws, v.x, ax);
            ay = fmaf(ws, v.y, ay);
        }
        float2 xv = ((const float2*)(X + (size_t)node * 64))[lane];
        float2 o;
        o.x = c * (ax + xv.x);
        o.y = c * (ay + xv.y);
        if (BIASRELU) {
            o.x = fmaxf(o.x + bias[2 * lane],     0.0f);
            o.y = fmaxf(o.y + bias[2 * lane + 1], 0.0f);
        }
        if (OUTPLANES) {
            bf16 hx = __float2bfloat16(o.x), hy = __float2bfloat16(o.y);
            *(uint32_t*)&OH[(size_t)node * 64 + 2 * lane] = pack_bf(o.x, o.y);
            *(uint32_t*)&OL[(size_t)node * 64 + 2 * lane] = pack_bf(o.x - __bfloat162float(hx),
                                                                    o.y - __bfloat162float(hy));
        } else {
            ((float2*)(OUT + (size_t)node * 64))[lane] = o;
        }
    } else {
        float acc = 0.0f;
        #pragma unroll 4
        for (int j = beg; j < end; j++) {
            int s = adj[j];
            float ws = __ldg(&dinv[s]);
            acc = fmaf(ws, X[(size_t)s * 32 + lane], acc);
        }
        float v = c * (acc + X[(size_t)node * 32 + lane]);
        if (BIASRELU) v = fmaxf(v + bias[lane], 0.0f);
        if (OUTPLANES) {
            bf16 h = __float2bfloat16(v);
            OH[(size_t)node * 32 + lane] = h;
            OL[(size_t)node * 32 + lane] = __float2bfloat16(v - __bfloat162float(h));
        } else {
            OUT[(size_t)node * 32 + lane] = v;
        }
    }
}

// ---------------- launch ----------------
extern "C" void kernel_launch(void* const* d_in, const int* in_sizes, int n_in,
                              void* d_out, int out_size) {
    const float* x     = (const float*)d_in[0];
    const void*  edges = d_in[1];
    const float* W1  = (const float*)d_in[3];  const float* b1  = (const float*)d_in[4];
    const float* W2  = (const float*)d_in[5];  const float* b2  = (const float*)d_in[6];
    const float* W3  = (const float*)d_in[7];  const float* b3  = (const float*)d_in[8];
    const float* tW1 = (const float*)d_in[9];  const float* tb1 = (const float*)d_in[10];
    const float* tW2 = (const float*)d_in[11]; const float* tb2 = (const float*)d_in[12];
    const float* tW3 = (const float*)d_in[13]; const float* tb3 = (const float*)d_in[14];
    const float* Wpi = (const float*)d_in[15]; const float* bpi = (const float*)d_in[16];
    const float* Wn  = (const float*)d_in[17]; const float* bn  = (const float*)d_in[18];
    const float* Wp  = (const float*)d_in[19]; const float* bp  = (const float*)d_in[20];
    float* out = (float*)d_out;

    const int TOT = in_sizes[0] / FDIM;
    const int E   = in_sizes[1] / 2;

    float *dinv, *H2raw, *H2;
    int *cnt, *rowp, *curs, *adj, *part;
    bf16 *A1h, *A1l, *H1h, *H1l, *A3h, *A3l, *H3h, *H3l, *C1h, *C1l, *C2h, *C2l;
    bf16 *W1h, *W1l, *W2h, *W2l, *W3h, *W3l, *T1h, *T1l, *T2h, *T2l, *T3h, *T3l;
    cudaGetSymbolAddress((void**)&dinv,  g_dinv);
    cudaGetSymbolAddress((void**)&cnt,   g_cnt);
    cudaGetSymbolAddress((void**)&rowp,  g_rowp);
    cudaGetSymbolAddress((void**)&curs,  g_curs);
    cudaGetSymbolAddress((void**)&adj,   g_adj);
    cudaGetSymbolAddress((void**)&part,  g_part);
    cudaGetSymbolAddress((void**)&A1h,   g_A1h);  cudaGetSymbolAddress((void**)&A1l, g_A1l);
    cudaGetSymbolAddress((void**)&H1h,   g_H1h);  cudaGetSymbolAddress((void**)&H1l, g_H1l);
    cudaGetSymbolAddress((void**)&A3h,   g_A3h);  cudaGetSymbolAddress((void**)&A3l, g_A3l);
    cudaGetSymbolAddress((void**)&H3h,   g_H3h);  cudaGetSymbolAddress((void**)&H3l, g_H3l);
    cudaGetSymbolAddress((void**)&C1h,   g_C1h);  cudaGetSymbolAddress((void**)&C1l, g_C1l);
    cudaGetSymbolAddress((void**)&C2h,   g_C2h);  cudaGetSymbolAddress((void**)&C2l, g_C2l);
    cudaGetSymbolAddress((void**)&H2raw, g_H2raw);
    cudaGetSymbolAddress((void**)&H2,    g_H2);
    cudaGetSymbolAddress((void**)&W1h, g_W1h); cudaGetSymbolAddress((void**)&W1l, g_W1l);
    cudaGetSymbolAddress((void**)&W2h, g_W2h); cudaGetSymbolAddress((void**)&W2l, g_W2l);
    cudaGetSymbolAddress((void**)&W3h, g_W3h); cudaGetSymbolAddress((void**)&W3l, g_W3l);
    cudaGetSymbolAddress((void**)&T1h, g_T1h); cudaGetSymbolAddress((void**)&T1l, g_T1l);
    cudaGetSymbolAddress((void**)&T2h, g_T2h); cudaGetSymbolAddress((void**)&T2l, g_T2l);
    cudaGetSymbolAddress((void**)&T3h, g_T3h); cudaGetSymbolAddress((void**)&T3l, g_T3l);

    const int gatherBlocks = (TOT * 32) / 256;
    const int grid1 = TOT / 128;   // TILES=1
    const int grid2 = TOT / 256;   // TILES=2

    // smem sizes (bytes)
    const int SM_G1 = 4 * (128 * 72 * 2)  + 2 * (128 * 72 * 2);              // 110592
    const int SM_G2 = 2 * (128 * 136 * 2) + 2 * (32 * 136 * 2);              // 87040
    const int SM_G3 = 4 * (128 * 40 * 2)  + 2 * (128 * 40 * 2);              // 61440
    const int SM_C1 = 2 * (130 * 72 * 2)  + 4 * (128 * 72 * 2);              // 111168 (B dbl-buf)
    const int SM_C2 = 2 * (130 * 72 * 2)  + 2 * (3 * 32 * 72 * 2);           // 65088
    const int SM_C3 = 4 * (130 * 40 * 2)  + 2 * (3 * 128 * 40 * 2) + 1536;   // 104576

    cudaFuncSetAttribute(mma_layer<64, 128, 1, 64, 1, 1, 1, 0, 2, 1>,  cudaFuncAttributeMaxDynamicSharedMemorySize, SM_G1);
    cudaFuncSetAttribute(mma_layer<128, 32, 1, 128, 0, 0, 0, 0, 2, 0>, cudaFuncAttributeMaxDynamicSharedMemorySize, SM_G2);
    cudaFuncSetAttribute(mma_layer<32, 128, 1, 32, 1, 1, 1, 0, 2, 1>,  cudaFuncAttributeMaxDynamicSharedMemorySize, SM_G3);
    cudaFuncSetAttribute(mma_layer<128, 128, 3, 64, 1, 1, 1, 0, 1, 0>, cudaFuncAttributeMaxDynamicSharedMemorySize, SM_C1);
    cudaFuncSetAttribute(mma_layer<128, 32, 3, 64, 1, 1, 1, 0, 1, 0>,  cudaFuncAttributeMaxDynamicSharedMemorySize, SM_C2);
    cudaFuncSetAttribute(mma_layer<32, 128, 3, 32, 1, 1, 0, 1, 2, 1>,  cudaFuncAttributeMaxDynamicSharedMemorySize, SM_C3);

    // ---- prep (weight planes + zero + detect) + CSR build ----
    prep_kernel<<<256, 256>>>(cnt, TOT, (const unsigned int*)edges, W1, W2, W3, tW1, tW2, tW3);
    count_kernel<<<2048, 256>>>(edges, cnt, E);
    scan_partial_kernel<<<SCB, 256>>>(cnt, part);
    scan_emit_kernel<<<SCB, 256>>>(cnt, part, rowp, curs, dinv);
    fill_kernel<<<2048, 256>>>(edges, curs, adj, E);

    // ---- GCN stack ----
    gather_kernel<64, 0, 1><<<gatherBlocks, 256>>>(rowp, adj, dinv, x, nullptr, nullptr, A1h, A1l, TOT);
    mma_layer<64, 128, 1, 64, 1, 1, 1, 0, 2, 1><<<grid2, 256, SM_G1>>>(
        A1h, A1l, W1h, W1l, b1, nullptr, H1h, H1l,
        nullptr, nullptr, nullptr, nullptr, nullptr, nullptr, nullptr);
    mma_layer<128, 32, 1, 128, 0, 0, 0, 0, 2, 0><<<grid2, 256, SM_G2>>>(
        H1h, H1l, W2h, W2l, nullptr, H2raw, nullptr, nullptr,
        nullptr, nullptr, nullptr, nullptr, nullptr, nullptr, nullptr);
    gather_kernel<32, 1, 0><<<gatherBlocks, 256>>>(rowp, adj, dinv, H2raw, b2, H2, nullptr, nullptr, TOT);
    gather_kernel<32, 0, 1><<<gatherBlocks, 256>>>(rowp, adj, dinv, H2, nullptr, nullptr, A3h, A3l, TOT);
    mma_layer<32, 128, 1, 32, 1, 1, 1, 0, 2, 1><<<grid2, 256, SM_G3>>>(
        A3h, A3l, W3h, W3l, b3, nullptr, H3h, H3l,
        nullptr, nullptr, nullptr, nullptr, nullptr, nullptr, nullptr);

    // ---- temporal conv stack (k=3, pad=1); conv3 fuses the 3 heads ----
    mma_layer<128, 128, 3, 64, 1, 1, 1, 0, 1, 0><<<grid1, 256, SM_C1>>>(
        H3h, H3l, T1h, T1l, tb1, nullptr, C1h, C1l,
        nullptr, nullptr, nullptr, nullptr, nullptr, nullptr, nullptr);
    mma_layer<128, 32, 3, 64, 1, 1, 1, 0, 1, 0><<<grid1, 256, SM_C2>>>(
        C1h, C1l, T2h, T2l, tb2, nullptr, C2h, C2l,
        nullptr, nullptr, nullptr, nullptr, nullptr, nullptr, nullptr);
    mma_layer<32, 128, 3, 32, 1, 1, 0, 1, 2, 1><<<grid2, 256, SM_C3>>>(
        C2h, C2l, T3h, T3l, tb3, nullptr, nullptr, nullptr,
        Wpi, Wn, Wp, bpi, bn, bp, out);
}